// round 10
// baseline (speedup 1.0000x reference)
#include <cuda_runtime.h>
#include <cuda_fp16.h>
#include <math.h>
#include <stdint.h>

// ---------------- problem constants ----------------
#define BATCH 2
#define SEQ   2048
#define DM    5120
#define NH    8
#define DH    640
#define DR    16
#define SPLITD 624
#define DKV   128
#define MROWS (BATCH*SEQ)        // 4096
#define KP    160                // per-head score K-dim: [128 ckv |16 rope |1 bias |15 pad]
#define LDQP  (NH*KP)            // 1280
#define NDD   256                // merged down-proj N: [ckv|cq]

// ---------------- scratch (device globals; no allocs allowed) ----------------
__device__ __align__(16) __half g_hh   [(size_t)MROWS*DM];
__device__ __align__(16) __half g_ckvcq[(size_t)MROWS*NDD];   // [ckv(0:128) | cq(128:256)]
__device__ __align__(16) __half g_krqrp[2*MROWS*DKV];          // [krp | qrp]
__device__ __align__(16) __half g_qp   [(size_t)MROWS*LDQP];
__device__ __align__(16) __half g_kp   [(size_t)MROWS*LDQP];
__device__ __align__(16) __half g_u    [(size_t)MROWS*NH*DKV]; // [4096,1024]
__device__ __align__(16) float  g_ckvf [MROWS*DKV];
// weights
__device__ __align__(16) __half g_wdd  [(size_t)NDD*DM];       // [wt_dkv; wt_dq] [256,5120]
__device__ __align__(16) __half g_wkq  [2*DKV*DKV];            // [wt_kr; wt_qr]
__device__ __align__(16) __half g_wout_h[(size_t)DM*DM];       // Wout raw order, half
__device__ __align__(16) __half g_wuv_h [DKV*DM];
__device__ __align__(16) __half g_wuq_p [DKV*NH*DH];           // zero-padded 624->640
__device__ __align__(16) __half g_wuk_p [DKV*NH*DH];
__device__ __align__(16) __half g_mt    [NH*DKV*DKV];          // Mt_h = Wuk_h Wuq_h^T
__device__ __align__(16) __half g_w2    [(size_t)NH*DKV*DM];   // [1024,5120] = (Wuv_h Wout_h) rows hj
__device__ __align__(16) float  g_bias2 [DM];
__device__ __align__(16) float  g_bqrow [NH*DKV];
__device__ __align__(16) float  g_wh    [NH*DKV];
__device__ __align__(16) float  g_sconst[NH];
__device__ __align__(16) float  g_bdd   [NDD];
__device__ __align__(16) float  g_bkq   [2*DKV];

// ---------------- PTX helpers ----------------
__device__ __forceinline__ uint32_t smem_u32(const void* p) {
    uint32_t a;
    asm("{ .reg .u64 t; cvta.to.shared.u64 t, %1; cvt.u32.u64 %0, t; }" : "=r"(a) : "l"(p));
    return a;
}
__device__ __forceinline__ void cp16(uint32_t dst, const void* src) {
    asm volatile("cp.async.cg.shared.global [%0], [%1], 16;" :: "r"(dst), "l"(src) : "memory");
}
#define CP_COMMIT() asm volatile("cp.async.commit_group;" ::: "memory")
#define CP_WAIT(n)  asm volatile("cp.async.wait_group %0;" :: "n"(n) : "memory")

__device__ __forceinline__ void ldm_x4(uint32_t* r, uint32_t addr) {
    asm volatile("ldmatrix.sync.aligned.m8n8.x4.shared.b16 {%0,%1,%2,%3}, [%4];"
                 : "=r"(r[0]), "=r"(r[1]), "=r"(r[2]), "=r"(r[3]) : "r"(addr));
}
__device__ __forceinline__ void ldm_x4t(uint32_t* r, uint32_t addr) {
    asm volatile("ldmatrix.sync.aligned.m8n8.x4.trans.shared.b16 {%0,%1,%2,%3}, [%4];"
                 : "=r"(r[0]), "=r"(r[1]), "=r"(r[2]), "=r"(r[3]) : "r"(addr));
}
__device__ __forceinline__ void mma_f16(float* c, const uint32_t* a, uint32_t b0, uint32_t b1) {
    asm volatile("mma.sync.aligned.m16n8k16.row.col.f32.f16.f16.f32 "
                 "{%0,%1,%2,%3}, {%4,%5,%6,%7}, {%8,%9}, {%0,%1,%2,%3};"
                 : "+f"(c[0]), "+f"(c[1]), "+f"(c[2]), "+f"(c[3])
                 : "r"(a[0]), "r"(a[1]), "r"(a[2]), "r"(a[3]), "r"(b0), "r"(b1));
}
__device__ __forceinline__ uint32_t packh2(float x, float y) {
    __half2 h = __floats2half2_rn(x, y);
    return *reinterpret_cast<uint32_t*>(&h);
}

// ============================================================================
// fp16 mma.sync GEMM. 128x128 tile, BK=32, 2-stage cp.async.
// TRB=false: C = alpha*A[M,K] * B[N,K]^T + bias  (B K-major)
// TRB=true : C = alpha*A[M,K] * B[K,N]   + bias  (B NN; via ldmatrix.trans)
// Cf written only for cols < cfN (ld ldcf); Ch full (ld ldc).
// ============================================================================
#define SPADH 40
#define TBLD  136    // TRB B tile row stride (128 + 8)

template<bool TRB>
__global__ __launch_bounds__(256)
void hgemm(const __half* __restrict__ A, const __half* __restrict__ B,
           float* __restrict__ Cf, __half* __restrict__ Ch,
           const float* __restrict__ bias,
           int M, int N, int K, int lda, int ldb, int ldc, int ldcf, int cfN,
           float alpha,
           long long sAhi, long long sAlo, long long sBhi, long long sBlo,
           long long sChi, long long sClo, long long sBiasLo, int zdiv)
{
    __shared__ __half As[2][128][SPADH];
    __shared__ __half Bs[2][128][SPADH];   // TRB: reinterpreted as [2][32][TBLD]

    int tid  = threadIdx.x;
    int warp = tid >> 5;
    int lane = tid & 31;
    int wr = warp >> 1;
    int wc = warp & 1;
    int qid = lane >> 2;
    int tig = lane & 3;

    int z  = blockIdx.z;
    int zh = z / zdiv, zl = z % zdiv;
    A += zh * sAhi + zl * sAlo;
    B += zh * sBhi + zl * sBlo;
    long long cofs = zh * sChi + zl * sClo;
    if (Cf) Cf += cofs;
    if (Ch) Ch += cofs;
    if (bias) bias += zl * sBiasLo;

    int row0 = blockIdx.y * 128, col0 = blockIdx.x * 128;
    const __half* Ab = A + (size_t)row0 * lda;
    const __half* Bb = TRB ? (B + col0) : (B + (size_t)col0 * ldb);

    // A cp.async coords (both modes)
    int r0 = tid >> 2, cc = (tid & 3) * 8;
    int r1 = r0 + 64;
    uint32_t dA0[2], dA1[2];
    // non-TRB B coords
    uint32_t dB0[2], dB1[2];
    // TRB B coords: 512 chunks, 2/thread: row = idx>>4 (0..31), col = (idx&15)*8
    int tr0 = tid >> 4,          tc0 = (tid & 15) * 8;
    int tr1 = (tid + 256) >> 4,  tc1 = tc0;
    uint32_t dT0[2], dT1[2];
#pragma unroll
    for (int s = 0; s < 2; s++) {
        dA0[s] = smem_u32(&As[s][r0][cc]);
        dA1[s] = smem_u32(&As[s][r1][cc]);
        if (!TRB) {
            dB0[s] = smem_u32(&Bs[s][r0][cc]);
            dB1[s] = smem_u32(&Bs[s][r1][cc]);
        } else {
            __half* bb = &Bs[s][0][0];
            dT0[s] = smem_u32(bb + tr0 * TBLD + tc0);
            dT1[s] = smem_u32(bb + tr1 * TBLD + tc1);
        }
    }
    uint32_t aAddr[2][2], bAddr[2][4];
#pragma unroll
    for (int s = 0; s < 2; s++) {
#pragma unroll
        for (int mi = 0; mi < 2; mi++)
            aAddr[s][mi] = smem_u32(&As[s][wr * 32 + mi * 16 + (lane & 15)][(lane >> 4) * 8]);
        if (!TRB) {
#pragma unroll
            for (int np = 0; np < 4; np++)
                bAddr[s][np] = smem_u32(&Bs[s][wc * 64 + np * 16 + (lane & 7) + ((lane >> 4) & 1) * 8]
                                            [((lane >> 3) & 1) * 8]);
        } else {
            __half* bb = &Bs[s][0][0];
#pragma unroll
            for (int nb = 0; nb < 4; nb++)
                bAddr[s][nb] = smem_u32(bb + (lane & 15) * TBLD
                                           + wc * 64 + nb * 16 + ((lane >> 4) << 3));
        }
    }

    float acc[2][8][4];
#pragma unroll
    for (int mi = 0; mi < 2; mi++)
#pragma unroll
        for (int ni = 0; ni < 8; ni++)
#pragma unroll
            for (int i = 0; i < 4; i++) acc[mi][ni][i] = 0.0f;

    int T = K >> 5;

    // prologue
    cp16(dA0[0], Ab + (size_t)r0 * lda + cc);
    cp16(dA1[0], Ab + (size_t)r1 * lda + cc);
    if (!TRB) {
        cp16(dB0[0], Bb + (size_t)r0 * ldb + cc);
        cp16(dB1[0], Bb + (size_t)r1 * ldb + cc);
    } else {
        cp16(dT0[0], Bb + (size_t)tr0 * ldb + tc0);
        cp16(dT1[0], Bb + (size_t)tr1 * ldb + tc1);
    }
    CP_COMMIT();

    for (int t = 0; t < T; t++) {
        if (t + 1 < T) {
            int s = (t + 1) & 1;
            int k0 = (t + 1) * 32;
            cp16(dA0[s], Ab + (size_t)r0 * lda + k0 + cc);
            cp16(dA1[s], Ab + (size_t)r1 * lda + k0 + cc);
            if (!TRB) {
                cp16(dB0[s], Bb + (size_t)r0 * ldb + k0 + cc);
                cp16(dB1[s], Bb + (size_t)r1 * ldb + k0 + cc);
            } else {
                cp16(dT0[s], Bb + (size_t)(k0 + tr0) * ldb + tc0);
                cp16(dT1[s], Bb + (size_t)(k0 + tr1) * ldb + tc1);
            }
            CP_COMMIT();
            CP_WAIT(1);
        } else {
            CP_WAIT(0);
        }
        __syncthreads();

        int s = t & 1;
#pragma unroll
        for (int ks = 0; ks < 2; ks++) {
            uint32_t koff = ks * 32;
            uint32_t a[2][4];
#pragma unroll
            for (int mi = 0; mi < 2; mi++) ldm_x4(a[mi], aAddr[s][mi] + koff);
            if (!TRB) {
                uint32_t b[16];
#pragma unroll
                for (int np = 0; np < 4; np++) ldm_x4(b + np * 4, bAddr[s][np] + koff);
#pragma unroll
                for (int ni = 0; ni < 8; ni++) {
                    uint32_t b0 = b[(ni >> 1) * 4 + (ni & 1) * 2];
                    uint32_t b1 = b[(ni >> 1) * 4 + (ni & 1) * 2 + 1];
                    mma_f16(acc[0][ni], a[0], b0, b1);
                    mma_f16(acc[1][ni], a[1], b0, b1);
                }
            } else {
                uint32_t toff = ks * (16 * TBLD * 2);   // 16 k-rows down
#pragma unroll
                for (int nb = 0; nb < 4; nb++) {
                    uint32_t bb[4];
                    ldm_x4t(bb, bAddr[s][nb] + toff);
                    mma_f16(acc[0][2 * nb],     a[0], bb[0], bb[1]);
                    mma_f16(acc[1][2 * nb],     a[1], bb[0], bb[1]);
                    mma_f16(acc[0][2 * nb + 1], a[0], bb[2], bb[3]);
                    mma_f16(acc[1][2 * nb + 1], a[1], bb[2], bb[3]);
                }
            }
        }
        __syncthreads();
    }

#pragma unroll
    for (int mi = 0; mi < 2; mi++) {
        int rg = row0 + wr * 32 + mi * 16 + qid;
#pragma unroll
        for (int ni = 0; ni < 8; ni++) {
            int cg = col0 + wc * 64 + ni * 8 + tig * 2;
            float bx = 0.0f, by = 0.0f;
            if (bias) { bx = bias[cg]; by = bias[cg + 1]; }
            float o0 = alpha * acc[mi][ni][0] + bx;
            float o1 = alpha * acc[mi][ni][1] + by;
            float o2 = alpha * acc[mi][ni][2] + bx;
            float o3 = alpha * acc[mi][ni][3] + by;
            if (Cf && cg < cfN) {
                *reinterpret_cast<float2*>(Cf + (size_t)rg * ldcf + cg)       = make_float2(o0, o1);
                *reinterpret_cast<float2*>(Cf + (size_t)(rg + 8) * ldcf + cg) = make_float2(o2, o3);
            }
            if (Ch) {
                *reinterpret_cast<__half2*>(Ch + (size_t)rg * ldc + cg)       = __floats2half2_rn(o0, o1);
                *reinterpret_cast<__half2*>(Ch + (size_t)(rg + 8) * ldc + cg) = __floats2half2_rn(o2, o3);
            }
        }
    }
}

// ============================================================================
// flash attention: per CTA = (q-tile 128 rows, one (b,h)). online softmax.
// ============================================================================
#define FAQ_LD 168
#define FAV_LD 136
#define FA_SMEM ((3*128*FAQ_LD + 2*128*FAV_LD) * 2)   // 198656 B

__global__ __launch_bounds__(256, 1)
void flash_k(const __half* __restrict__ qp, const __half* __restrict__ kp,
             const __half* __restrict__ ckv, int ldckv,
             __half* __restrict__ u, float scale)
{
    extern __shared__ __half sm[];
    __half* Qs = sm;
    __half* Ks = sm + 128 * FAQ_LD;
    __half* Vs = sm + 3 * 128 * FAQ_LD;

    int tid = threadIdx.x;
    int warp = tid >> 5, lane = tid & 31;
    int qid = lane >> 2, tig = lane & 3;

    int qt = blockIdx.x;
    int z  = blockIdx.y;
    int b = z >> 3, h = z & 7;

    const __half* Qg = qp + ((size_t)(b * SEQ + qt * 128)) * LDQP + h * KP;
    const __half* Kg = kp + ((size_t)b * SEQ) * LDQP + h * KP;
    const __half* Vg = ckv + ((size_t)b * SEQ) * ldckv;

#pragma unroll
    for (int i = 0; i < 10; i++) {
        int idx = tid + i * 256;
        int r = idx / 20, c = idx % 20;
        cp16(smem_u32(Qs + r * FAQ_LD + c * 8), Qg + (size_t)r * LDQP + c * 8);
    }
#pragma unroll
    for (int i = 0; i < 10; i++) {
        int idx = tid + i * 256;
        int r = idx / 20, c = idx % 20;
        cp16(smem_u32(Ks + r * FAQ_LD + c * 8), Kg + (size_t)r * LDQP + c * 8);
    }
#pragma unroll
    for (int i = 0; i < 8; i++) {
        int idx = tid + i * 256;
        int r = idx / 16, c = idx % 16;
        cp16(smem_u32(Vs + r * FAV_LD + c * 8), Vg + (size_t)r * ldckv + c * 8);
    }
    CP_COMMIT();

    uint32_t qAddr = smem_u32(Qs + (warp * 16 + (lane & 15)) * FAQ_LD + (lane >> 4) * 8);
    uint32_t kAddr[2][8], vAddr[2][8];
#pragma unroll
    for (int s = 0; s < 2; s++) {
#pragma unroll
        for (int nb = 0; nb < 8; nb++) {
            kAddr[s][nb] = smem_u32(Ks + s * 128 * FAQ_LD
                + (nb * 16 + (lane & 7) + ((lane >> 4) & 1) * 8) * FAQ_LD
                + ((lane >> 3) & 1) * 8);
            vAddr[s][nb] = smem_u32(Vs + s * 128 * FAV_LD
                + (lane & 15) * FAV_LD
                + nb * 16 + ((lane >> 4) << 3));
        }
    }

    float oacc[16][4];
#pragma unroll
    for (int j = 0; j < 16; j++)
#pragma unroll
        for (int i = 0; i < 4; i++) oacc[j][i] = 0.0f;
    float m0 = -1e30f, m1 = -1e30f, l0 = 0.0f, l1 = 0.0f;

    for (int kt = 0; kt < 16; kt++) {
        CP_WAIT(0);
        __syncthreads();
        if (kt + 1 < 16) {
            int s = (kt + 1) & 1;
            const __half* Kt = Kg + (size_t)(kt + 1) * 128 * LDQP;
            const __half* Vt = Vg + (size_t)(kt + 1) * 128 * ldckv;
#pragma unroll
            for (int i = 0; i < 10; i++) {
                int idx = tid + i * 256;
                int r = idx / 20, c = idx % 20;
                cp16(smem_u32(Ks + s * 128 * FAQ_LD + r * FAQ_LD + c * 8),
                     Kt + (size_t)r * LDQP + c * 8);
            }
#pragma unroll
            for (int i = 0; i < 8; i++) {
                int idx = tid + i * 256;
                int r = idx / 16, c = idx % 16;
                cp16(smem_u32(Vs + s * 128 * FAV_LD + r * FAV_LD + c * 8),
                     Vt + (size_t)r * ldckv + c * 8);
            }
            CP_COMMIT();
        }

        int s = kt & 1;
        float sacc[16][4];
#pragma unroll
        for (int j = 0; j < 16; j++)
#pragma unroll
            for (int i = 0; i < 4; i++) sacc[j][i] = 0.0f;
#pragma unroll
        for (int ks = 0; ks < 10; ks++) {
            uint32_t a[4];
            ldm_x4(a, qAddr + ks * 32);
#pragma unroll
            for (int nb = 0; nb < 8; nb++) {
                uint32_t bb[4];
                ldm_x4(bb, kAddr[s][nb] + ks * 32);
                mma_f16(sacc[2 * nb],     a, bb[0], bb[1]);
                mma_f16(sacc[2 * nb + 1], a, bb[2], bb[3]);
            }
        }
        float mx0 = -1e30f, mx1 = -1e30f;
#pragma unroll
        for (int j = 0; j < 16; j++) {
            sacc[j][0] *= scale; sacc[j][1] *= scale;
            sacc[j][2] *= scale; sacc[j][3] *= scale;
            mx0 = fmaxf(mx0, fmaxf(sacc[j][0], sacc[j][1]));
            mx1 = fmaxf(mx1, fmaxf(sacc[j][2], sacc[j][3]));
        }
        mx0 = fmaxf(mx0, __shfl_xor_sync(0xFFFFFFFF, mx0, 1));
        mx0 = fmaxf(mx0, __shfl_xor_sync(0xFFFFFFFF, mx0, 2));
        mx1 = fmaxf(mx1, __shfl_xor_sync(0xFFFFFFFF, mx1, 1));
        mx1 = fmaxf(mx1, __shfl_xor_sync(0xFFFFFFFF, mx1, 2));
        float mn0 = fmaxf(m0, mx0), mn1 = fmaxf(m1, mx1);
        float f0 = __expf(m0 - mn0), f1 = __expf(m1 - mn1);
        m0 = mn0; m1 = mn1;
        float ts0 = 0.0f, ts1 = 0.0f;
#pragma unroll
        for (int j = 0; j < 16; j++) {
            sacc[j][0] = __expf(sacc[j][0] - m0);
            sacc[j][1] = __expf(sacc[j][1] - m0);
            sacc[j][2] = __expf(sacc[j][2] - m1);
            sacc[j][3] = __expf(sacc[j][3] - m1);
            ts0 += sacc[j][0] + sacc[j][1];
            ts1 += sacc[j][2] + sacc[j][3];
        }
        ts0 += __shfl_xor_sync(0xFFFFFFFF, ts0, 1);
        ts0 += __shfl_xor_sync(0xFFFFFFFF, ts0, 2);
        ts1 += __shfl_xor_sync(0xFFFFFFFF, ts1, 1);
        ts1 += __shfl_xor_sync(0xFFFFFFFF, ts1, 2);
        l0 = l0 * f0 + ts0;
        l1 = l1 * f1 + ts1;
#pragma unroll
        for (int j = 0; j < 16; j++) {
            oacc[j][0] *= f0; oacc[j][1] *= f0;
            oacc[j][2] *= f1; oacc[j][3] *= f1;
        }
#pragma unroll
        for (int kb = 0; kb < 8; kb++) {
            uint32_t a[4];
            a[0] = packh2(sacc[2 * kb][0],     sacc[2 * kb][1]);
            a[1] = packh2(sacc[2 * kb][2],     sacc[2 * kb][3]);
            a[2] = packh2(sacc[2 * kb + 1][0], sacc[2 * kb + 1][1]);
            a[3] = packh2(sacc[2 * kb + 1][2], sacc[2 * kb + 1][3]);
            uint32_t voff = (uint32_t)(kb * 16 * FAV_LD * 2);
#pragma unroll
            for (int nb = 0; nb < 8; nb++) {
                uint32_t bb[4];
                ldm_x4t(bb, vAddr[s][nb] + voff);
                mma_f16(oacc[2 * nb],     a, bb[0], bb[1]);
                mma_f16(oacc[2 * nb + 1], a, bb[2], bb[3]);
            }
        }
    }

    float il0 = 1.0f / l0, il1 = 1.0f / l1;
    int rowg = b * SEQ + qt * 128 + warp * 16;
#pragma unroll
    for (int j = 0; j < 16; j++) {
        int col = h * 128 + j * 8 + tig * 2;
        *reinterpret_cast<__half2*>(u + (size_t)(rowg + qid) * (NH * DKV) + col)
            = __floats2half2_rn(oacc[j][0] * il0, oacc[j][1] * il0);
        *reinterpret_cast<__half2*>(u + (size_t)(rowg + qid + 8) * (NH * DKV) + col)
            = __floats2half2_rn(oacc[j][2] * il1, oacc[j][3] * il1);
    }
}

// ============================================================================
// small kernels
// ============================================================================
__global__ __launch_bounds__(256)
void transpose_f2h(const float* __restrict__ in, __half* __restrict__ out, int ldi, int ldo)
{
    __shared__ float t[32][33];
    int bx = blockIdx.x * 32, by = blockIdx.y * 32;
    int tx = threadIdx.x & 31, ty = threadIdx.x >> 5;
#pragma unroll
    for (int i = 0; i < 4; i++)
        t[ty + 8 * i][tx] = in[(size_t)(by + ty + 8 * i) * ldi + bx + tx];
    __syncthreads();
#pragma unroll
    for (int i = 0; i < 4; i++)
        out[(size_t)(bx + ty + 8 * i) * ldo + by + tx] = __float2half_rn(t[tx][ty + 8 * i]);
}

__global__ void f2h_k(const float* __restrict__ in, __half* __restrict__ out, int n4)
{
    int i = blockIdx.x * blockDim.x + threadIdx.x;
    if (i >= n4) return;
    float4 v = *reinterpret_cast<const float4*>(in + (size_t)i * 4);
    __half2 a = __floats2half2_rn(v.x, v.y);
    __half2 b = __floats2half2_rn(v.z, v.w);
    *reinterpret_cast<uint2*>(out + (size_t)i * 4) = make_uint2(
        *reinterpret_cast<uint32_t*>(&a), *reinterpret_cast<uint32_t*>(&b));
}

__global__ void pad_w_k(const float* __restrict__ in, __half* __restrict__ out)
{
    int idx = blockIdx.x * blockDim.x + threadIdx.x;
    if (idx >= DKV * NH * DH) return;
    int i = idx / (NH * DH);
    int c = idx % (NH * DH);
    int h = c / DH, d = c % DH;
    float v = (d < SPLITD) ? in[(size_t)i * (NH * SPLITD) + h * SPLITD + d] : 0.0f;
    out[idx] = __float2half_rn(v);
}

// coalesced bias2: each thread owns one n; loops over m reading consecutive n
__global__ __launch_bounds__(256)
void bias2c_k(const float* __restrict__ outw, const float* __restrict__ outb,
              const float* __restrict__ buv, float* __restrict__ o)
{
    int n = blockIdx.x * 256 + threadIdx.x;
    float s = 0.0f;
    for (int m = 0; m < DM; m++) s += buv[m] * outw[(size_t)m * DM + n];
    o[n] = outb[n] + s;
}

__global__ void bqrow_k(const float* __restrict__ buq, const float* __restrict__ wuk,
                        float* __restrict__ o)
{
    int idx = blockIdx.x * blockDim.x + threadIdx.x;
    if (idx >= NH * DKV) return;
    int h = idx / DKV, n = idx % DKV;
    float s = 0.0f;
    for (int d = 0; d < SPLITD; d++)
        s += buq[h * SPLITD + d] * wuk[(size_t)n * (NH * SPLITD) + h * SPLITD + d];
    o[idx] = s;
}

__global__ void wh_k(const float* __restrict__ wuq, const float* __restrict__ buk,
                     const float* __restrict__ buq, float* __restrict__ o, float* __restrict__ sc)
{
    int idx = blockIdx.x * blockDim.x + threadIdx.x;
    if (idx >= NH * DKV) return;
    int h = idx / DKV, k = idx % DKV;
    float s = 0.0f;
    for (int d = 0; d < SPLITD; d++)
        s += wuq[(size_t)k * (NH * SPLITD) + h * SPLITD + d] * buk[h * SPLITD + d];
    o[idx] = s;
    if (k == 0) {
        float c = 0.0f;
        for (int d = 0; d < SPLITD; d++) c += buq[h * SPLITD + d] * buk[h * SPLITD + d];
        sc[h] = c;
    }
}

__global__ void bias_cat2(const float* a, const float* b, float* o, int n1, int n2)
{
    int i = blockIdx.x * blockDim.x + threadIdx.x;
    if (i >= n1 + n2) return;
    o[i] = (i < n1) ? a[i] : b[i - n1];
}

// s_q column + zero pad cols 145..159
__global__ void sq_k(const __half* __restrict__ cq, int ldcq, const float* __restrict__ wh,
                     const float* __restrict__ scst, __half* __restrict__ qp)
{
    int idx = blockIdx.x * blockDim.x + threadIdx.x;
    if (idx >= MROWS * NH) return;
    int m = idx / NH, h = idx % NH;
    float s = scst[h];
    for (int k = 0; k < DKV; k++)
        s += __half2float(cq[(size_t)m * ldcq + k]) * wh[h * DKV + k];
    __half* p = qp + (size_t)m * LDQP + h * KP;
    p[144] = __float2half_rn(s);
    __half z = __float2half_rn(0.0f);
    for (int c = 145; c < KP; c++) p[c] = z;
}

__global__ void kpfill_k(const __half* __restrict__ ckv, int ldckv, __half* __restrict__ kp)
{
    int idx = blockIdx.x * blockDim.x + threadIdx.x;
    int total = MROWS * NH * 18;
    if (idx >= total) return;
    int c = idx % 18;
    int mh = idx / 18;
    int m = mh / NH, h = mh % NH;
    __half* p = kp + (size_t)m * LDQP + h * KP;
    if (c < 16) {
        uint4 v = *reinterpret_cast<const uint4*>(ckv + (size_t)m * ldckv + c * 8);
        *reinterpret_cast<uint4*>(p + c * 8) = v;
    } else if (c == 16) {
        __half z = __float2half_rn(0.0f);
        __half vals[8] = { __float2half_rn(1.0f), z, z, z, z, z, z, z };
        *reinterpret_cast<uint4*>(p + 144) = *reinterpret_cast<uint4*>(vals);
    } else {
        __half z = __float2half_rn(0.0f);
        __half vals[8] = { z, z, z, z, z, z, z, z };
        *reinterpret_cast<uint4*>(p + 152) = *reinterpret_cast<uint4*>(vals);
    }
}

// merged RoPE for both sides: side 0 = k (krp -> kp, + float out), side 1 = q (qrp -> qp)
__global__ void rope2_k(const __half* __restrict__ krp, const __half* __restrict__ qrp,
                        __half* __restrict__ kp, __half* __restrict__ qp,
                        float* __restrict__ rout)
{
    int gidx = blockIdx.x * blockDim.x + threadIdx.x;
    if (gidx >= 2 * MROWS * DKV) return;
    int side = gidx >= MROWS * DKV;
    int idx  = side ? gidx - MROWS * DKV : gidx;
    const __half* pre = side ? qrp : krp;
    __half* dst = side ? qp : kp;
    int m = idx >> 7;
    int c = idx & 127;
    int h = c >> 4;
    int d = c & 15;
    int j = d & 7;
    int s = m & (SEQ - 1);
    float t = (float)s * (1.0f / 40.0f);
    float invf = __expf(-(float)j * 0.86346941f);  // ln(1000)/8
    float ang = t * invf;
    float sn, cs;
    sincosf(ang, &sn, &cs);
    float x = __half2float(pre[idx]);
    float p = __half2float(pre[(m << 7) + (h << 4) + ((d < 8) ? d + 8 : d - 8)]);
    float val = x * cs + ((d < 8) ? -p : p) * sn;
    dst[(size_t)m * LDQP + h * KP + 128 + d] = __float2half_rn(val);
    if (!side && rout) rout[idx] = val;
}

// ============================================================================
// host launcher
// ============================================================================
extern "C" void kernel_launch(void* const* d_in, const int* in_sizes, int n_in,
                              void* d_out, int out_size)
{
    const float* h    = (const float*)d_in[0];
    const float* Wdkv = (const float*)d_in[1];
    const float* bdkv = (const float*)d_in[2];
    const float* Wdq  = (const float*)d_in[3];
    const float* bdq  = (const float*)d_in[4];
    const float* Wuk  = (const float*)d_in[5];
    const float* buk  = (const float*)d_in[6];
    const float* Wuv  = (const float*)d_in[7];
    const float* buv  = (const float*)d_in[8];
    const float* Wuq  = (const float*)d_in[9];
    const float* buq  = (const float*)d_in[10];
    const float* Wqr  = (const float*)d_in[11];
    const float* bqr  = (const float*)d_in[12];
    const float* Wkr  = (const float*)d_in[13];
    const float* bkr  = (const float*)d_in[14];
    const float* outw = (const float*)d_in[15];
    const float* outb = (const float*)d_in[16];
    float* out = (float*)d_out;

    __half *hh, *ckvcq, *krqrp, *qp, *kp, *u;
    __half *wdd, *wkq, *wout_h, *wuv_h, *wuq_p, *wuk_p, *mt, *w2;
    float *ckvf, *bias2, *bqrow, *wh, *scst, *bdd, *bkq;
    cudaGetSymbolAddress((void**)&hh,    g_hh);
    cudaGetSymbolAddress((void**)&ckvcq, g_ckvcq);
    cudaGetSymbolAddress((void**)&krqrp, g_krqrp);
    cudaGetSymbolAddress((void**)&qp,    g_qp);
    cudaGetSymbolAddress((void**)&kp,    g_kp);
    cudaGetSymbolAddress((void**)&u,     g_u);
    cudaGetSymbolAddress((void**)&ckvf,  g_ckvf);
    cudaGetSymbolAddress((void**)&wdd,   g_wdd);
    cudaGetSymbolAddress((void**)&wkq,   g_wkq);
    cudaGetSymbolAddress((void**)&wout_h, g_wout_h);
    cudaGetSymbolAddress((void**)&wuv_h,  g_wuv_h);
    cudaGetSymbolAddress((void**)&wuq_p,  g_wuq_p);
    cudaGetSymbolAddress((void**)&wuk_p,  g_wuk_p);
    cudaGetSymbolAddress((void**)&mt,     g_mt);
    cudaGetSymbolAddress((void**)&w2,     g_w2);
    cudaGetSymbolAddress((void**)&bias2,  g_bias2);
    cudaGetSymbolAddress((void**)&bqrow,  g_bqrow);
    cudaGetSymbolAddress((void**)&wh,     g_wh);
    cudaGetSymbolAddress((void**)&scst,   g_sconst);
    cudaGetSymbolAddress((void**)&bdd,    g_bdd);
    cudaGetSymbolAddress((void**)&bkq,    g_bkq);

    cudaFuncSetAttribute(flash_k, cudaFuncAttributeMaxDynamicSharedMemorySize, FA_SMEM);

    dim3 b256(256);
    f2h_k<<<((size_t)MROWS * DM / 4 + 255) / 256, 256>>>(h, hh, MROWS * DM / 4);
    f2h_k<<<(DKV * DM / 4 + 255) / 256, 256>>>(Wuv, wuv_h, DKV * DM / 4);
    f2h_k<<<((size_t)DM * DM / 4 + 255) / 256, 256>>>(outw, wout_h, (int)((size_t)DM * DM / 4));
    transpose_f2h<<<dim3(DKV/32, DM/32), b256>>>(Wdkv, wdd,                 DKV, DM);
    transpose_f2h<<<dim3(DKV/32, DM/32), b256>>>(Wdq,  wdd + (size_t)DKV*DM, DKV, DM);
    transpose_f2h<<<dim3(DKV/32, DKV/32), b256>>>(Wkr, wkq,                 DKV, DKV);
    transpose_f2h<<<dim3(DKV/32, DKV/32), b256>>>(Wqr, wkq + DKV*DKV,       DKV, DKV);
    pad_w_k<<<(DKV * NH * DH + 255) / 256, 256>>>(Wuq, wuq_p);
    pad_w_k<<<(DKV * NH * DH + 255) / 256, 256>>>(Wuk, wuk_p);
    bias2c_k<<<DM / 256, 256>>>(outw, outb, buv, bias2);
    bqrow_k<<<(NH * DKV + 255) / 256, 256>>>(buq, Wuk, bqrow);
    wh_k<<<(NH * DKV + 255) / 256, 256>>>(Wuq, buk, buq, wh, scst);
    bias_cat2<<<(NDD + 255) / 256, 256>>>(bdkv, bdq, bdd, DKV, DKV);
    bias_cat2<<<(2 * DKV + 255) / 256, 256>>>(bkr, bqr, bkq, DKV, DKV);

    const size_t out_ckv_off  = (size_t)MROWS * DM;
    const size_t out_krot_off = out_ckv_off + (size_t)MROWS * DKV;
    bool full_out = (size_t)out_size >= out_krot_off + (size_t)MROWS * DKV;
    float* ckv_dst = full_out ? (out + out_ckv_off) : ckvf;

    dim3 blk(256);
    auto grd = [](int M, int N, int Z) { return dim3((unsigned)(N / 128), (unsigned)(M / 128), (unsigned)Z); };

    // precompute Mt_h = Wuk_h Wuq_h^T  [8][128][128]
    hgemm<false><<<grd(DKV, DKV, NH), blk>>>(wuk_p, wuq_p, nullptr, mt, nullptr,
        DKV, DKV, DH, NH*DH, NH*DH, DKV, DKV, 0, 1.0f,
        0, DH, 0, DH, 0, DKV*DKV, 0, NH);
    // precompute w2[h*128+j, n] = sum_d Wuv[j, h*640+d] * Wout[h*640+d, n]   (TRB)
    hgemm<true><<<grd(DKV, DM, NH), blk>>>(wuv_h, wout_h, nullptr, w2, nullptr,
        DKV, DM, DH, DM, DM, DM, DM, 0, 1.0f,
        0, DH, 0, (long long)DH * DM, 0, (long long)DKV * DM, 0, NH);

    // 1) merged down projection: [ckv|cq] = h @ [Wdkv|Wdq] ; float ckv to output
    hgemm<false><<<grd(MROWS, NDD, 1), blk>>>(hh, wdd, ckv_dst, ckvcq, bdd,
        MROWS, NDD, DM, DM, DM, NDD, DKV, DKV, 1.0f, 0,0,0,0,0,0,0, 1);

    // 2) merged rotary pre-projections: z=0: krp = ckv@Wkr^T; z=1: qrp = cq@Wqr^T
    hgemm<false><<<grd(MROWS, DKV, 2), blk>>>(ckvcq, wkq, nullptr, krqrp, bkq,
        MROWS, DKV, DKV, NDD, DKV, DKV, DKV, 0, 1.0f,
        0, DKV, 0, DKV*DKV, 0, (long long)MROWS*DKV, DKV, 2);

    // 3) q-tilde = cq @ Mt_h^T + bqrow_h  -> qp cols [h*KP .. h*KP+127]
    hgemm<false><<<grd(MROWS, DKV, NH), blk>>>(ckvcq + DKV, mt, nullptr, qp, bqrow,
        MROWS, DKV, DKV, NDD, DKV, LDQP, LDQP, 0, 1.0f,
        0, 0, 0, DKV*DKV, 0, KP, DKV, NH);

    // 4) assemble qp / kp
    rope2_k<<<(2 * MROWS * DKV + 255) / 256, 256>>>(krqrp, krqrp + (size_t)MROWS * DKV,
        kp, qp, full_out ? (out + out_krot_off) : nullptr);
    sq_k<<<(MROWS * NH + 255) / 256, 256>>>(ckvcq + DKV, NDD, wh, scst, qp);
    kpfill_k<<<(MROWS * NH * 18 + 255) / 256, 256>>>(ckvcq, NDD, kp);

    // 5) fused flash attention -> u [4096, 1024]
    float inv_sqrt = 1.0f / sqrtf((float)DH);
    flash_k<<<dim3(SEQ/128, BATCH*NH), blk, FA_SMEM>>>(qp, kp, ckvcq, NDD, u, inv_sqrt);

    // 6) out = u @ w2 + bias2   [4096,5120]  (TRB: w2 is [1024,5120] NN)
    hgemm<true><<<grd(MROWS, DM, 1), blk>>>(u, w2, out, nullptr, bias2,
        MROWS, DM, NH*DKV, NH*DKV, DM, DM, DM, DM, 1.0f, 0,0,0,0,0,0,0, 1);
}

// round 11
// speedup vs baseline: 1.0282x; 1.0282x over previous
#include <cuda_runtime.h>
#include <cuda_fp16.h>
#include <math.h>
#include <stdint.h>

// ---------------- problem constants ----------------
#define BATCH 2
#define SEQ   2048
#define DM    5120
#define NH    8
#define DH    640
#define DR    16
#define SPLITD 624
#define DKV   128
#define MROWS (BATCH*SEQ)        // 4096
#define KP    160                // per-head score K-dim: [128 ckv |16 rope |1 bias |15 pad]
#define LDQP  (NH*KP)            // 1280
#define NDD   256                // merged down-proj N: [ckv|cq]

// ---------------- scratch (device globals; no allocs allowed) ----------------
__device__ __align__(16) __half g_hh   [(size_t)MROWS*DM];
__device__ __align__(16) __half g_ckvcq[(size_t)MROWS*NDD];   // [ckv(0:128) | cq(128:256)]
__device__ __align__(16) __half g_krqrp[2*MROWS*DKV];          // [krp | qrp]
__device__ __align__(16) __half g_qp   [(size_t)MROWS*LDQP];
__device__ __align__(16) __half g_kp   [(size_t)MROWS*LDQP];
__device__ __align__(16) __half g_u    [(size_t)MROWS*NH*DKV]; // [4096,1024]
__device__ __align__(16) float  g_ckvf [MROWS*DKV];
__device__ __align__(16) float  g_part [2*(size_t)MROWS*NDD];  // split-K partials
// weights
__device__ __align__(16) __half g_wdd  [(size_t)NDD*DM];       // [wt_dkv; wt_dq] [256,5120]
__device__ __align__(16) __half g_wkq  [2*DKV*DKV];            // [wt_kr; wt_qr]
__device__ __align__(16) __half g_wt_out[(size_t)DM*DM];       // Wout^T [DM, NH*DH]
__device__ __align__(16) __half g_wuv_h [DKV*DM];
__device__ __align__(16) __half g_wuq_p [DKV*NH*DH];           // zero-padded 624->640
__device__ __align__(16) __half g_wuk_p [DKV*NH*DH];
__device__ __align__(16) __half g_mt    [NH*DKV*DKV];          // Mt_h = Wuk_h Wuq_h^T
__device__ __align__(16) __half g_w2t   [(size_t)DM*NH*DKV];   // [5120,1024] K-major
__device__ __align__(16) float  g_bias2 [DM];
__device__ __align__(16) float  g_bqrow [NH*DKV];
__device__ __align__(16) float  g_wh    [NH*DKV];
__device__ __align__(16) float  g_sconst[NH];
__device__ __align__(16) float  g_bdd   [NDD];
__device__ __align__(16) float  g_bkq   [2*DKV];

// ---------------- PTX helpers ----------------
__device__ __forceinline__ uint32_t smem_u32(const void* p) {
    uint32_t a;
    asm("{ .reg .u64 t; cvta.to.shared.u64 t, %1; cvt.u32.u64 %0, t; }" : "=r"(a) : "l"(p));
    return a;
}
__device__ __forceinline__ void cp16(uint32_t dst, const void* src) {
    asm volatile("cp.async.cg.shared.global [%0], [%1], 16;" :: "r"(dst), "l"(src) : "memory");
}
#define CP_COMMIT() asm volatile("cp.async.commit_group;" ::: "memory")
#define CP_WAIT(n)  asm volatile("cp.async.wait_group %0;" :: "n"(n) : "memory")

__device__ __forceinline__ void ldm_x4(uint32_t* r, uint32_t addr) {
    asm volatile("ldmatrix.sync.aligned.m8n8.x4.shared.b16 {%0,%1,%2,%3}, [%4];"
                 : "=r"(r[0]), "=r"(r[1]), "=r"(r[2]), "=r"(r[3]) : "r"(addr));
}
__device__ __forceinline__ void ldm_x4t(uint32_t* r, uint32_t addr) {
    asm volatile("ldmatrix.sync.aligned.m8n8.x4.trans.shared.b16 {%0,%1,%2,%3}, [%4];"
                 : "=r"(r[0]), "=r"(r[1]), "=r"(r[2]), "=r"(r[3]) : "r"(addr));
}
__device__ __forceinline__ void mma_f16(float* c, const uint32_t* a, uint32_t b0, uint32_t b1) {
    asm volatile("mma.sync.aligned.m16n8k16.row.col.f32.f16.f16.f32 "
                 "{%0,%1,%2,%3}, {%4,%5,%6,%7}, {%8,%9}, {%0,%1,%2,%3};"
                 : "+f"(c[0]), "+f"(c[1]), "+f"(c[2]), "+f"(c[3])
                 : "r"(a[0]), "r"(a[1]), "r"(a[2]), "r"(a[3]), "r"(b0), "r"(b1));
}
__device__ __forceinline__ uint32_t packh2(float x, float y) {
    __half2 h = __floats2half2_rn(x, y);
    return *reinterpret_cast<uint32_t*>(&h);
}

// ============================================================================
// fp16 mma.sync GEMM (R9-proven): C = alpha*A[M,K]*B[N,K]^T + bias.
// 128x128 tile, BK=32, 2-stage. Cf cols < cfN (ld ldcf); Ch full (ld ldc).
// ============================================================================
#define SPADH 40

__global__ __launch_bounds__(256)
void hgemm(const __half* __restrict__ A, const __half* __restrict__ B,
           float* __restrict__ Cf, __half* __restrict__ Ch,
           const float* __restrict__ bias,
           int M, int N, int K, int lda, int ldb, int ldc, int ldcf, int cfN,
           float alpha,
           long long sAhi, long long sAlo, long long sBhi, long long sBlo,
           long long sChi, long long sClo, long long sBiasLo, int zdiv)
{
    __shared__ __half As[2][128][SPADH];
    __shared__ __half Bs[2][128][SPADH];

    int tid  = threadIdx.x;
    int warp = tid >> 5;
    int lane = tid & 31;
    int wr = warp >> 1;
    int wc = warp & 1;
    int qid = lane >> 2;
    int tig = lane & 3;

    int z  = blockIdx.z;
    int zh = z / zdiv, zl = z % zdiv;
    A += zh * sAhi + zl * sAlo;
    B += zh * sBhi + zl * sBlo;
    long long cofs = zh * sChi + zl * sClo;
    if (Cf) Cf += cofs;
    if (Ch) Ch += cofs;
    if (bias) bias += zl * sBiasLo;

    int row0 = blockIdx.y * 128, col0 = blockIdx.x * 128;
    const __half* Ab = A + (size_t)row0 * lda;
    const __half* Bb = B + (size_t)col0 * ldb;

    int r0 = tid >> 2, cc = (tid & 3) * 8;
    int r1 = r0 + 64;
    uint32_t dA0[2], dA1[2], dB0[2], dB1[2];
#pragma unroll
    for (int s = 0; s < 2; s++) {
        dA0[s] = smem_u32(&As[s][r0][cc]);
        dA1[s] = smem_u32(&As[s][r1][cc]);
        dB0[s] = smem_u32(&Bs[s][r0][cc]);
        dB1[s] = smem_u32(&Bs[s][r1][cc]);
    }
    uint32_t aAddr[2][2], bAddr[2][4];
#pragma unroll
    for (int s = 0; s < 2; s++) {
#pragma unroll
        for (int mi = 0; mi < 2; mi++)
            aAddr[s][mi] = smem_u32(&As[s][wr * 32 + mi * 16 + (lane & 15)][(lane >> 4) * 8]);
#pragma unroll
        for (int np = 0; np < 4; np++)
            bAddr[s][np] = smem_u32(&Bs[s][wc * 64 + np * 16 + (lane & 7) + ((lane >> 4) & 1) * 8]
                                        [((lane >> 3) & 1) * 8]);
    }

    float acc[2][8][4];
#pragma unroll
    for (int mi = 0; mi < 2; mi++)
#pragma unroll
        for (int ni = 0; ni < 8; ni++)
#pragma unroll
            for (int i = 0; i < 4; i++) acc[mi][ni][i] = 0.0f;

    int T = K >> 5;

    cp16(dA0[0], Ab + (size_t)r0 * lda + cc);
    cp16(dA1[0], Ab + (size_t)r1 * lda + cc);
    cp16(dB0[0], Bb + (size_t)r0 * ldb + cc);
    cp16(dB1[0], Bb + (size_t)r1 * ldb + cc);
    CP_COMMIT();

    for (int t = 0; t < T; t++) {
        if (t + 1 < T) {
            int s = (t + 1) & 1;
            int k0 = (t + 1) * 32;
            cp16(dA0[s], Ab + (size_t)r0 * lda + k0 + cc);
            cp16(dA1[s], Ab + (size_t)r1 * lda + k0 + cc);
            cp16(dB0[s], Bb + (size_t)r0 * ldb + k0 + cc);
            cp16(dB1[s], Bb + (size_t)r1 * ldb + k0 + cc);
            CP_COMMIT();
            CP_WAIT(1);
        } else {
            CP_WAIT(0);
        }
        __syncthreads();

        int s = t & 1;
#pragma unroll
        for (int ks = 0; ks < 2; ks++) {
            uint32_t koff = ks * 32;
            uint32_t a[2][4], b[16];
#pragma unroll
            for (int mi = 0; mi < 2; mi++) ldm_x4(a[mi], aAddr[s][mi] + koff);
#pragma unroll
            for (int np = 0; np < 4; np++) ldm_x4(b + np * 4, bAddr[s][np] + koff);
#pragma unroll
            for (int ni = 0; ni < 8; ni++) {
                uint32_t b0 = b[(ni >> 1) * 4 + (ni & 1) * 2];
                uint32_t b1 = b[(ni >> 1) * 4 + (ni & 1) * 2 + 1];
                mma_f16(acc[0][ni], a[0], b0, b1);
                mma_f16(acc[1][ni], a[1], b0, b1);
            }
        }
        __syncthreads();
    }

#pragma unroll
    for (int mi = 0; mi < 2; mi++) {
        int rg = row0 + wr * 32 + mi * 16 + qid;
#pragma unroll
        for (int ni = 0; ni < 8; ni++) {
            int cg = col0 + wc * 64 + ni * 8 + tig * 2;
            float bx = 0.0f, by = 0.0f;
            if (bias) { bx = bias[cg]; by = bias[cg + 1]; }
            float o0 = alpha * acc[mi][ni][0] + bx;
            float o1 = alpha * acc[mi][ni][1] + by;
            float o2 = alpha * acc[mi][ni][2] + bx;
            float o3 = alpha * acc[mi][ni][3] + by;
            if (Cf && cg < cfN) {
                *reinterpret_cast<float2*>(Cf + (size_t)rg * ldcf + cg)       = make_float2(o0, o1);
                *reinterpret_cast<float2*>(Cf + (size_t)(rg + 8) * ldcf + cg) = make_float2(o2, o3);
            }
            if (Ch) {
                *reinterpret_cast<__half2*>(Ch + (size_t)rg * ldc + cg)       = __floats2half2_rn(o0, o1);
                *reinterpret_cast<__half2*>(Ch + (size_t)(rg + 8) * ldc + cg) = __floats2half2_rn(o2, o3);
            }
        }
    }
}

// ============================================================================
// flash attention (R9-proven): per CTA = (q-tile 128 rows, one (b,h)).
// ============================================================================
#define FAQ_LD 168
#define FAV_LD 136
#define FA_SMEM ((3*128*FAQ_LD + 2*128*FAV_LD) * 2)   // 198656 B

__global__ __launch_bounds__(256, 1)
void flash_k(const __half* __restrict__ qp, const __half* __restrict__ kp,
             const __half* __restrict__ ckv, int ldckv,
             __half* __restrict__ u, float scale)
{
    extern __shared__ __half sm[];
    __half* Qs = sm;
    __half* Ks = sm + 128 * FAQ_LD;
    __half* Vs = sm + 3 * 128 * FAQ_LD;

    int tid = threadIdx.x;
    int warp = tid >> 5, lane = tid & 31;
    int qid = lane >> 2, tig = lane & 3;

    int qt = blockIdx.x;
    int z  = blockIdx.y;
    int b = z >> 3, h = z & 7;

    const __half* Qg = qp + ((size_t)(b * SEQ + qt * 128)) * LDQP + h * KP;
    const __half* Kg = kp + ((size_t)b * SEQ) * LDQP + h * KP;
    const __half* Vg = ckv + ((size_t)b * SEQ) * ldckv;

#pragma unroll
    for (int i = 0; i < 10; i++) {
        int idx = tid + i * 256;
        int r = idx / 20, c = idx % 20;
        cp16(smem_u32(Qs + r * FAQ_LD + c * 8), Qg + (size_t)r * LDQP + c * 8);
    }
#pragma unroll
    for (int i = 0; i < 10; i++) {
        int idx = tid + i * 256;
        int r = idx / 20, c = idx % 20;
        cp16(smem_u32(Ks + r * FAQ_LD + c * 8), Kg + (size_t)r * LDQP + c * 8);
    }
#pragma unroll
    for (int i = 0; i < 8; i++) {
        int idx = tid + i * 256;
        int r = idx / 16, c = idx % 16;
        cp16(smem_u32(Vs + r * FAV_LD + c * 8), Vg + (size_t)r * ldckv + c * 8);
    }
    CP_COMMIT();

    uint32_t qAddr = smem_u32(Qs + (warp * 16 + (lane & 15)) * FAQ_LD + (lane >> 4) * 8);
    uint32_t kAddr[2][8], vAddr[2][8];
#pragma unroll
    for (int s = 0; s < 2; s++) {
#pragma unroll
        for (int nb = 0; nb < 8; nb++) {
            kAddr[s][nb] = smem_u32(Ks + s * 128 * FAQ_LD
                + (nb * 16 + (lane & 7) + ((lane >> 4) & 1) * 8) * FAQ_LD
                + ((lane >> 3) & 1) * 8);
            vAddr[s][nb] = smem_u32(Vs + s * 128 * FAV_LD
                + (lane & 15) * FAV_LD
                + nb * 16 + ((lane >> 4) << 3));
        }
    }

    float oacc[16][4];
#pragma unroll
    for (int j = 0; j < 16; j++)
#pragma unroll
        for (int i = 0; i < 4; i++) oacc[j][i] = 0.0f;
    float m0 = -1e30f, m1 = -1e30f, l0 = 0.0f, l1 = 0.0f;

    for (int kt = 0; kt < 16; kt++) {
        CP_WAIT(0);
        __syncthreads();
        if (kt + 1 < 16) {
            int s = (kt + 1) & 1;
            const __half* Kt = Kg + (size_t)(kt + 1) * 128 * LDQP;
            const __half* Vt = Vg + (size_t)(kt + 1) * 128 * ldckv;
#pragma unroll
            for (int i = 0; i < 10; i++) {
                int idx = tid + i * 256;
                int r = idx / 20, c = idx % 20;
                cp16(smem_u32(Ks + s * 128 * FAQ_LD + r * FAQ_LD + c * 8),
                     Kt + (size_t)r * LDQP + c * 8);
            }
#pragma unroll
            for (int i = 0; i < 8; i++) {
                int idx = tid + i * 256;
                int r = idx / 16, c = idx % 16;
                cp16(smem_u32(Vs + s * 128 * FAV_LD + r * FAV_LD + c * 8),
                     Vt + (size_t)r * ldckv + c * 8);
            }
            CP_COMMIT();
        }

        int s = kt & 1;
        float sacc[16][4];
#pragma unroll
        for (int j = 0; j < 16; j++)
#pragma unroll
            for (int i = 0; i < 4; i++) sacc[j][i] = 0.0f;
#pragma unroll
        for (int ks = 0; ks < 10; ks++) {
            uint32_t a[4];
            ldm_x4(a, qAddr + ks * 32);
#pragma unroll
            for (int nb = 0; nb < 8; nb++) {
                uint32_t bb[4];
                ldm_x4(bb, kAddr[s][nb] + ks * 32);
                mma_f16(sacc[2 * nb],     a, bb[0], bb[1]);
                mma_f16(sacc[2 * nb + 1], a, bb[2], bb[3]);
            }
        }
        float mx0 = -1e30f, mx1 = -1e30f;
#pragma unroll
        for (int j = 0; j < 16; j++) {
            sacc[j][0] *= scale; sacc[j][1] *= scale;
            sacc[j][2] *= scale; sacc[j][3] *= scale;
            mx0 = fmaxf(mx0, fmaxf(sacc[j][0], sacc[j][1]));
            mx1 = fmaxf(mx1, fmaxf(sacc[j][2], sacc[j][3]));
        }
        mx0 = fmaxf(mx0, __shfl_xor_sync(0xFFFFFFFF, mx0, 1));
        mx0 = fmaxf(mx0, __shfl_xor_sync(0xFFFFFFFF, mx0, 2));
        mx1 = fmaxf(mx1, __shfl_xor_sync(0xFFFFFFFF, mx1, 1));
        mx1 = fmaxf(mx1, __shfl_xor_sync(0xFFFFFFFF, mx1, 2));
        float mn0 = fmaxf(m0, mx0), mn1 = fmaxf(m1, mx1);
        float f0 = __expf(m0 - mn0), f1 = __expf(m1 - mn1);
        m0 = mn0; m1 = mn1;
        float ts0 = 0.0f, ts1 = 0.0f;
#pragma unroll
        for (int j = 0; j < 16; j++) {
            sacc[j][0] = __expf(sacc[j][0] - m0);
            sacc[j][1] = __expf(sacc[j][1] - m0);
            sacc[j][2] = __expf(sacc[j][2] - m1);
            sacc[j][3] = __expf(sacc[j][3] - m1);
            ts0 += sacc[j][0] + sacc[j][1];
            ts1 += sacc[j][2] + sacc[j][3];
        }
        ts0 += __shfl_xor_sync(0xFFFFFFFF, ts0, 1);
        ts0 += __shfl_xor_sync(0xFFFFFFFF, ts0, 2);
        ts1 += __shfl_xor_sync(0xFFFFFFFF, ts1, 1);
        ts1 += __shfl_xor_sync(0xFFFFFFFF, ts1, 2);
        l0 = l0 * f0 + ts0;
        l1 = l1 * f1 + ts1;
#pragma unroll
        for (int j = 0; j < 16; j++) {
            oacc[j][0] *= f0; oacc[j][1] *= f0;
            oacc[j][2] *= f1; oacc[j][3] *= f1;
        }
#pragma unroll
        for (int kb = 0; kb < 8; kb++) {
            uint32_t a[4];
            a[0] = packh2(sacc[2 * kb][0],     sacc[2 * kb][1]);
            a[1] = packh2(sacc[2 * kb][2],     sacc[2 * kb][3]);
            a[2] = packh2(sacc[2 * kb + 1][0], sacc[2 * kb + 1][1]);
            a[3] = packh2(sacc[2 * kb + 1][2], sacc[2 * kb + 1][3]);
            uint32_t voff = (uint32_t)(kb * 16 * FAV_LD * 2);
#pragma unroll
            for (int nb = 0; nb < 8; nb++) {
                uint32_t bb[4];
                ldm_x4t(bb, vAddr[s][nb] + voff);
                mma_f16(oacc[2 * nb],     a, bb[0], bb[1]);
                mma_f16(oacc[2 * nb + 1], a, bb[2], bb[3]);
            }
        }
    }

    float il0 = 1.0f / l0, il1 = 1.0f / l1;
    int rowg = b * SEQ + qt * 128 + warp * 16;
#pragma unroll
    for (int j = 0; j < 16; j++) {
        int col = h * 128 + j * 8 + tig * 2;
        *reinterpret_cast<__half2*>(u + (size_t)(rowg + qid) * (NH * DKV) + col)
            = __floats2half2_rn(oacc[j][0] * il0, oacc[j][1] * il0);
        *reinterpret_cast<__half2*>(u + (size_t)(rowg + qid + 8) * (NH * DKV) + col)
            = __floats2half2_rn(oacc[j][2] * il1, oacc[j][3] * il1);
    }
}

// ============================================================================
// small kernels
// ============================================================================
__global__ __launch_bounds__(256)
void transpose_f2h(const float* __restrict__ in, __half* __restrict__ out, int ldi, int ldo)
{
    __shared__ float t[32][33];
    int bx = blockIdx.x * 32, by = blockIdx.y * 32;
    int tx = threadIdx.x & 31, ty = threadIdx.x >> 5;
#pragma unroll
    for (int i = 0; i < 4; i++)
        t[ty + 8 * i][tx] = in[(size_t)(by + ty + 8 * i) * ldi + bx + tx];
    __syncthreads();
#pragma unroll
    for (int i = 0; i < 4; i++)
        out[(size_t)(bx + ty + 8 * i) * ldo + by + tx] = __float2half_rn(t[tx][ty + 8 * i]);
}

__global__ void f2h_k(const float* __restrict__ in, __half* __restrict__ out, int n4)
{
    int i = blockIdx.x * blockDim.x + threadIdx.x;
    if (i >= n4) return;
    float4 v = *reinterpret_cast<const float4*>(in + (size_t)i * 4);
    __half2 a = __floats2half2_rn(v.x, v.y);
    __half2 b = __floats2half2_rn(v.z, v.w);
    *reinterpret_cast<uint2*>(out + (size_t)i * 4) = make_uint2(
        *reinterpret_cast<uint32_t*>(&a), *reinterpret_cast<uint32_t*>(&b));
}

// merged pad for both Wuq and Wuk
__global__ void pad_w2_k(const float* __restrict__ wuq, const float* __restrict__ wuk,
                         __half* __restrict__ oq, __half* __restrict__ ok)
{
    int gidx = blockIdx.x * blockDim.x + threadIdx.x;
    int n = DKV * NH * DH;
    if (gidx >= 2 * n) return;
    int side = gidx >= n;
    int idx = side ? gidx - n : gidx;
    const float* in = side ? wuk : wuq;
    __half* out = side ? ok : oq;
    int i = idx / (NH * DH);
    int c = idx % (NH * DH);
    int h = c / DH, d = c % DH;
    float v = (d < SPLITD) ? in[(size_t)i * (NH * SPLITD) + h * SPLITD + d] : 0.0f;
    out[idx] = __float2half_rn(v);
}

// coalesced bias2
__global__ __launch_bounds__(256)
void bias2c_k(const float* __restrict__ outw, const float* __restrict__ outb,
              const float* __restrict__ buv, float* __restrict__ o)
{
    int n = blockIdx.x * 256 + threadIdx.x;
    float s = 0.0f;
    for (int m = 0; m < DM; m++) s += buv[m] * outw[(size_t)m * DM + n];
    o[n] = outb[n] + s;
}

__global__ void bqrow_k(const float* __restrict__ buq, const float* __restrict__ wuk,
                        float* __restrict__ o)
{
    int idx = blockIdx.x * blockDim.x + threadIdx.x;
    if (idx >= NH * DKV) return;
    int h = idx / DKV, n = idx % DKV;
    float s = 0.0f;
    for (int d = 0; d < SPLITD; d++)
        s += buq[h * SPLITD + d] * wuk[(size_t)n * (NH * SPLITD) + h * SPLITD + d];
    o[idx] = s;
}

__global__ void wh_k(const float* __restrict__ wuq, const float* __restrict__ buk,
                     const float* __restrict__ buq, float* __restrict__ o, float* __restrict__ sc)
{
    int idx = blockIdx.x * blockDim.x + threadIdx.x;
    if (idx >= NH * DKV) return;
    int h = idx / DKV, k = idx % DKV;
    float s = 0.0f;
    for (int d = 0; d < SPLITD; d++)
        s += wuq[(size_t)k * (NH * SPLITD) + h * SPLITD + d] * buk[h * SPLITD + d];
    o[idx] = s;
    if (k == 0) {
        float c = 0.0f;
        for (int d = 0; d < SPLITD; d++) c += buq[h * SPLITD + d] * buk[h * SPLITD + d];
        sc[h] = c;
    }
}

// merged bias concat: bdd = [bdkv|bdq], bkq = [bkr|bqr]
__global__ void bias_cat4(const float* bdkv, const float* bdq,
                          const float* bkr, const float* bqr,
                          float* bdd, float* bkq)
{
    int i = blockIdx.x * blockDim.x + threadIdx.x;
    if (i < NDD)
        bdd[i] = (i < DKV) ? bdkv[i] : bdq[i - DKV];
    if (i < 2 * DKV)
        bkq[i] = (i < DKV) ? bkr[i] : bqr[i - DKV];
}

// split-K reduce: ckvcq_half = p0+p1+bdd ; ckv float output for cols<128
__global__ void spk_reduce(const float* __restrict__ p0, const float* __restrict__ p1,
                           const float* __restrict__ bdd,
                           __half* __restrict__ ckvcq, float* __restrict__ ckvf)
{
    int i = blockIdx.x * blockDim.x + threadIdx.x;
    if (i >= MROWS * NDD) return;
    int m = i / NDD, c = i % NDD;
    float s = p0[i] + p1[i] + bdd[c];
    ckvcq[i] = __float2half_rn(s);
    if (c < DKV) ckvf[(size_t)m * DKV + c] = s;
}

// s_q column + zero pad cols 145..159
__global__ void sq_k(const __half* __restrict__ cq, int ldcq, const float* __restrict__ wh,
                     const float* __restrict__ scst, __half* __restrict__ qp)
{
    int idx = blockIdx.x * blockDim.x + threadIdx.x;
    if (idx >= MROWS * NH) return;
    int m = idx / NH, h = idx % NH;
    float s = scst[h];
    for (int k = 0; k < DKV; k++)
        s += __half2float(cq[(size_t)m * ldcq + k]) * wh[h * DKV + k];
    __half* p = qp + (size_t)m * LDQP + h * KP;
    p[144] = __float2half_rn(s);
    __half z = __float2half_rn(0.0f);
    for (int c = 145; c < KP; c++) p[c] = z;
}

__global__ void kpfill_k(const __half* __restrict__ ckv, int ldckv, __half* __restrict__ kp)
{
    int idx = blockIdx.x * blockDim.x + threadIdx.x;
    int total = MROWS * NH * 18;
    if (idx >= total) return;
    int c = idx % 18;
    int mh = idx / 18;
    int m = mh / NH, h = mh % NH;
    __half* p = kp + (size_t)m * LDQP + h * KP;
    if (c < 16) {
        uint4 v = *reinterpret_cast<const uint4*>(ckv + (size_t)m * ldckv + c * 8);
        *reinterpret_cast<uint4*>(p + c * 8) = v;
    } else if (c == 16) {
        __half z = __float2half_rn(0.0f);
        __half vals[8] = { __float2half_rn(1.0f), z, z, z, z, z, z, z };
        *reinterpret_cast<uint4*>(p + 144) = *reinterpret_cast<uint4*>(vals);
    } else {
        __half z = __float2half_rn(0.0f);
        __half vals[8] = { z, z, z, z, z, z, z, z };
        *reinterpret_cast<uint4*>(p + 152) = *reinterpret_cast<uint4*>(vals);
    }
}

// merged RoPE: side 0 = k (krp -> kp, + float out), side 1 = q (qrp -> qp)
__global__ void rope2_k(const __half* __restrict__ krp, const __half* __restrict__ qrp,
                        __half* __restrict__ kp, __half* __restrict__ qp,
                        float* __restrict__ rout)
{
    int gidx = blockIdx.x * blockDim.x + threadIdx.x;
    if (gidx >= 2 * MROWS * DKV) return;
    int side = gidx >= MROWS * DKV;
    int idx  = side ? gidx - MROWS * DKV : gidx;
    const __half* pre = side ? qrp : krp;
    __half* dst = side ? qp : kp;
    int m = idx >> 7;
    int c = idx & 127;
    int h = c >> 4;
    int d = c & 15;
    int j = d & 7;
    int s = m & (SEQ - 1);
    float t = (float)s * (1.0f / 40.0f);
    float invf = __expf(-(float)j * 0.86346941f);  // ln(1000)/8
    float ang = t * invf;
    float sn, cs;
    sincosf(ang, &sn, &cs);
    float x = __half2float(pre[idx]);
    float p = __half2float(pre[(m << 7) + (h << 4) + ((d < 8) ? d + 8 : d - 8)]);
    float val = x * cs + ((d < 8) ? -p : p) * sn;
    dst[(size_t)m * LDQP + h * KP + 128 + d] = __float2half_rn(val);
    if (!side && rout) rout[idx] = val;
}

// ============================================================================
// host launcher
// ============================================================================
extern "C" void kernel_launch(void* const* d_in, const int* in_sizes, int n_in,
                              void* d_out, int out_size)
{
    const float* h    = (const float*)d_in[0];
    const float* Wdkv = (const float*)d_in[1];
    const float* bdkv = (const float*)d_in[2];
    const float* Wdq  = (const float*)d_in[3];
    const float* bdq  = (const float*)d_in[4];
    const float* Wuk  = (const float*)d_in[5];
    const float* buk  = (const float*)d_in[6];
    const float* Wuv  = (const float*)d_in[7];
    const float* buv  = (const float*)d_in[8];
    const float* Wuq  = (const float*)d_in[9];
    const float* buq  = (const float*)d_in[10];
    const float* Wqr  = (const float*)d_in[11];
    const float* bqr  = (const float*)d_in[12];
    const float* Wkr  = (const float*)d_in[13];
    const float* bkr  = (const float*)d_in[14];
    const float* outw = (const float*)d_in[15];
    const float* outb = (const float*)d_in[16];
    float* out = (float*)d_out;

    __half *hh, *ckvcq, *krqrp, *qp, *kp, *u;
    __half *wdd, *wkq, *wt_out, *wuv_h, *wuq_p, *wuk_p, *mt, *w2t;
    float *ckvf, *part, *bias2, *bqrow, *wh, *scst, *bdd, *bkq;
    cudaGetSymbolAddress((void**)&hh,    g_hh);
    cudaGetSymbolAddress((void**)&ckvcq, g_ckvcq);
    cudaGetSymbolAddress((void**)&krqrp, g_krqrp);
    cudaGetSymbolAddress((void**)&qp,    g_qp);
    cudaGetSymbolAddress((void**)&kp,    g_kp);
    cudaGetSymbolAddress((void**)&u,     g_u);
    cudaGetSymbolAddress((void**)&ckvf,  g_ckvf);
    cudaGetSymbolAddress((void**)&part,  g_part);
    cudaGetSymbolAddress((void**)&wdd,   g_wdd);
    cudaGetSymbolAddress((void**)&wkq,   g_wkq);
    cudaGetSymbolAddress((void**)&wt_out, g_wt_out);
    cudaGetSymbolAddress((void**)&wuv_h,  g_wuv_h);
    cudaGetSymbolAddress((void**)&wuq_p,  g_wuq_p);
    cudaGetSymbolAddress((void**)&wuk_p,  g_wuk_p);
    cudaGetSymbolAddress((void**)&mt,     g_mt);
    cudaGetSymbolAddress((void**)&w2t,    g_w2t);
    cudaGetSymbolAddress((void**)&bias2,  g_bias2);
    cudaGetSymbolAddress((void**)&bqrow,  g_bqrow);
    cudaGetSymbolAddress((void**)&wh,     g_wh);
    cudaGetSymbolAddress((void**)&scst,   g_sconst);
    cudaGetSymbolAddress((void**)&bdd,    g_bdd);
    cudaGetSymbolAddress((void**)&bkq,    g_bkq);

    cudaFuncSetAttribute(flash_k, cudaFuncAttributeMaxDynamicSharedMemorySize, FA_SMEM);

    dim3 b256(256);
    f2h_k<<<((size_t)MROWS * DM / 4 + 255) / 256, 256>>>(h, hh, MROWS * DM / 4);
    f2h_k<<<(DKV * DM / 4 + 255) / 256, 256>>>(Wuv, wuv_h, DKV * DM / 4);
    transpose_f2h<<<dim3(DKV/32, DM/32), b256>>>(Wdkv, wdd,                 DKV, DM);
    transpose_f2h<<<dim3(DKV/32, DM/32), b256>>>(Wdq,  wdd + (size_t)DKV*DM, DKV, DM);
    transpose_f2h<<<dim3(DKV/32, DKV/32), b256>>>(Wkr, wkq,                 DKV, DKV);
    transpose_f2h<<<dim3(DKV/32, DKV/32), b256>>>(Wqr, wkq + DKV*DKV,       DKV, DKV);
    transpose_f2h<<<dim3(DM/32, DM/32), b256>>>(outw, wt_out, DM, DM);
    pad_w2_k<<<(2 * DKV * NH * DH + 255) / 256, 256>>>(Wuq, Wuk, wuq_p, wuk_p);
    bias2c_k<<<DM / 256, 256>>>(outw, outb, buv, bias2);
    bqrow_k<<<(NH * DKV + 255) / 256, 256>>>(buq, Wuk, bqrow);
    wh_k<<<(NH * DKV + 255) / 256, 256>>>(Wuq, buk, buq, wh, scst);
    bias_cat4<<<(NDD + 255) / 256, 256>>>(bdkv, bdq, bkr, bqr, bdd, bkq);

    const size_t out_ckv_off  = (size_t)MROWS * DM;
    const size_t out_krot_off = out_ckv_off + (size_t)MROWS * DKV;
    bool full_out = (size_t)out_size >= out_krot_off + (size_t)MROWS * DKV;
    float* ckv_dst = full_out ? (out + out_ckv_off) : ckvf;

    dim3 blk(256);
    auto grd = [](int M, int N, int Z) { return dim3((unsigned)(N / 128), (unsigned)(M / 128), (unsigned)Z); };

    // precompute Mt_h = Wuk_h Wuq_h^T  [8][128][128]
    hgemm<<<grd(DKV, DKV, NH), blk>>>(wuk_p, wuq_p, nullptr, mt, nullptr,
        DKV, DKV, DH, NH*DH, NH*DH, DKV, DKV, 0, 1.0f,
        0, DH, 0, DH, 0, DKV*DKV, 0, NH);
    // precompute w2t[n, h*128+j] = sum_d Wout^T[n, h*640+d] * Wuv[j, h*640+d]
    hgemm<<<grd(DM, DKV, NH), blk>>>(wt_out, wuv_h, nullptr, w2t, nullptr,
        DM, DKV, DH, DM, DM, NH*DKV, NH*DKV, 0, 1.0f,
        0, DH, 0, DH, 0, DKV, 0, NH);

    // 1) merged down projection, split-K (z = K-split of 2560): partials in float
    hgemm<<<grd(MROWS, NDD, 2), blk>>>(hh, wdd, part, nullptr, nullptr,
        MROWS, NDD, DM/2, DM, DM, NDD, NDD, NDD, 1.0f,
        0, DM/2, 0, DM/2, 0, (long long)MROWS * NDD, 0, 2);
    spk_reduce<<<(MROWS * NDD + 255) / 256, 256>>>(part, part + (size_t)MROWS * NDD,
        bdd, ckvcq, ckv_dst);

    // 2) merged rotary pre-projections: z=0: krp = ckv@Wkr^T; z=1: qrp = cq@Wqr^T
    hgemm<<<grd(MROWS, DKV, 2), blk>>>(ckvcq, wkq, nullptr, krqrp, bkq,
        MROWS, DKV, DKV, NDD, DKV, DKV, DKV, 0, 1.0f,
        0, DKV, 0, DKV*DKV, 0, (long long)MROWS*DKV, DKV, 2);

    // 3) q-tilde = cq @ Mt_h^T + bqrow_h  -> qp cols [h*KP .. h*KP+127]
    hgemm<<<grd(MROWS, DKV, NH), blk>>>(ckvcq + DKV, mt, nullptr, qp, bqrow,
        MROWS, DKV, DKV, NDD, DKV, LDQP, LDQP, 0, 1.0f,
        0, 0, 0, DKV*DKV, 0, KP, DKV, NH);

    // 4) assemble qp / kp
    rope2_k<<<(2 * MROWS * DKV + 255) / 256, 256>>>(krqrp, krqrp + (size_t)MROWS * DKV,
        kp, qp, full_out ? (out + out_krot_off) : nullptr);
    sq_k<<<(MROWS * NH + 255) / 256, 256>>>(ckvcq + DKV, NDD, wh, scst, qp);
    kpfill_k<<<(MROWS * NH * 18 + 255) / 256, 256>>>(ckvcq, NDD, kp);

    // 5) fused flash attention -> u [4096, 1024]
    float inv_sqrt = 1.0f / sqrtf((float)DH);
    flash_k<<<dim3(SEQ/128, BATCH*NH), blk, FA_SMEM>>>(qp, kp, ckvcq, NDD, u, inv_sqrt);

    // 6) out = u @ w2t^T + bias2   [4096,5120]
    hgemm<<<grd(MROWS, DM, 1), blk>>>(u, w2t, out, nullptr, bias2,
        MROWS, DM, NH*DKV, NH*DKV, NH*DKV, DM, DM, DM, 1.0f, 0,0,0,0,0,0,0, 1);
}

// round 12
// speedup vs baseline: 1.3832x; 1.3453x over previous
#include <cuda_runtime.h>
#include <cuda_fp16.h>
#include <math.h>
#include <stdint.h>

// ---------------- problem constants ----------------
#define BATCH 2
#define SEQ   2048
#define DM    5120
#define NH    8
#define DH    640
#define DR    16
#define SPLITD 624
#define DKV   128
#define MROWS (BATCH*SEQ)        // 4096
#define KP    160                // per-head score K-dim: [128 ckv |16 rope |1 bias |15 pad]
#define LDQP  (NH*KP)            // 1280
#define NDD   256                // merged down-proj N: [ckv|cq]

// ---------------- scratch (device globals; no allocs allowed) ----------------
__device__ __align__(16) __half g_hh   [(size_t)MROWS*DM];
__device__ __align__(16) __half g_ckvcq[(size_t)MROWS*NDD];   // [ckv(0:128) | cq(128:256)]
__device__ __align__(16) __half g_krqrp[2*MROWS*DKV];          // [krp | qrp]
__device__ __align__(16) __half g_qp   [(size_t)MROWS*LDQP];
__device__ __align__(16) __half g_kp   [(size_t)MROWS*LDQP];
__device__ __align__(16) __half g_u    [(size_t)MROWS*NH*DKV]; // [4096,1024]
__device__ __align__(16) float  g_ckvf [MROWS*DKV];
// weights
__device__ __align__(16) __half g_wdd  [(size_t)NDD*DM];       // [wt_dkv; wt_dq] [256,5120]
__device__ __align__(16) __half g_wkq  [2*DKV*DKV];            // [wt_kr; wt_qr]
__device__ __align__(16) __half g_wt_out[(size_t)DM*DM];       // Wout^T [DM, NH*DH]
__device__ __align__(16) __half g_wuv_h [DKV*DM];
__device__ __align__(16) __half g_wuq_p [DKV*NH*DH];           // zero-padded 624->640
__device__ __align__(16) __half g_wuk_p [DKV*NH*DH];
__device__ __align__(16) __half g_mt    [NH*DKV*DKV];          // Mt_h = Wuk_h Wuq_h^T
__device__ __align__(16) __half g_w2t   [(size_t)DM*NH*DKV];   // [5120,1024]
__device__ __align__(16) float  g_bias2 [DM];
__device__ __align__(16) float  g_bqrow [NH*DKV];
__device__ __align__(16) float  g_wh    [NH*DKV];
__device__ __align__(16) float  g_sconst[NH];
__device__ __align__(16) float  g_bdd   [NDD];
__device__ __align__(16) float  g_bkq   [2*DKV];

// ---------------- PTX helpers ----------------
__device__ __forceinline__ uint32_t smem_u32(const void* p) {
    uint32_t a;
    asm("{ .reg .u64 t; cvta.to.shared.u64 t, %1; cvt.u32.u64 %0, t; }" : "=r"(a) : "l"(p));
    return a;
}
__device__ __forceinline__ void cp16(uint32_t dst, const void* src) {
    asm volatile("cp.async.cg.shared.global [%0], [%1], 16;" :: "r"(dst), "l"(src) : "memory");
}
#define CP_COMMIT() asm volatile("cp.async.commit_group;" ::: "memory")
#define CP_WAIT(n)  asm volatile("cp.async.wait_group %0;" :: "n"(n) : "memory")

__device__ __forceinline__ void ldm_x4(uint32_t* r, uint32_t addr) {
    asm volatile("ldmatrix.sync.aligned.m8n8.x4.shared.b16 {%0,%1,%2,%3}, [%4];"
                 : "=r"(r[0]), "=r"(r[1]), "=r"(r[2]), "=r"(r[3]) : "r"(addr));
}
__device__ __forceinline__ void ldm_x4t(uint32_t* r, uint32_t addr) {
    asm volatile("ldmatrix.sync.aligned.m8n8.x4.trans.shared.b16 {%0,%1,%2,%3}, [%4];"
                 : "=r"(r[0]), "=r"(r[1]), "=r"(r[2]), "=r"(r[3]) : "r"(addr));
}
__device__ __forceinline__ void mma_f16(float* c, const uint32_t* a, uint32_t b0, uint32_t b1) {
    asm volatile("mma.sync.aligned.m16n8k16.row.col.f32.f16.f16.f32 "
                 "{%0,%1,%2,%3}, {%4,%5,%6,%7}, {%8,%9}, {%0,%1,%2,%3};"
                 : "+f"(c[0]), "+f"(c[1]), "+f"(c[2]), "+f"(c[3])
                 : "r"(a[0]), "r"(a[1]), "r"(a[2]), "r"(a[3]), "r"(b0), "r"(b1));
}
__device__ __forceinline__ uint32_t packh2(float x, float y) {
    __half2 h = __floats2half2_rn(x, y);
    return *reinterpret_cast<uint32_t*>(&h);
}

// ============================================================================
// fp16 mma.sync GEMM: C = alpha*A*B^T + bias. 128x128 tile, BK=32, 2-stage.
// Cf written only for cols < cfN (ld ldcf); Ch full (ld ldc).
// ============================================================================
#define SPADH 40

__global__ __launch_bounds__(256)
void hgemm(const __half* __restrict__ A, const __half* __restrict__ B,
           float* __restrict__ Cf, __half* __restrict__ Ch,
           const float* __restrict__ bias,
           int M, int N, int K, int lda, int ldb, int ldc, int ldcf, int cfN,
           float alpha,
           long long sAhi, long long sAlo, long long sBhi, long long sBlo,
           long long sChi, long long sClo, long long sBiasLo, int zdiv)
{
    __shared__ __half As[2][128][SPADH];
    __shared__ __half Bs[2][128][SPADH];

    int tid  = threadIdx.x;
    int warp = tid >> 5;
    int lane = tid & 31;
    int wr = warp >> 1;
    int wc = warp & 1;
    int qid = lane >> 2;
    int tig = lane & 3;

    int z  = blockIdx.z;
    int zh = z / zdiv, zl = z % zdiv;
    A += zh * sAhi + zl * sAlo;
    B += zh * sBhi + zl * sBlo;
    long long cofs = zh * sChi + zl * sClo;
    if (Cf) Cf += cofs;
    if (Ch) Ch += cofs;
    if (bias) bias += zl * sBiasLo;

    int row0 = blockIdx.y * 128, col0 = blockIdx.x * 128;
    const __half* Ab = A + (size_t)row0 * lda;
    const __half* Bb = B + (size_t)col0 * ldb;

    int r0 = tid >> 2, cc = (tid & 3) * 8;
    int r1 = r0 + 64;
    uint32_t dA0[2], dA1[2], dB0[2], dB1[2];
#pragma unroll
    for (int s = 0; s < 2; s++) {
        dA0[s] = smem_u32(&As[s][r0][cc]);
        dA1[s] = smem_u32(&As[s][r1][cc]);
        dB0[s] = smem_u32(&Bs[s][r0][cc]);
        dB1[s] = smem_u32(&Bs[s][r1][cc]);
    }
    uint32_t aAddr[2][2], bAddr[2][4];
#pragma unroll
    for (int s = 0; s < 2; s++) {
#pragma unroll
        for (int mi = 0; mi < 2; mi++)
            aAddr[s][mi] = smem_u32(&As[s][wr * 32 + mi * 16 + (lane & 15)][(lane >> 4) * 8]);
#pragma unroll
        for (int np = 0; np < 4; np++)
            bAddr[s][np] = smem_u32(&Bs[s][wc * 64 + np * 16 + (lane & 7) + ((lane >> 4) & 1) * 8]
                                        [((lane >> 3) & 1) * 8]);
    }

    float acc[2][8][4];
#pragma unroll
    for (int mi = 0; mi < 2; mi++)
#pragma unroll
        for (int ni = 0; ni < 8; ni++)
#pragma unroll
            for (int i = 0; i < 4; i++) acc[mi][ni][i] = 0.0f;

    int T = K >> 5;

    cp16(dA0[0], Ab + (size_t)r0 * lda + cc);
    cp16(dA1[0], Ab + (size_t)r1 * lda + cc);
    cp16(dB0[0], Bb + (size_t)r0 * ldb + cc);
    cp16(dB1[0], Bb + (size_t)r1 * ldb + cc);
    CP_COMMIT();

    for (int t = 0; t < T; t++) {
        if (t + 1 < T) {
            int s = (t + 1) & 1;
            int k0 = (t + 1) * 32;
            cp16(dA0[s], Ab + (size_t)r0 * lda + k0 + cc);
            cp16(dA1[s], Ab + (size_t)r1 * lda + k0 + cc);
            cp16(dB0[s], Bb + (size_t)r0 * ldb + k0 + cc);
            cp16(dB1[s], Bb + (size_t)r1 * ldb + k0 + cc);
            CP_COMMIT();
            CP_WAIT(1);
        } else {
            CP_WAIT(0);
        }
        __syncthreads();

        int s = t & 1;
#pragma unroll
        for (int ks = 0; ks < 2; ks++) {
            uint32_t koff = ks * 32;
            uint32_t a[2][4], b[16];
#pragma unroll
            for (int mi = 0; mi < 2; mi++) ldm_x4(a[mi], aAddr[s][mi] + koff);
#pragma unroll
            for (int np = 0; np < 4; np++) ldm_x4(b + np * 4, bAddr[s][np] + koff);
#pragma unroll
            for (int ni = 0; ni < 8; ni++) {
                uint32_t b0 = b[(ni >> 1) * 4 + (ni & 1) * 2];
                uint32_t b1 = b[(ni >> 1) * 4 + (ni & 1) * 2 + 1];
                mma_f16(acc[0][ni], a[0], b0, b1);
                mma_f16(acc[1][ni], a[1], b0, b1);
            }
        }
        __syncthreads();
    }

#pragma unroll
    for (int mi = 0; mi < 2; mi++) {
        int rg = row0 + wr * 32 + mi * 16 + qid;
#pragma unroll
        for (int ni = 0; ni < 8; ni++) {
            int cg = col0 + wc * 64 + ni * 8 + tig * 2;
            float bx = 0.0f, by = 0.0f;
            if (bias) { bx = bias[cg]; by = bias[cg + 1]; }
            float o0 = alpha * acc[mi][ni][0] + bx;
            float o1 = alpha * acc[mi][ni][1] + by;
            float o2 = alpha * acc[mi][ni][2] + bx;
            float o3 = alpha * acc[mi][ni][3] + by;
            if (Cf && cg < cfN) {
                *reinterpret_cast<float2*>(Cf + (size_t)rg * ldcf + cg)       = make_float2(o0, o1);
                *reinterpret_cast<float2*>(Cf + (size_t)(rg + 8) * ldcf + cg) = make_float2(o2, o3);
            }
            if (Ch) {
                *reinterpret_cast<__half2*>(Ch + (size_t)rg * ldc + cg)       = __floats2half2_rn(o0, o1);
                *reinterpret_cast<__half2*>(Ch + (size_t)(rg + 8) * ldc + cg) = __floats2half2_rn(o2, o3);
            }
        }
    }
}

// ============================================================================
// flash attention: per CTA = (q-tile 128 rows, one (b,h)). online softmax.
// ============================================================================
#define FAQ_LD 168
#define FAV_LD 136
#define FA_SMEM ((3*128*FAQ_LD + 2*128*FAV_LD) * 2)   // 198656 B

__global__ __launch_bounds__(256, 1)
void flash_k(const __half* __restrict__ qp, const __half* __restrict__ kp,
             const __half* __restrict__ ckv, int ldckv,
             __half* __restrict__ u, float scale)
{
    extern __shared__ __half sm[];
    __half* Qs = sm;
    __half* Ks = sm + 128 * FAQ_LD;
    __half* Vs = sm + 3 * 128 * FAQ_LD;

    int tid = threadIdx.x;
    int warp = tid >> 5, lane = tid & 31;
    int qid = lane >> 2, tig = lane & 3;

    int qt = blockIdx.x;
    int z  = blockIdx.y;
    int b = z >> 3, h = z & 7;

    const __half* Qg = qp + ((size_t)(b * SEQ + qt * 128)) * LDQP + h * KP;
    const __half* Kg = kp + ((size_t)b * SEQ) * LDQP + h * KP;
    const __half* Vg = ckv + ((size_t)b * SEQ) * ldckv;

#pragma unroll
    for (int i = 0; i < 10; i++) {
        int idx = tid + i * 256;
        int r = idx / 20, c = idx % 20;
        cp16(smem_u32(Qs + r * FAQ_LD + c * 8), Qg + (size_t)r * LDQP + c * 8);
    }
#pragma unroll
    for (int i = 0; i < 10; i++) {
        int idx = tid + i * 256;
        int r = idx / 20, c = idx % 20;
        cp16(smem_u32(Ks + r * FAQ_LD + c * 8), Kg + (size_t)r * LDQP + c * 8);
    }
#pragma unroll
    for (int i = 0; i < 8; i++) {
        int idx = tid + i * 256;
        int r = idx / 16, c = idx % 16;
        cp16(smem_u32(Vs + r * FAV_LD + c * 8), Vg + (size_t)r * ldckv + c * 8);
    }
    CP_COMMIT();

    uint32_t qAddr = smem_u32(Qs + (warp * 16 + (lane & 15)) * FAQ_LD + (lane >> 4) * 8);
    uint32_t kAddr[2][8], vAddr[2][8];
#pragma unroll
    for (int s = 0; s < 2; s++) {
#pragma unroll
        for (int nb = 0; nb < 8; nb++) {
            kAddr[s][nb] = smem_u32(Ks + s * 128 * FAQ_LD
                + (nb * 16 + (lane & 7) + ((lane >> 4) & 1) * 8) * FAQ_LD
                + ((lane >> 3) & 1) * 8);
            vAddr[s][nb] = smem_u32(Vs + s * 128 * FAV_LD
                + (lane & 15) * FAV_LD
                + nb * 16 + ((lane >> 4) << 3));
        }
    }

    float oacc[16][4];
#pragma unroll
    for (int j = 0; j < 16; j++)
#pragma unroll
        for (int i = 0; i < 4; i++) oacc[j][i] = 0.0f;
    float m0 = -1e30f, m1 = -1e30f, l0 = 0.0f, l1 = 0.0f;

    for (int kt = 0; kt < 16; kt++) {
        CP_WAIT(0);
        __syncthreads();
        if (kt + 1 < 16) {
            int s = (kt + 1) & 1;
            const __half* Kt = Kg + (size_t)(kt + 1) * 128 * LDQP;
            const __half* Vt = Vg + (size_t)(kt + 1) * 128 * ldckv;
#pragma unroll
            for (int i = 0; i < 10; i++) {
                int idx = tid + i * 256;
                int r = idx / 20, c = idx % 20;
                cp16(smem_u32(Ks + s * 128 * FAQ_LD + r * FAQ_LD + c * 8),
                     Kt + (size_t)r * LDQP + c * 8);
            }
#pragma unroll
            for (int i = 0; i < 8; i++) {
                int idx = tid + i * 256;
                int r = idx / 16, c = idx % 16;
                cp16(smem_u32(Vs + s * 128 * FAV_LD + r * FAV_LD + c * 8),
                     Vt + (size_t)r * ldckv + c * 8);
            }
            CP_COMMIT();
        }

        int s = kt & 1;
        float sacc[16][4];
#pragma unroll
        for (int j = 0; j < 16; j++)
#pragma unroll
            for (int i = 0; i < 4; i++) sacc[j][i] = 0.0f;
#pragma unroll
        for (int ks = 0; ks < 10; ks++) {
            uint32_t a[4];
            ldm_x4(a, qAddr + ks * 32);
#pragma unroll
            for (int nb = 0; nb < 8; nb++) {
                uint32_t bb[4];
                ldm_x4(bb, kAddr[s][nb] + ks * 32);
                mma_f16(sacc[2 * nb],     a, bb[0], bb[1]);
                mma_f16(sacc[2 * nb + 1], a, bb[2], bb[3]);
            }
        }
        float mx0 = -1e30f, mx1 = -1e30f;
#pragma unroll
        for (int j = 0; j < 16; j++) {
            sacc[j][0] *= scale; sacc[j][1] *= scale;
            sacc[j][2] *= scale; sacc[j][3] *= scale;
            mx0 = fmaxf(mx0, fmaxf(sacc[j][0], sacc[j][1]));
            mx1 = fmaxf(mx1, fmaxf(sacc[j][2], sacc[j][3]));
        }
        mx0 = fmaxf(mx0, __shfl_xor_sync(0xFFFFFFFF, mx0, 1));
        mx0 = fmaxf(mx0, __shfl_xor_sync(0xFFFFFFFF, mx0, 2));
        mx1 = fmaxf(mx1, __shfl_xor_sync(0xFFFFFFFF, mx1, 1));
        mx1 = fmaxf(mx1, __shfl_xor_sync(0xFFFFFFFF, mx1, 2));
        float mn0 = fmaxf(m0, mx0), mn1 = fmaxf(m1, mx1);
        float f0 = __expf(m0 - mn0), f1 = __expf(m1 - mn1);
        m0 = mn0; m1 = mn1;
        float ts0 = 0.0f, ts1 = 0.0f;
#pragma unroll
        for (int j = 0; j < 16; j++) {
            sacc[j][0] = __expf(sacc[j][0] - m0);
            sacc[j][1] = __expf(sacc[j][1] - m0);
            sacc[j][2] = __expf(sacc[j][2] - m1);
            sacc[j][3] = __expf(sacc[j][3] - m1);
            ts0 += sacc[j][0] + sacc[j][1];
            ts1 += sacc[j][2] + sacc[j][3];
        }
        ts0 += __shfl_xor_sync(0xFFFFFFFF, ts0, 1);
        ts0 += __shfl_xor_sync(0xFFFFFFFF, ts0, 2);
        ts1 += __shfl_xor_sync(0xFFFFFFFF, ts1, 1);
        ts1 += __shfl_xor_sync(0xFFFFFFFF, ts1, 2);
        l0 = l0 * f0 + ts0;
        l1 = l1 * f1 + ts1;
#pragma unroll
        for (int j = 0; j < 16; j++) {
            oacc[j][0] *= f0; oacc[j][1] *= f0;
            oacc[j][2] *= f1; oacc[j][3] *= f1;
        }
#pragma unroll
        for (int kb = 0; kb < 8; kb++) {
            uint32_t a[4];
            a[0] = packh2(sacc[2 * kb][0],     sacc[2 * kb][1]);
            a[1] = packh2(sacc[2 * kb][2],     sacc[2 * kb][3]);
            a[2] = packh2(sacc[2 * kb + 1][0], sacc[2 * kb + 1][1]);
            a[3] = packh2(sacc[2 * kb + 1][2], sacc[2 * kb + 1][3]);
            uint32_t voff = (uint32_t)(kb * 16 * FAV_LD * 2);
#pragma unroll
            for (int nb = 0; nb < 8; nb++) {
                uint32_t bb[4];
                ldm_x4t(bb, vAddr[s][nb] + voff);
                mma_f16(oacc[2 * nb],     a, bb[0], bb[1]);
                mma_f16(oacc[2 * nb + 1], a, bb[2], bb[3]);
            }
        }
    }

    float il0 = 1.0f / l0, il1 = 1.0f / l1;
    int rowg = b * SEQ + qt * 128 + warp * 16;
#pragma unroll
    for (int j = 0; j < 16; j++) {
        int col = h * 128 + j * 8 + tig * 2;
        *reinterpret_cast<__half2*>(u + (size_t)(rowg + qid) * (NH * DKV) + col)
            = __floats2half2_rn(oacc[j][0] * il0, oacc[j][1] * il0);
        *reinterpret_cast<__half2*>(u + (size_t)(rowg + qid + 8) * (NH * DKV) + col)
            = __floats2half2_rn(oacc[j][2] * il1, oacc[j][3] * il1);
    }
}

// ============================================================================
// small kernels
// ============================================================================
__global__ __launch_bounds__(256)
void transpose_f2h(const float* __restrict__ in, __half* __restrict__ out, int ldi, int ldo)
{
    __shared__ float t[32][33];
    int bx = blockIdx.x * 32, by = blockIdx.y * 32;
    int tx = threadIdx.x & 31, ty = threadIdx.x >> 5;
#pragma unroll
    for (int i = 0; i < 4; i++)
        t[ty + 8 * i][tx] = in[(size_t)(by + ty + 8 * i) * ldi + bx + tx];
    __syncthreads();
#pragma unroll
    for (int i = 0; i < 4; i++)
        out[(size_t)(bx + ty + 8 * i) * ldo + by + tx] = __float2half_rn(t[tx][ty + 8 * i]);
}

__global__ void f2h_k(const float* __restrict__ in, __half* __restrict__ out, int n4)
{
    int i = blockIdx.x * blockDim.x + threadIdx.x;
    if (i >= n4) return;
    float4 v = *reinterpret_cast<const float4*>(in + (size_t)i * 4);
    __half2 a = __floats2half2_rn(v.x, v.y);
    __half2 b = __floats2half2_rn(v.z, v.w);
    *reinterpret_cast<uint2*>(out + (size_t)i * 4) = make_uint2(
        *reinterpret_cast<uint32_t*>(&a), *reinterpret_cast<uint32_t*>(&b));
}

__global__ void pad_w_k(const float* __restrict__ in, __half* __restrict__ out)
{
    int idx = blockIdx.x * blockDim.x + threadIdx.x;
    if (idx >= DKV * NH * DH) return;
    int i = idx / (NH * DH);
    int c = idx % (NH * DH);
    int h = c / DH, d = c % DH;
    float v = (d < SPLITD) ? in[(size_t)i * (NH * SPLITD) + h * SPLITD + d] : 0.0f;
    out[idx] = __float2half_rn(v);
}

// bias2 = outb + buv @ Wout : 2D-parallel, coalesced, atomic accumulate
__global__ void bias2init_k(const float* __restrict__ outb, float* __restrict__ o)
{
    int n = blockIdx.x * 256 + threadIdx.x;
    if (n < DM) o[n] = outb[n];
}
__global__ __launch_bounds__(256)
void bias2p_k(const float* __restrict__ outw, const float* __restrict__ buv,
              float* __restrict__ o)
{
    int n = blockIdx.x * 256 + threadIdx.x;
    int m0 = blockIdx.y * 256;
    float s = 0.0f;
#pragma unroll 4
    for (int i = 0; i < 256; i++)
        s += buv[m0 + i] * outw[(size_t)(m0 + i) * DM + n];
    atomicAdd(&o[n], s);
}

__global__ void bqrow_k(const float* __restrict__ buq, const float* __restrict__ wuk,
                        float* __restrict__ o)
{
    int idx = blockIdx.x * blockDim.x + threadIdx.x;
    if (idx >= NH * DKV) return;
    int h = idx / DKV, n = idx % DKV;
    float s = 0.0f;
    for (int d = 0; d < SPLITD; d++)
        s += buq[h * SPLITD + d] * wuk[(size_t)n * (NH * SPLITD) + h * SPLITD + d];
    o[idx] = s;
}

__global__ void wh_k(const float* __restrict__ wuq, const float* __restrict__ buk,
                     const float* __restrict__ buq, float* __restrict__ o, float* __restrict__ sc)
{
    int idx = blockIdx.x * blockDim.x + threadIdx.x;
    if (idx >= NH * DKV) return;
    int h = idx / DKV, k = idx % DKV;
    float s = 0.0f;
    for (int d = 0; d < SPLITD; d++)
        s += wuq[(size_t)k * (NH * SPLITD) + h * SPLITD + d] * buk[h * SPLITD + d];
    o[idx] = s;
    if (k == 0) {
        float c = 0.0f;
        for (int d = 0; d < SPLITD; d++) c += buq[h * SPLITD + d] * buk[h * SPLITD + d];
        sc[h] = c;
    }
}

__global__ void bias_cat2(const float* a, const float* b, float* o, int n1, int n2)
{
    int i = blockIdx.x * blockDim.x + threadIdx.x;
    if (i >= n1 + n2) return;
    o[i] = (i < n1) ? a[i] : b[i - n1];
}

__global__ void sq_k(const __half* __restrict__ cq, int ldcq, const float* __restrict__ wh,
                     const float* __restrict__ scst, __half* __restrict__ qp)
{
    int idx = blockIdx.x * blockDim.x + threadIdx.x;
    if (idx >= MROWS * NH) return;
    int m = idx / NH, h = idx % NH;
    float s = scst[h];
    for (int k = 0; k < DKV; k++)
        s += __half2float(cq[(size_t)m * ldcq + k]) * wh[h * DKV + k];
    qp[(size_t)m * LDQP + h * KP + 144] = __float2half_rn(s);
}

__global__ void qppad_k(__half* __restrict__ qp)
{
    int idx = blockIdx.x * blockDim.x + threadIdx.x;
    if (idx >= MROWS * NH) return;
    int m = idx / NH, h = idx % NH;
    __half* p = qp + (size_t)m * LDQP + h * KP;
    for (int c = 145; c < KP; c++) p[c] = __float2half_rn(0.0f);
}

__global__ void kpfill_k(const __half* __restrict__ ckv, int ldckv, __half* __restrict__ kp)
{
    int idx = blockIdx.x * blockDim.x + threadIdx.x;
    int total = MROWS * NH * 18;
    if (idx >= total) return;
    int c = idx % 18;
    int mh = idx / 18;
    int m = mh / NH, h = mh % NH;
    __half* p = kp + (size_t)m * LDQP + h * KP;
    if (c < 16) {
        uint4 v = *reinterpret_cast<const uint4*>(ckv + (size_t)m * ldckv + c * 8);
        *reinterpret_cast<uint4*>(p + c * 8) = v;
    } else if (c == 16) {
        __half z = __float2half_rn(0.0f);
        __half vals[8] = { __float2half_rn(1.0f), z, z, z, z, z, z, z };
        *reinterpret_cast<uint4*>(p + 144) = *reinterpret_cast<uint4*>(vals);
    } else {
        __half z = __float2half_rn(0.0f);
        __half vals[8] = { z, z, z, z, z, z, z, z };
        *reinterpret_cast<uint4*>(p + 152) = *reinterpret_cast<uint4*>(vals);
    }
}

__global__ void rope_k(const __half* __restrict__ pre, __half* __restrict__ dst,
                       float* __restrict__ rout)
{
    int idx = blockIdx.x * blockDim.x + threadIdx.x;
    if (idx >= MROWS * DKV) return;
    int m = idx >> 7;
    int c = idx & 127;
    int h = c >> 4;
    int d = c & 15;
    int j = d & 7;
    int s = m & (SEQ - 1);
    float t = (float)s * (1.0f / 40.0f);
    float invf = __expf(-(float)j * 0.86346941f);  // ln(1000)/8
    float ang = t * invf;
    float sn, cs;
    sincosf(ang, &sn, &cs);
    float x = __half2float(pre[idx]);
    float p = __half2float(pre[(m << 7) + (h << 4) + ((d < 8) ? d + 8 : d - 8)]);
    float val = x * cs + ((d < 8) ? -p : p) * sn;
    dst[(size_t)m * LDQP + h * KP + 128 + d] = __float2half_rn(val);
    if (rout) rout[idx] = val;
}

// ============================================================================
// host launcher
// ============================================================================
extern "C" void kernel_launch(void* const* d_in, const int* in_sizes, int n_in,
                              void* d_out, int out_size)
{
    const float* h    = (const float*)d_in[0];
    const float* Wdkv = (const float*)d_in[1];
    const float* bdkv = (const float*)d_in[2];
    const float* Wdq  = (const float*)d_in[3];
    const float* bdq  = (const float*)d_in[4];
    const float* Wuk  = (const float*)d_in[5];
    const float* buk  = (const float*)d_in[6];
    const float* Wuv  = (const float*)d_in[7];
    const float* buv  = (const float*)d_in[8];
    const float* Wuq  = (const float*)d_in[9];
    const float* buq  = (const float*)d_in[10];
    const float* Wqr  = (const float*)d_in[11];
    const float* bqr  = (const float*)d_in[12];
    const float* Wkr  = (const float*)d_in[13];
    const float* bkr  = (const float*)d_in[14];
    const float* outw = (const float*)d_in[15];
    const float* outb = (const float*)d_in[16];
    float* out = (float*)d_out;

    __half *hh, *ckvcq, *krqrp, *qp, *kp, *u;
    __half *wdd, *wkq, *wt_out, *wuv_h, *wuq_p, *wuk_p, *mt, *w2t;
    float *ckvf, *bias2, *bqrow, *wh, *scst, *bdd, *bkq;
    cudaGetSymbolAddress((void**)&hh,    g_hh);
    cudaGetSymbolAddress((void**)&ckvcq, g_ckvcq);
    cudaGetSymbolAddress((void**)&krqrp, g_krqrp);
    cudaGetSymbolAddress((void**)&qp,    g_qp);
    cudaGetSymbolAddress((void**)&kp,    g_kp);
    cudaGetSymbolAddress((void**)&u,     g_u);
    cudaGetSymbolAddress((void**)&ckvf,  g_ckvf);
    cudaGetSymbolAddress((void**)&wdd,   g_wdd);
    cudaGetSymbolAddress((void**)&wkq,   g_wkq);
    cudaGetSymbolAddress((void**)&wt_out, g_wt_out);
    cudaGetSymbolAddress((void**)&wuv_h,  g_wuv_h);
    cudaGetSymbolAddress((void**)&wuq_p,  g_wuq_p);
    cudaGetSymbolAddress((void**)&wuk_p,  g_wuk_p);
    cudaGetSymbolAddress((void**)&mt,     g_mt);
    cudaGetSymbolAddress((void**)&w2t,    g_w2t);
    cudaGetSymbolAddress((void**)&bias2,  g_bias2);
    cudaGetSymbolAddress((void**)&bqrow,  g_bqrow);
    cudaGetSymbolAddress((void**)&wh,     g_wh);
    cudaGetSymbolAddress((void**)&scst,   g_sconst);
    cudaGetSymbolAddress((void**)&bdd,    g_bdd);
    cudaGetSymbolAddress((void**)&bkq,    g_bkq);

    cudaFuncSetAttribute(flash_k, cudaFuncAttributeMaxDynamicSharedMemorySize, FA_SMEM);

    dim3 b256(256);
    f2h_k<<<((size_t)MROWS * DM / 4 + 255) / 256, 256>>>(h, hh, MROWS * DM / 4);
    f2h_k<<<(DKV * DM / 4 + 255) / 256, 256>>>(Wuv, wuv_h, DKV * DM / 4);
    transpose_f2h<<<dim3(DKV/32, DM/32), b256>>>(Wdkv, wdd,                 DKV, DM);
    transpose_f2h<<<dim3(DKV/32, DM/32), b256>>>(Wdq,  wdd + (size_t)DKV*DM, DKV, DM);
    transpose_f2h<<<dim3(DKV/32, DKV/32), b256>>>(Wkr, wkq,                 DKV, DKV);
    transpose_f2h<<<dim3(DKV/32, DKV/32), b256>>>(Wqr, wkq + DKV*DKV,       DKV, DKV);
    transpose_f2h<<<dim3(DM/32, DM/32), b256>>>(outw, wt_out, DM, DM);
    pad_w_k<<<(DKV * NH * DH + 255) / 256, 256>>>(Wuq, wuq_p);
    pad_w_k<<<(DKV * NH * DH + 255) / 256, 256>>>(Wuk, wuk_p);
    bias2init_k<<<DM / 256, 256>>>(outb, bias2);
    bias2p_k<<<dim3(DM / 256, DM / 256), 256>>>(outw, buv, bias2);
    bqrow_k<<<(NH * DKV + 255) / 256, 256>>>(buq, Wuk, bqrow);
    wh_k<<<(NH * DKV + 255) / 256, 256>>>(Wuq, buk, buq, wh, scst);
    bias_cat2<<<(NDD + 255) / 256, 256>>>(bdkv, bdq, bdd, DKV, DKV);
    bias_cat2<<<(2 * DKV + 255) / 256, 256>>>(bkr, bqr, bkq, DKV, DKV);

    const size_t out_ckv_off  = (size_t)MROWS * DM;
    const size_t out_krot_off = out_ckv_off + (size_t)MROWS * DKV;
    bool full_out = (size_t)out_size >= out_krot_off + (size_t)MROWS * DKV;
    float* ckv_dst = full_out ? (out + out_ckv_off) : ckvf;

    dim3 blk(256);
    auto grd = [](int M, int N, int Z) { return dim3((unsigned)(N / 128), (unsigned)(M / 128), (unsigned)Z); };

    // precompute Mt_h = Wuk_h Wuq_h^T  [8][128][128]
    hgemm<<<grd(DKV, DKV, NH), blk>>>(wuk_p, wuq_p, nullptr, mt, nullptr,
        DKV, DKV, DH, NH*DH, NH*DH, DKV, DKV, 0, 1.0f,
        0, DH, 0, DH, 0, DKV*DKV, 0, NH);
    // precompute w2t[n, h*128+j] = sum_d Wout^T[n, h*640+d] * Wuv[j, h*640+d]
    hgemm<<<grd(DM, DKV, NH), blk>>>(wt_out, wuv_h, nullptr, w2t, nullptr,
        DM, DKV, DH, DM, DM, NH*DKV, NH*DKV, 0, 1.0f,
        0, DH, 0, DH, 0, DKV, 0, NH);

    // 1) merged down projection: [ckv|cq] = h @ [Wdkv|Wdq] ; float ckv to output
    hgemm<<<grd(MROWS, NDD, 1), blk>>>(hh, wdd, ckv_dst, ckvcq, bdd,
        MROWS, NDD, DM, DM, DM, NDD, DKV, DKV, 1.0f, 0,0,0,0,0,0,0, 1);

    // 2) merged rotary pre-projections: z=0: krp = ckv@Wkr^T; z=1: qrp = cq@Wqr^T
    hgemm<<<grd(MROWS, DKV, 2), blk>>>(ckvcq, wkq, nullptr, krqrp, bkq,
        MROWS, DKV, DKV, NDD, DKV, DKV, DKV, 0, 1.0f,
        0, DKV, 0, DKV*DKV, 0, (long long)MROWS*DKV, DKV, 2);

    // 3) q-tilde = cq @ Mt_h^T + bqrow_h  -> qp cols [h*KP .. h*KP+127]
    hgemm<<<grd(MROWS, DKV, NH), blk>>>(ckvcq + DKV, mt, nullptr, qp, bqrow,
        MROWS, DKV, DKV, NDD, DKV, LDQP, LDQP, 0, 1.0f,
        0, 0, 0, DKV*DKV, 0, KP, DKV, NH);

    // 4) assemble qp / kp
    rope_k<<<(MROWS * DKV + 255) / 256, 256>>>(krqrp + (size_t)MROWS * DKV, qp, nullptr);
    rope_k<<<(MROWS * DKV + 255) / 256, 256>>>(krqrp, kp,
        full_out ? (out + out_krot_off) : nullptr);
    sq_k<<<(MROWS * NH + 255) / 256, 256>>>(ckvcq + DKV, NDD, wh, scst, qp);
    qppad_k<<<(MROWS * NH + 255) / 256, 256>>>(qp);
    kpfill_k<<<(MROWS * NH * 18 + 255) / 256, 256>>>(ckvcq, NDD, kp);

    // 5) fused flash attention -> u [4096, 1024]
    float inv_sqrt = 1.0f / sqrtf((float)DH);
    flash_k<<<dim3(SEQ/128, BATCH*NH), blk, FA_SMEM>>>(qp, kp, ckvcq, NDD, u, inv_sqrt);

    // 6) out = u @ w2t^T + bias2   [4096,5120]
    hgemm<<<grd(MROWS, DM, 1), blk>>>(u, w2t, out, nullptr, bias2,
        MROWS, DM, NH*DKV, NH*DKV, NH*DKV, DM, DM, DM, 1.0f, 0,0,0,0,0,0,0, 1);
}

// round 13
// speedup vs baseline: 1.4737x; 1.0655x over previous
#include <cuda_runtime.h>
#include <cuda_fp16.h>
#include <math.h>
#include <stdint.h>

// ---------------- problem constants ----------------
#define BATCH 2
#define SEQ   2048
#define DM    5120
#define NH    8
#define DH    640
#define DR    16
#define SPLITD 624
#define DKV   128
#define MROWS (BATCH*SEQ)        // 4096
#define KP    160                // per-head score K-dim: [128 ckv |16 rope |1 bias |15 pad]
#define LDQP  (NH*KP)            // 1280
#define NDD   256                // merged down-proj N: [ckv|cq]

// ---------------- scratch (device globals; no allocs allowed) ----------------
__device__ __align__(16) __half g_hh   [(size_t)MROWS*DM];
__device__ __align__(16) __half g_ckvcq[(size_t)MROWS*NDD];   // [ckv(0:128) | cq(128:256)]
__device__ __align__(16) __half g_krqrp[2*MROWS*DKV];          // [krp | qrp]
__device__ __align__(16) __half g_qp   [(size_t)MROWS*LDQP];
__device__ __align__(16) __half g_kp   [(size_t)MROWS*LDQP];
__device__ __align__(16) __half g_u    [(size_t)MROWS*NH*DKV]; // [4096,1024]
__device__ __align__(16) float  g_ckvf [MROWS*DKV];
__device__ __align__(16) float  g_part [2*(size_t)MROWS*NDD];  // split-K partials
// weights
__device__ __align__(16) __half g_wdd  [(size_t)NDD*DM];       // [wt_dkv; wt_dq] [256,5120]
__device__ __align__(16) __half g_wkq  [2*DKV*DKV];            // [wt_kr; wt_qr]
__device__ __align__(16) __half g_wt_out[(size_t)DM*DM];       // Wout^T [DM, NH*DH]
__device__ __align__(16) __half g_wuv_h [DKV*DM];
__device__ __align__(16) __half g_wuq_p [DKV*NH*DH];           // zero-padded 624->640
__device__ __align__(16) __half g_wuk_p [DKV*NH*DH];
__device__ __align__(16) __half g_mt    [NH*DKV*DKV];          // Mt_h = Wuk_h Wuq_h^T
__device__ __align__(16) __half g_w2t   [(size_t)DM*NH*DKV];   // [5120,1024]
__device__ __align__(16) float  g_bias2 [DM];
__device__ __align__(16) float  g_bqrow [NH*DKV];
__device__ __align__(16) float  g_wh    [NH*DKV];
__device__ __align__(16) float  g_sconst[NH];
__device__ __align__(16) float  g_bdd   [NDD];
__device__ __align__(16) float  g_bkq   [2*DKV];

// ---------------- PTX helpers ----------------
__device__ __forceinline__ uint32_t smem_u32(const void* p) {
    uint32_t a;
    asm("{ .reg .u64 t; cvta.to.shared.u64 t, %1; cvt.u32.u64 %0, t; }" : "=r"(a) : "l"(p));
    return a;
}
__device__ __forceinline__ void cp16(uint32_t dst, const void* src) {
    asm volatile("cp.async.cg.shared.global [%0], [%1], 16;" :: "r"(dst), "l"(src) : "memory");
}
#define CP_COMMIT() asm volatile("cp.async.commit_group;" ::: "memory")
#define CP_WAIT(n)  asm volatile("cp.async.wait_group %0;" :: "n"(n) : "memory")

__device__ __forceinline__ void ldm_x4(uint32_t* r, uint32_t addr) {
    asm volatile("ldmatrix.sync.aligned.m8n8.x4.shared.b16 {%0,%1,%2,%3}, [%4];"
                 : "=r"(r[0]), "=r"(r[1]), "=r"(r[2]), "=r"(r[3]) : "r"(addr));
}
__device__ __forceinline__ void ldm_x4t(uint32_t* r, uint32_t addr) {
    asm volatile("ldmatrix.sync.aligned.m8n8.x4.trans.shared.b16 {%0,%1,%2,%3}, [%4];"
                 : "=r"(r[0]), "=r"(r[1]), "=r"(r[2]), "=r"(r[3]) : "r"(addr));
}
__device__ __forceinline__ void mma_f16(float* c, const uint32_t* a, uint32_t b0, uint32_t b1) {
    asm volatile("mma.sync.aligned.m16n8k16.row.col.f32.f16.f16.f32 "
                 "{%0,%1,%2,%3}, {%4,%5,%6,%7}, {%8,%9}, {%0,%1,%2,%3};"
                 : "+f"(c[0]), "+f"(c[1]), "+f"(c[2]), "+f"(c[3])
                 : "r"(a[0]), "r"(a[1]), "r"(a[2]), "r"(a[3]), "r"(b0), "r"(b1));
}
__device__ __forceinline__ uint32_t packh2(float x, float y) {
    __half2 h = __floats2half2_rn(x, y);
    return *reinterpret_cast<uint32_t*>(&h);
}

// ============================================================================
// fp16 mma.sync GEMM: C = alpha*A*B^T + bias. 128x128 tile, BK=32, 2-stage.
// Cf written only for cols < cfN (ld ldcf); Ch full (ld ldc).
// ============================================================================
#define SPADH 40

__global__ __launch_bounds__(256)
void hgemm(const __half* __restrict__ A, const __half* __restrict__ B,
           float* __restrict__ Cf, __half* __restrict__ Ch,
           const float* __restrict__ bias,
           int M, int N, int K, int lda, int ldb, int ldc, int ldcf, int cfN,
           float alpha,
           long long sAhi, long long sAlo, long long sBhi, long long sBlo,
           long long sChi, long long sClo, long long sBiasLo, int zdiv)
{
    __shared__ __half As[2][128][SPADH];
    __shared__ __half Bs[2][128][SPADH];

    int tid  = threadIdx.x;
    int warp = tid >> 5;
    int lane = tid & 31;
    int wr = warp >> 1;
    int wc = warp & 1;
    int qid = lane >> 2;
    int tig = lane & 3;

    int z  = blockIdx.z;
    int zh = z / zdiv, zl = z % zdiv;
    A += zh * sAhi + zl * sAlo;
    B += zh * sBhi + zl * sBlo;
    long long cofs = zh * sChi + zl * sClo;
    if (Cf) Cf += cofs;
    if (Ch) Ch += cofs;
    if (bias) bias += zl * sBiasLo;

    int row0 = blockIdx.y * 128, col0 = blockIdx.x * 128;
    const __half* Ab = A + (size_t)row0 * lda;
    const __half* Bb = B + (size_t)col0 * ldb;

    int r0 = tid >> 2, cc = (tid & 3) * 8;
    int r1 = r0 + 64;
    uint32_t dA0[2], dA1[2], dB0[2], dB1[2];
#pragma unroll
    for (int s = 0; s < 2; s++) {
        dA0[s] = smem_u32(&As[s][r0][cc]);
        dA1[s] = smem_u32(&As[s][r1][cc]);
        dB0[s] = smem_u32(&Bs[s][r0][cc]);
        dB1[s] = smem_u32(&Bs[s][r1][cc]);
    }
    uint32_t aAddr[2][2], bAddr[2][4];
#pragma unroll
    for (int s = 0; s < 2; s++) {
#pragma unroll
        for (int mi = 0; mi < 2; mi++)
            aAddr[s][mi] = smem_u32(&As[s][wr * 32 + mi * 16 + (lane & 15)][(lane >> 4) * 8]);
#pragma unroll
        for (int np = 0; np < 4; np++)
            bAddr[s][np] = smem_u32(&Bs[s][wc * 64 + np * 16 + (lane & 7) + ((lane >> 4) & 1) * 8]
                                        [((lane >> 3) & 1) * 8]);
    }

    float acc[2][8][4];
#pragma unroll
    for (int mi = 0; mi < 2; mi++)
#pragma unroll
        for (int ni = 0; ni < 8; ni++)
#pragma unroll
            for (int i = 0; i < 4; i++) acc[mi][ni][i] = 0.0f;

    int T = K >> 5;

    cp16(dA0[0], Ab + (size_t)r0 * lda + cc);
    cp16(dA1[0], Ab + (size_t)r1 * lda + cc);
    cp16(dB0[0], Bb + (size_t)r0 * ldb + cc);
    cp16(dB1[0], Bb + (size_t)r1 * ldb + cc);
    CP_COMMIT();

    for (int t = 0; t < T; t++) {
        if (t + 1 < T) {
            int s = (t + 1) & 1;
            int k0 = (t + 1) * 32;
            cp16(dA0[s], Ab + (size_t)r0 * lda + k0 + cc);
            cp16(dA1[s], Ab + (size_t)r1 * lda + k0 + cc);
            cp16(dB0[s], Bb + (size_t)r0 * ldb + k0 + cc);
            cp16(dB1[s], Bb + (size_t)r1 * ldb + k0 + cc);
            CP_COMMIT();
            CP_WAIT(1);
        } else {
            CP_WAIT(0);
        }
        __syncthreads();

        int s = t & 1;
#pragma unroll
        for (int ks = 0; ks < 2; ks++) {
            uint32_t koff = ks * 32;
            uint32_t a[2][4], b[16];
#pragma unroll
            for (int mi = 0; mi < 2; mi++) ldm_x4(a[mi], aAddr[s][mi] + koff);
#pragma unroll
            for (int np = 0; np < 4; np++) ldm_x4(b + np * 4, bAddr[s][np] + koff);
#pragma unroll
            for (int ni = 0; ni < 8; ni++) {
                uint32_t b0 = b[(ni >> 1) * 4 + (ni & 1) * 2];
                uint32_t b1 = b[(ni >> 1) * 4 + (ni & 1) * 2 + 1];
                mma_f16(acc[0][ni], a[0], b0, b1);
                mma_f16(acc[1][ni], a[1], b0, b1);
            }
        }
        __syncthreads();
    }

#pragma unroll
    for (int mi = 0; mi < 2; mi++) {
        int rg = row0 + wr * 32 + mi * 16 + qid;
#pragma unroll
        for (int ni = 0; ni < 8; ni++) {
            int cg = col0 + wc * 64 + ni * 8 + tig * 2;
            float bx = 0.0f, by = 0.0f;
            if (bias) { bx = bias[cg]; by = bias[cg + 1]; }
            float o0 = alpha * acc[mi][ni][0] + bx;
            float o1 = alpha * acc[mi][ni][1] + by;
            float o2 = alpha * acc[mi][ni][2] + bx;
            float o3 = alpha * acc[mi][ni][3] + by;
            if (Cf && cg < cfN) {
                *reinterpret_cast<float2*>(Cf + (size_t)rg * ldcf + cg)       = make_float2(o0, o1);
                *reinterpret_cast<float2*>(Cf + (size_t)(rg + 8) * ldcf + cg) = make_float2(o2, o3);
            }
            if (Ch) {
                *reinterpret_cast<__half2*>(Ch + (size_t)rg * ldc + cg)       = __floats2half2_rn(o0, o1);
                *reinterpret_cast<__half2*>(Ch + (size_t)(rg + 8) * ldc + cg) = __floats2half2_rn(o2, o3);
            }
        }
    }
}

// ============================================================================
// flash attention: per CTA = (q-tile 128 rows, one (b,h)). online softmax.
// ============================================================================
#define FAQ_LD 168
#define FAV_LD 136
#define FA_SMEM ((3*128*FAQ_LD + 2*128*FAV_LD) * 2)   // 198656 B

__global__ __launch_bounds__(256, 1)
void flash_k(const __half* __restrict__ qp, const __half* __restrict__ kp,
             const __half* __restrict__ ckv, int ldckv,
             __half* __restrict__ u, float scale)
{
    extern __shared__ __half sm[];
    __half* Qs = sm;
    __half* Ks = sm + 128 * FAQ_LD;
    __half* Vs = sm + 3 * 128 * FAQ_LD;

    int tid = threadIdx.x;
    int warp = tid >> 5, lane = tid & 31;
    int qid = lane >> 2, tig = lane & 3;

    int qt = blockIdx.x;
    int z  = blockIdx.y;
    int b = z >> 3, h = z & 7;

    const __half* Qg = qp + ((size_t)(b * SEQ + qt * 128)) * LDQP + h * KP;
    const __half* Kg = kp + ((size_t)b * SEQ) * LDQP + h * KP;
    const __half* Vg = ckv + ((size_t)b * SEQ) * ldckv;

#pragma unroll
    for (int i = 0; i < 10; i++) {
        int idx = tid + i * 256;
        int r = idx / 20, c = idx % 20;
        cp16(smem_u32(Qs + r * FAQ_LD + c * 8), Qg + (size_t)r * LDQP + c * 8);
    }
#pragma unroll
    for (int i = 0; i < 10; i++) {
        int idx = tid + i * 256;
        int r = idx / 20, c = idx % 20;
        cp16(smem_u32(Ks + r * FAQ_LD + c * 8), Kg + (size_t)r * LDQP + c * 8);
    }
#pragma unroll
    for (int i = 0; i < 8; i++) {
        int idx = tid + i * 256;
        int r = idx / 16, c = idx % 16;
        cp16(smem_u32(Vs + r * FAV_LD + c * 8), Vg + (size_t)r * ldckv + c * 8);
    }
    CP_COMMIT();

    uint32_t qAddr = smem_u32(Qs + (warp * 16 + (lane & 15)) * FAQ_LD + (lane >> 4) * 8);
    uint32_t kAddr[2][8], vAddr[2][8];
#pragma unroll
    for (int s = 0; s < 2; s++) {
#pragma unroll
        for (int nb = 0; nb < 8; nb++) {
            kAddr[s][nb] = smem_u32(Ks + s * 128 * FAQ_LD
                + (nb * 16 + (lane & 7) + ((lane >> 4) & 1) * 8) * FAQ_LD
                + ((lane >> 3) & 1) * 8);
            vAddr[s][nb] = smem_u32(Vs + s * 128 * FAV_LD
                + (lane & 15) * FAV_LD
                + nb * 16 + ((lane >> 4) << 3));
        }
    }

    float oacc[16][4];
#pragma unroll
    for (int j = 0; j < 16; j++)
#pragma unroll
        for (int i = 0; i < 4; i++) oacc[j][i] = 0.0f;
    float m0 = -1e30f, m1 = -1e30f, l0 = 0.0f, l1 = 0.0f;

    for (int kt = 0; kt < 16; kt++) {
        CP_WAIT(0);
        __syncthreads();
        if (kt + 1 < 16) {
            int s = (kt + 1) & 1;
            const __half* Kt = Kg + (size_t)(kt + 1) * 128 * LDQP;
            const __half* Vt = Vg + (size_t)(kt + 1) * 128 * ldckv;
#pragma unroll
            for (int i = 0; i < 10; i++) {
                int idx = tid + i * 256;
                int r = idx / 20, c = idx % 20;
                cp16(smem_u32(Ks + s * 128 * FAQ_LD + r * FAQ_LD + c * 8),
                     Kt + (size_t)r * LDQP + c * 8);
            }
#pragma unroll
            for (int i = 0; i < 8; i++) {
                int idx = tid + i * 256;
                int r = idx / 16, c = idx % 16;
                cp16(smem_u32(Vs + s * 128 * FAV_LD + r * FAV_LD + c * 8),
                     Vt + (size_t)r * ldckv + c * 8);
            }
            CP_COMMIT();
        }

        int s = kt & 1;
        float sacc[16][4];
#pragma unroll
        for (int j = 0; j < 16; j++)
#pragma unroll
            for (int i = 0; i < 4; i++) sacc[j][i] = 0.0f;
#pragma unroll
        for (int ks = 0; ks < 10; ks++) {
            uint32_t a[4];
            ldm_x4(a, qAddr + ks * 32);
#pragma unroll
            for (int nb = 0; nb < 8; nb++) {
                uint32_t bb[4];
                ldm_x4(bb, kAddr[s][nb] + ks * 32);
                mma_f16(sacc[2 * nb],     a, bb[0], bb[1]);
                mma_f16(sacc[2 * nb + 1], a, bb[2], bb[3]);
            }
        }
        float mx0 = -1e30f, mx1 = -1e30f;
#pragma unroll
        for (int j = 0; j < 16; j++) {
            sacc[j][0] *= scale; sacc[j][1] *= scale;
            sacc[j][2] *= scale; sacc[j][3] *= scale;
            mx0 = fmaxf(mx0, fmaxf(sacc[j][0], sacc[j][1]));
            mx1 = fmaxf(mx1, fmaxf(sacc[j][2], sacc[j][3]));
        }
        mx0 = fmaxf(mx0, __shfl_xor_sync(0xFFFFFFFF, mx0, 1));
        mx0 = fmaxf(mx0, __shfl_xor_sync(0xFFFFFFFF, mx0, 2));
        mx1 = fmaxf(mx1, __shfl_xor_sync(0xFFFFFFFF, mx1, 1));
        mx1 = fmaxf(mx1, __shfl_xor_sync(0xFFFFFFFF, mx1, 2));
        float mn0 = fmaxf(m0, mx0), mn1 = fmaxf(m1, mx1);
        float f0 = __expf(m0 - mn0), f1 = __expf(m1 - mn1);
        m0 = mn0; m1 = mn1;
        float ts0 = 0.0f, ts1 = 0.0f;
#pragma unroll
        for (int j = 0; j < 16; j++) {
            sacc[j][0] = __expf(sacc[j][0] - m0);
            sacc[j][1] = __expf(sacc[j][1] - m0);
            sacc[j][2] = __expf(sacc[j][2] - m1);
            sacc[j][3] = __expf(sacc[j][3] - m1);
            ts0 += sacc[j][0] + sacc[j][1];
            ts1 += sacc[j][2] + sacc[j][3];
        }
        ts0 += __shfl_xor_sync(0xFFFFFFFF, ts0, 1);
        ts0 += __shfl_xor_sync(0xFFFFFFFF, ts0, 2);
        ts1 += __shfl_xor_sync(0xFFFFFFFF, ts1, 1);
        ts1 += __shfl_xor_sync(0xFFFFFFFF, ts1, 2);
        l0 = l0 * f0 + ts0;
        l1 = l1 * f1 + ts1;
#pragma unroll
        for (int j = 0; j < 16; j++) {
            oacc[j][0] *= f0; oacc[j][1] *= f0;
            oacc[j][2] *= f1; oacc[j][3] *= f1;
        }
#pragma unroll
        for (int kb = 0; kb < 8; kb++) {
            uint32_t a[4];
            a[0] = packh2(sacc[2 * kb][0],     sacc[2 * kb][1]);
            a[1] = packh2(sacc[2 * kb][2],     sacc[2 * kb][3]);
            a[2] = packh2(sacc[2 * kb + 1][0], sacc[2 * kb + 1][1]);
            a[3] = packh2(sacc[2 * kb + 1][2], sacc[2 * kb + 1][3]);
            uint32_t voff = (uint32_t)(kb * 16 * FAV_LD * 2);
#pragma unroll
            for (int nb = 0; nb < 8; nb++) {
                uint32_t bb[4];
                ldm_x4t(bb, vAddr[s][nb] + voff);
                mma_f16(oacc[2 * nb],     a, bb[0], bb[1]);
                mma_f16(oacc[2 * nb + 1], a, bb[2], bb[3]);
            }
        }
    }

    float il0 = 1.0f / l0, il1 = 1.0f / l1;
    int rowg = b * SEQ + qt * 128 + warp * 16;
#pragma unroll
    for (int j = 0; j < 16; j++) {
        int col = h * 128 + j * 8 + tig * 2;
        *reinterpret_cast<__half2*>(u + (size_t)(rowg + qid) * (NH * DKV) + col)
            = __floats2half2_rn(oacc[j][0] * il0, oacc[j][1] * il0);
        *reinterpret_cast<__half2*>(u + (size_t)(rowg + qid + 8) * (NH * DKV) + col)
            = __floats2half2_rn(oacc[j][2] * il1, oacc[j][3] * il1);
    }
}

// ============================================================================
// small kernels
// ============================================================================
__global__ __launch_bounds__(256)
void transpose_f2h(const float* __restrict__ in, __half* __restrict__ out, int ldi, int ldo)
{
    __shared__ float t[32][33];
    int bx = blockIdx.x * 32, by = blockIdx.y * 32;
    int tx = threadIdx.x & 31, ty = threadIdx.x >> 5;
#pragma unroll
    for (int i = 0; i < 4; i++)
        t[ty + 8 * i][tx] = in[(size_t)(by + ty + 8 * i) * ldi + bx + tx];
    __syncthreads();
#pragma unroll
    for (int i = 0; i < 4; i++)
        out[(size_t)(bx + ty + 8 * i) * ldo + by + tx] = __float2half_rn(t[tx][ty + 8 * i]);
}

__global__ void f2h_k(const float* __restrict__ in, __half* __restrict__ out, int n4)
{
    int i = blockIdx.x * blockDim.x + threadIdx.x;
    if (i >= n4) return;
    float4 v = *reinterpret_cast<const float4*>(in + (size_t)i * 4);
    __half2 a = __floats2half2_rn(v.x, v.y);
    __half2 b = __floats2half2_rn(v.z, v.w);
    *reinterpret_cast<uint2*>(out + (size_t)i * 4) = make_uint2(
        *reinterpret_cast<uint32_t*>(&a), *reinterpret_cast<uint32_t*>(&b));
}

__global__ void pad_w_k(const float* __restrict__ in, __half* __restrict__ out)
{
    int idx = blockIdx.x * blockDim.x + threadIdx.x;
    if (idx >= DKV * NH * DH) return;
    int i = idx / (NH * DH);
    int c = idx % (NH * DH);
    int h = c / DH, d = c % DH;
    float v = (d < SPLITD) ? in[(size_t)i * (NH * SPLITD) + h * SPLITD + d] : 0.0f;
    out[idx] = __float2half_rn(v);
}

// bias2 = outb + buv @ Wout : 2D-parallel, coalesced, atomic accumulate
__global__ void bias2init_k(const float* __restrict__ outb, float* __restrict__ o)
{
    int n = blockIdx.x * 256 + threadIdx.x;
    if (n < DM) o[n] = outb[n];
}
__global__ __launch_bounds__(256)
void bias2p_k(const float* __restrict__ outw, const float* __restrict__ buv,
              float* __restrict__ o)
{
    int n = blockIdx.x * 256 + threadIdx.x;
    int m0 = blockIdx.y * 256;
    float s = 0.0f;
#pragma unroll 4
    for (int i = 0; i < 256; i++)
        s += buv[m0 + i] * outw[(size_t)(m0 + i) * DM + n];
    atomicAdd(&o[n], s);
}

__global__ void bqrow_k(const float* __restrict__ buq, const float* __restrict__ wuk,
                        float* __restrict__ o)
{
    int idx = blockIdx.x * blockDim.x + threadIdx.x;
    if (idx >= NH * DKV) return;
    int h = idx / DKV, n = idx % DKV;
    float s = 0.0f;
    for (int d = 0; d < SPLITD; d++)
        s += buq[h * SPLITD + d] * wuk[(size_t)n * (NH * SPLITD) + h * SPLITD + d];
    o[idx] = s;
}

__global__ void wh_k(const float* __restrict__ wuq, const float* __restrict__ buk,
                     const float* __restrict__ buq, float* __restrict__ o, float* __restrict__ sc)
{
    int idx = blockIdx.x * blockDim.x + threadIdx.x;
    if (idx >= NH * DKV) return;
    int h = idx / DKV, k = idx % DKV;
    float s = 0.0f;
    for (int d = 0; d < SPLITD; d++)
        s += wuq[(size_t)k * (NH * SPLITD) + h * SPLITD + d] * buk[h * SPLITD + d];
    o[idx] = s;
    if (k == 0) {
        float c = 0.0f;
        for (int d = 0; d < SPLITD; d++) c += buq[h * SPLITD + d] * buk[h * SPLITD + d];
        sc[h] = c;
    }
}

__global__ void bias_cat2(const float* a, const float* b, float* o, int n1, int n2)
{
    int i = blockIdx.x * blockDim.x + threadIdx.x;
    if (i >= n1 + n2) return;
    o[i] = (i < n1) ? a[i] : b[i - n1];
}

// split-K reduce: ckvcq_half = p0+p1+bdd ; ckv float output for cols<128
__global__ void spk_reduce(const float* __restrict__ p0, const float* __restrict__ p1,
                           const float* __restrict__ bdd,
                           __half* __restrict__ ckvcq, float* __restrict__ ckvf)
{
    int i = blockIdx.x * blockDim.x + threadIdx.x;
    if (i >= MROWS * NDD) return;
    int m = i / NDD, c = i % NDD;
    float s = p0[i] + p1[i] + bdd[c];
    ckvcq[i] = __float2half_rn(s);
    if (c < DKV) ckvf[(size_t)m * DKV + c] = s;
}

__global__ void sq_k(const __half* __restrict__ cq, int ldcq, const float* __restrict__ wh,
                     const float* __restrict__ scst, __half* __restrict__ qp)
{
    int idx = blockIdx.x * blockDim.x + threadIdx.x;
    if (idx >= MROWS * NH) return;
    int m = idx / NH, h = idx % NH;
    float s = scst[h];
    for (int k = 0; k < DKV; k++)
        s += __half2float(cq[(size_t)m * ldcq + k]) * wh[h * DKV + k];
    qp[(size_t)m * LDQP + h * KP + 144] = __float2half_rn(s);
}

__global__ void qppad_k(__half* __restrict__ qp)
{
    int idx = blockIdx.x * blockDim.x + threadIdx.x;
    if (idx >= MROWS * NH) return;
    int m = idx / NH, h = idx % NH;
    __half* p = qp + (size_t)m * LDQP + h * KP;
    for (int c = 145; c < KP; c++) p[c] = __float2half_rn(0.0f);
}

__global__ void kpfill_k(const __half* __restrict__ ckv, int ldckv, __half* __restrict__ kp)
{
    int idx = blockIdx.x * blockDim.x + threadIdx.x;
    int total = MROWS * NH * 18;
    if (idx >= total) return;
    int c = idx % 18;
    int mh = idx / 18;
    int m = mh / NH, h = mh % NH;
    __half* p = kp + (size_t)m * LDQP + h * KP;
    if (c < 16) {
        uint4 v = *reinterpret_cast<const uint4*>(ckv + (size_t)m * ldckv + c * 8);
        *reinterpret_cast<uint4*>(p + c * 8) = v;
    } else if (c == 16) {
        __half z = __float2half_rn(0.0f);
        __half vals[8] = { __float2half_rn(1.0f), z, z, z, z, z, z, z };
        *reinterpret_cast<uint4*>(p + 144) = *reinterpret_cast<uint4*>(vals);
    } else {
        __half z = __float2half_rn(0.0f);
        __half vals[8] = { z, z, z, z, z, z, z, z };
        *reinterpret_cast<uint4*>(p + 152) = *reinterpret_cast<uint4*>(vals);
    }
}

__global__ void rope_k(const __half* __restrict__ pre, __half* __restrict__ dst,
                       float* __restrict__ rout)
{
    int idx = blockIdx.x * blockDim.x + threadIdx.x;
    if (idx >= MROWS * DKV) return;
    int m = idx >> 7;
    int c = idx & 127;
    int h = c >> 4;
    int d = c & 15;
    int j = d & 7;
    int s = m & (SEQ - 1);
    float t = (float)s * (1.0f / 40.0f);
    float invf = __expf(-(float)j * 0.86346941f);  // ln(1000)/8
    float ang = t * invf;
    float sn, cs;
    sincosf(ang, &sn, &cs);
    float x = __half2float(pre[idx]);
    float p = __half2float(pre[(m << 7) + (h << 4) + ((d < 8) ? d + 8 : d - 8)]);
    float val = x * cs + ((d < 8) ? -p : p) * sn;
    dst[(size_t)m * LDQP + h * KP + 128 + d] = __float2half_rn(val);
    if (rout) rout[idx] = val;
}

// ============================================================================
// host launcher
// ============================================================================
extern "C" void kernel_launch(void* const* d_in, const int* in_sizes, int n_in,
                              void* d_out, int out_size)
{
    const float* h    = (const float*)d_in[0];
    const float* Wdkv = (const float*)d_in[1];
    const float* bdkv = (const float*)d_in[2];
    const float* Wdq  = (const float*)d_in[3];
    const float* bdq  = (const float*)d_in[4];
    const float* Wuk  = (const float*)d_in[5];
    const float* buk  = (const float*)d_in[6];
    const float* Wuv  = (const float*)d_in[7];
    const float* buv  = (const float*)d_in[8];
    const float* Wuq  = (const float*)d_in[9];
    const float* buq  = (const float*)d_in[10];
    const float* Wqr  = (const float*)d_in[11];
    const float* bqr  = (const float*)d_in[12];
    const float* Wkr  = (const float*)d_in[13];
    const float* bkr  = (const float*)d_in[14];
    const float* outw = (const float*)d_in[15];
    const float* outb = (const float*)d_in[16];
    float* out = (float*)d_out;

    __half *hh, *ckvcq, *krqrp, *qp, *kp, *u;
    __half *wdd, *wkq, *wt_out, *wuv_h, *wuq_p, *wuk_p, *mt, *w2t;
    float *ckvf, *part, *bias2, *bqrow, *wh, *scst, *bdd, *bkq;
    cudaGetSymbolAddress((void**)&hh,    g_hh);
    cudaGetSymbolAddress((void**)&ckvcq, g_ckvcq);
    cudaGetSymbolAddress((void**)&krqrp, g_krqrp);
    cudaGetSymbolAddress((void**)&qp,    g_qp);
    cudaGetSymbolAddress((void**)&kp,    g_kp);
    cudaGetSymbolAddress((void**)&u,     g_u);
    cudaGetSymbolAddress((void**)&ckvf,  g_ckvf);
    cudaGetSymbolAddress((void**)&part,  g_part);
    cudaGetSymbolAddress((void**)&wdd,   g_wdd);
    cudaGetSymbolAddress((void**)&wkq,   g_wkq);
    cudaGetSymbolAddress((void**)&wt_out, g_wt_out);
    cudaGetSymbolAddress((void**)&wuv_h,  g_wuv_h);
    cudaGetSymbolAddress((void**)&wuq_p,  g_wuq_p);
    cudaGetSymbolAddress((void**)&wuk_p,  g_wuk_p);
    cudaGetSymbolAddress((void**)&mt,     g_mt);
    cudaGetSymbolAddress((void**)&w2t,    g_w2t);
    cudaGetSymbolAddress((void**)&bias2,  g_bias2);
    cudaGetSymbolAddress((void**)&bqrow,  g_bqrow);
    cudaGetSymbolAddress((void**)&wh,     g_wh);
    cudaGetSymbolAddress((void**)&scst,   g_sconst);
    cudaGetSymbolAddress((void**)&bdd,    g_bdd);
    cudaGetSymbolAddress((void**)&bkq,    g_bkq);

    cudaFuncSetAttribute(flash_k, cudaFuncAttributeMaxDynamicSharedMemorySize, FA_SMEM);

    dim3 b256(256);
    f2h_k<<<((size_t)MROWS * DM / 4 + 255) / 256, 256>>>(h, hh, MROWS * DM / 4);
    f2h_k<<<(DKV * DM / 4 + 255) / 256, 256>>>(Wuv, wuv_h, DKV * DM / 4);
    transpose_f2h<<<dim3(DKV/32, DM/32), b256>>>(Wdkv, wdd,                 DKV, DM);
    transpose_f2h<<<dim3(DKV/32, DM/32), b256>>>(Wdq,  wdd + (size_t)DKV*DM, DKV, DM);
    transpose_f2h<<<dim3(DKV/32, DKV/32), b256>>>(Wkr, wkq,                 DKV, DKV);
    transpose_f2h<<<dim3(DKV/32, DKV/32), b256>>>(Wqr, wkq + DKV*DKV,       DKV, DKV);
    transpose_f2h<<<dim3(DM/32, DM/32), b256>>>(outw, wt_out, DM, DM);
    pad_w_k<<<(DKV * NH * DH + 255) / 256, 256>>>(Wuq, wuq_p);
    pad_w_k<<<(DKV * NH * DH + 255) / 256, 256>>>(Wuk, wuk_p);
    bias2init_k<<<DM / 256, 256>>>(outb, bias2);
    bias2p_k<<<dim3(DM / 256, DM / 256), 256>>>(outw, buv, bias2);
    bqrow_k<<<(NH * DKV + 255) / 256, 256>>>(buq, Wuk, bqrow);
    wh_k<<<(NH * DKV + 255) / 256, 256>>>(Wuq, buk, buq, wh, scst);
    bias_cat2<<<(NDD + 255) / 256, 256>>>(bdkv, bdq, bdd, DKV, DKV);
    bias_cat2<<<(2 * DKV + 255) / 256, 256>>>(bkr, bqr, bkq, DKV, DKV);

    const size_t out_ckv_off  = (size_t)MROWS * DM;
    const size_t out_krot_off = out_ckv_off + (size_t)MROWS * DKV;
    bool full_out = (size_t)out_size >= out_krot_off + (size_t)MROWS * DKV;
    float* ckv_dst = full_out ? (out + out_ckv_off) : ckvf;

    dim3 blk(256);
    auto grd = [](int M, int N, int Z) { return dim3((unsigned)(N / 128), (unsigned)(M / 128), (unsigned)Z); };

    // precompute Mt_h = Wuk_h Wuq_h^T  [8][128][128]
    hgemm<<<grd(DKV, DKV, NH), blk>>>(wuk_p, wuq_p, nullptr, mt, nullptr,
        DKV, DKV, DH, NH*DH, NH*DH, DKV, DKV, 0, 1.0f,
        0, DH, 0, DH, 0, DKV*DKV, 0, NH);
    // precompute w2t[n, h*128+j] = sum_d Wout^T[n, h*640+d] * Wuv[j, h*640+d]
    hgemm<<<grd(DM, DKV, NH), blk>>>(wt_out, wuv_h, nullptr, w2t, nullptr,
        DM, DKV, DH, DM, DM, NH*DKV, NH*DKV, 0, 1.0f,
        0, DH, 0, DH, 0, DKV, 0, NH);

    // 1) merged down projection with split-K (z = K-half of 2560): float partials,
    //    then reduce adds bias and emits half ckvcq + float ckv model-output.
    hgemm<<<grd(MROWS, NDD, 2), blk>>>(hh, wdd, part, nullptr, nullptr,
        MROWS, NDD, DM/2, DM, DM, NDD, NDD, NDD, 1.0f,
        0, DM/2, 0, DM/2, 0, (long long)MROWS * NDD, 0, 2);
    spk_reduce<<<(MROWS * NDD + 255) / 256, 256>>>(part, part + (size_t)MROWS * NDD,
        bdd, ckvcq, ckv_dst);

    // 2) merged rotary pre-projections: z=0: krp = ckv@Wkr^T; z=1: qrp = cq@Wqr^T
    hgemm<<<grd(MROWS, DKV, 2), blk>>>(ckvcq, wkq, nullptr, krqrp, bkq,
        MROWS, DKV, DKV, NDD, DKV, DKV, DKV, 0, 1.0f,
        0, DKV, 0, DKV*DKV, 0, (long long)MROWS*DKV, DKV, 2);

    // 3) q-tilde = cq @ Mt_h^T + bqrow_h  -> qp cols [h*KP .. h*KP+127]
    hgemm<<<grd(MROWS, DKV, NH), blk>>>(ckvcq + DKV, mt, nullptr, qp, bqrow,
        MROWS, DKV, DKV, NDD, DKV, LDQP, LDQP, 0, 1.0f,
        0, 0, 0, DKV*DKV, 0, KP, DKV, NH);

    // 4) assemble qp / kp
    rope_k<<<(MROWS * DKV + 255) / 256, 256>>>(krqrp + (size_t)MROWS * DKV, qp, nullptr);
    rope_k<<<(MROWS * DKV + 255) / 256, 256>>>(krqrp, kp,
        full_out ? (out + out_krot_off) : nullptr);
    sq_k<<<(MROWS * NH + 255) / 256, 256>>>(ckvcq + DKV, NDD, wh, scst, qp);
    qppad_k<<<(MROWS * NH + 255) / 256, 256>>>(qp);
    kpfill_k<<<(MROWS * NH * 18 + 255) / 256, 256>>>(ckvcq, NDD, kp);

    // 5) fused flash attention -> u [4096, 1024]
    float inv_sqrt = 1.0f / sqrtf((float)DH);
    flash_k<<<dim3(SEQ/128, BATCH*NH), blk, FA_SMEM>>>(qp, kp, ckvcq, NDD, u, inv_sqrt);

    // 6) out = u @ w2t^T + bias2   [4096,5120]
    hgemm<<<grd(MROWS, DM, 1), blk>>>(u, w2t, out, nullptr, bias2,
        MROWS, DM, NH*DKV, NH*DKV, NH*DKV, DM, DM, DM, 1.0f, 0,0,0,0,0,0,0, 1);
}

// round 14
// speedup vs baseline: 1.7708x; 1.2016x over previous
#include <cuda_runtime.h>
#include <cuda_fp16.h>
#include <math.h>
#include <stdint.h>

// ---------------- problem constants ----------------
#define BATCH 2
#define SEQ   2048
#define DM    5120
#define NH    8
#define DH    640
#define DR    16
#define SPLITD 624
#define DKV   128
#define MROWS (BATCH*SEQ)        // 4096
#define KP    160                // per-head score K-dim: [128 ckv |16 rope |1 bias |15 pad]
#define LDQP  (NH*KP)            // 1280
#define NDD   256                // merged down-proj N: [ckv|cq]

// ---------------- scratch (device globals; no allocs allowed) ----------------
__device__ __align__(16) __half g_hh   [(size_t)MROWS*DM];
__device__ __align__(16) __half g_ckvcq[(size_t)MROWS*NDD];   // [ckv(0:128) | cq(128:256)]
__device__ __align__(16) __half g_krqrp[2*MROWS*DKV];          // [krp | qrp]
__device__ __align__(16) __half g_qp   [(size_t)MROWS*LDQP];
__device__ __align__(16) __half g_kp   [(size_t)MROWS*LDQP];
__device__ __align__(16) __half g_u    [(size_t)MROWS*NH*DKV]; // [4096,1024]
__device__ __align__(16) float  g_ckvf [MROWS*DKV];
__device__ __align__(16) float  g_part [2*(size_t)MROWS*NDD];  // split-K partials
// weights
__device__ __align__(16) __half g_wdd  [(size_t)NDD*DM];       // [wt_dkv; wt_dq] [256,5120]
__device__ __align__(16) __half g_wkq  [2*DKV*DKV];            // [wt_kr; wt_qr]
__device__ __align__(16) __half g_wt_out[(size_t)DM*DM];       // Wout^T [DM, NH*DH]
__device__ __align__(16) __half g_wuv_h [DKV*DM];
__device__ __align__(16) __half g_wuq_p [DKV*NH*DH];           // zero-padded 624->640
__device__ __align__(16) __half g_wuk_p [DKV*NH*DH];
__device__ __align__(16) __half g_mt    [NH*DKV*DKV];          // Mt_h = Wuk_h Wuq_h^T
__device__ __align__(16) __half g_w2t   [(size_t)DM*NH*DKV];   // [5120,1024]
__device__ __align__(16) float  g_bias2 [DM];
__device__ __align__(16) float  g_bqrow [NH*DKV];
__device__ __align__(16) float  g_wh    [NH*DKV];
__device__ __align__(16) float  g_sconst[NH];
__device__ __align__(16) float  g_bdd   [NDD];
__device__ __align__(16) float  g_bkq   [2*DKV];

// ---------------- PTX helpers ----------------
__device__ __forceinline__ uint32_t smem_u32(const void* p) {
    uint32_t a;
    asm("{ .reg .u64 t; cvta.to.shared.u64 t, %1; cvt.u32.u64 %0, t; }" : "=r"(a) : "l"(p));
    return a;
}
__device__ __forceinline__ void cp16(uint32_t dst, const void* src) {
    asm volatile("cp.async.cg.shared.global [%0], [%1], 16;" :: "r"(dst), "l"(src) : "memory");
}
#define CP_COMMIT() asm volatile("cp.async.commit_group;" ::: "memory")
#define CP_WAIT(n)  asm volatile("cp.async.wait_group %0;" :: "n"(n) : "memory")

__device__ __forceinline__ void ldm_x4(uint32_t* r, uint32_t addr) {
    asm volatile("ldmatrix.sync.aligned.m8n8.x4.shared.b16 {%0,%1,%2,%3}, [%4];"
                 : "=r"(r[0]), "=r"(r[1]), "=r"(r[2]), "=r"(r[3]) : "r"(addr));
}
__device__ __forceinline__ void ldm_x4t(uint32_t* r, uint32_t addr) {
    asm volatile("ldmatrix.sync.aligned.m8n8.x4.trans.shared.b16 {%0,%1,%2,%3}, [%4];"
                 : "=r"(r[0]), "=r"(r[1]), "=r"(r[2]), "=r"(r[3]) : "r"(addr));
}
__device__ __forceinline__ void mma_f16(float* c, const uint32_t* a, uint32_t b0, uint32_t b1) {
    asm volatile("mma.sync.aligned.m16n8k16.row.col.f32.f16.f16.f32 "
                 "{%0,%1,%2,%3}, {%4,%5,%6,%7}, {%8,%9}, {%0,%1,%2,%3};"
                 : "+f"(c[0]), "+f"(c[1]), "+f"(c[2]), "+f"(c[3])
                 : "r"(a[0]), "r"(a[1]), "r"(a[2]), "r"(a[3]), "r"(b0), "r"(b1));
}
__device__ __forceinline__ uint32_t packh2(float x, float y) {
    __half2 h = __floats2half2_rn(x, y);
    return *reinterpret_cast<uint32_t*>(&h);
}

// ============================================================================
// fp16 mma.sync GEMM: C = alpha*A*B^T + bias. 128x128 tile, BK=32, 2-stage.
// Cf written only for cols < cfN (ld ldcf); Ch full (ld ldc).
// ============================================================================
#define SPADH 40

__global__ __launch_bounds__(256)
void hgemm(const __half* __restrict__ A, const __half* __restrict__ B,
           float* __restrict__ Cf, __half* __restrict__ Ch,
           const float* __restrict__ bias,
           int M, int N, int K, int lda, int ldb, int ldc, int ldcf, int cfN,
           float alpha,
           long long sAhi, long long sAlo, long long sBhi, long long sBlo,
           long long sChi, long long sClo, long long sBiasLo, int zdiv)
{
    __shared__ __half As[2][128][SPADH];
    __shared__ __half Bs[2][128][SPADH];

    int tid  = threadIdx.x;
    int warp = tid >> 5;
    int lane = tid & 31;
    int wr = warp >> 1;
    int wc = warp & 1;
    int qid = lane >> 2;
    int tig = lane & 3;

    int z  = blockIdx.z;
    int zh = z / zdiv, zl = z % zdiv;
    A += zh * sAhi + zl * sAlo;
    B += zh * sBhi + zl * sBlo;
    long long cofs = zh * sChi + zl * sClo;
    if (Cf) Cf += cofs;
    if (Ch) Ch += cofs;
    if (bias) bias += zl * sBiasLo;

    int row0 = blockIdx.y * 128, col0 = blockIdx.x * 128;
    const __half* Ab = A + (size_t)row0 * lda;
    const __half* Bb = B + (size_t)col0 * ldb;

    int r0 = tid >> 2, cc = (tid & 3) * 8;
    int r1 = r0 + 64;
    uint32_t dA0[2], dA1[2], dB0[2], dB1[2];
#pragma unroll
    for (int s = 0; s < 2; s++) {
        dA0[s] = smem_u32(&As[s][r0][cc]);
        dA1[s] = smem_u32(&As[s][r1][cc]);
        dB0[s] = smem_u32(&Bs[s][r0][cc]);
        dB1[s] = smem_u32(&Bs[s][r1][cc]);
    }
    uint32_t aAddr[2][2], bAddr[2][4];
#pragma unroll
    for (int s = 0; s < 2; s++) {
#pragma unroll
        for (int mi = 0; mi < 2; mi++)
            aAddr[s][mi] = smem_u32(&As[s][wr * 32 + mi * 16 + (lane & 15)][(lane >> 4) * 8]);
#pragma unroll
        for (int np = 0; np < 4; np++)
            bAddr[s][np] = smem_u32(&Bs[s][wc * 64 + np * 16 + (lane & 7) + ((lane >> 4) & 1) * 8]
                                        [((lane >> 3) & 1) * 8]);
    }

    float acc[2][8][4];
#pragma unroll
    for (int mi = 0; mi < 2; mi++)
#pragma unroll
        for (int ni = 0; ni < 8; ni++)
#pragma unroll
            for (int i = 0; i < 4; i++) acc[mi][ni][i] = 0.0f;

    int T = K >> 5;

    cp16(dA0[0], Ab + (size_t)r0 * lda + cc);
    cp16(dA1[0], Ab + (size_t)r1 * lda + cc);
    cp16(dB0[0], Bb + (size_t)r0 * ldb + cc);
    cp16(dB1[0], Bb + (size_t)r1 * ldb + cc);
    CP_COMMIT();

    for (int t = 0; t < T; t++) {
        if (t + 1 < T) {
            int s = (t + 1) & 1;
            int k0 = (t + 1) * 32;
            cp16(dA0[s], Ab + (size_t)r0 * lda + k0 + cc);
            cp16(dA1[s], Ab + (size_t)r1 * lda + k0 + cc);
            cp16(dB0[s], Bb + (size_t)r0 * ldb + k0 + cc);
            cp16(dB1[s], Bb + (size_t)r1 * ldb + k0 + cc);
            CP_COMMIT();
            CP_WAIT(1);
        } else {
            CP_WAIT(0);
        }
        __syncthreads();

        int s = t & 1;
#pragma unroll
        for (int ks = 0; ks < 2; ks++) {
            uint32_t koff = ks * 32;
            uint32_t a[2][4], b[16];
#pragma unroll
            for (int mi = 0; mi < 2; mi++) ldm_x4(a[mi], aAddr[s][mi] + koff);
#pragma unroll
            for (int np = 0; np < 4; np++) ldm_x4(b + np * 4, bAddr[s][np] + koff);
#pragma unroll
            for (int ni = 0; ni < 8; ni++) {
                uint32_t b0 = b[(ni >> 1) * 4 + (ni & 1) * 2];
                uint32_t b1 = b[(ni >> 1) * 4 + (ni & 1) * 2 + 1];
                mma_f16(acc[0][ni], a[0], b0, b1);
                mma_f16(acc[1][ni], a[1], b0, b1);
            }
        }
        __syncthreads();
    }

#pragma unroll
    for (int mi = 0; mi < 2; mi++) {
        int rg = row0 + wr * 32 + mi * 16 + qid;
#pragma unroll
        for (int ni = 0; ni < 8; ni++) {
            int cg = col0 + wc * 64 + ni * 8 + tig * 2;
            float bx = 0.0f, by = 0.0f;
            if (bias) { bx = bias[cg]; by = bias[cg + 1]; }
            float o0 = alpha * acc[mi][ni][0] + bx;
            float o1 = alpha * acc[mi][ni][1] + by;
            float o2 = alpha * acc[mi][ni][2] + bx;
            float o3 = alpha * acc[mi][ni][3] + by;
            if (Cf && cg < cfN) {
                *reinterpret_cast<float2*>(Cf + (size_t)rg * ldcf + cg)       = make_float2(o0, o1);
                *reinterpret_cast<float2*>(Cf + (size_t)(rg + 8) * ldcf + cg) = make_float2(o2, o3);
            }
            if (Ch) {
                *reinterpret_cast<__half2*>(Ch + (size_t)rg * ldc + cg)       = __floats2half2_rn(o0, o1);
                *reinterpret_cast<__half2*>(Ch + (size_t)(rg + 8) * ldc + cg) = __floats2half2_rn(o2, o3);
            }
        }
    }
}

// ============================================================================
// flash attention: per CTA = (q-tile 128 rows, one (b,h)). online softmax.
// ============================================================================
#define FAQ_LD 168
#define FAV_LD 136
#define FA_SMEM ((3*128*FAQ_LD + 2*128*FAV_LD) * 2)   // 198656 B

__global__ __launch_bounds__(256, 1)
void flash_k(const __half* __restrict__ qp, const __half* __restrict__ kp,
             const __half* __restrict__ ckv, int ldckv,
             __half* __restrict__ u, float scale)
{
    extern __shared__ __half sm[];
    __half* Qs = sm;
    __half* Ks = sm + 128 * FAQ_LD;
    __half* Vs = sm + 3 * 128 * FAQ_LD;

    int tid = threadIdx.x;
    int warp = tid >> 5, lane = tid & 31;
    int qid = lane >> 2, tig = lane & 3;

    int qt = blockIdx.x;
    int z  = blockIdx.y;
    int b = z >> 3, h = z & 7;

    const __half* Qg = qp + ((size_t)(b * SEQ + qt * 128)) * LDQP + h * KP;
    const __half* Kg = kp + ((size_t)b * SEQ) * LDQP + h * KP;
    const __half* Vg = ckv + ((size_t)b * SEQ) * ldckv;

#pragma unroll
    for (int i = 0; i < 10; i++) {
        int idx = tid + i * 256;
        int r = idx / 20, c = idx % 20;
        cp16(smem_u32(Qs + r * FAQ_LD + c * 8), Qg + (size_t)r * LDQP + c * 8);
    }
#pragma unroll
    for (int i = 0; i < 10; i++) {
        int idx = tid + i * 256;
        int r = idx / 20, c = idx % 20;
        cp16(smem_u32(Ks + r * FAQ_LD + c * 8), Kg + (size_t)r * LDQP + c * 8);
    }
#pragma unroll
    for (int i = 0; i < 8; i++) {
        int idx = tid + i * 256;
        int r = idx / 16, c = idx % 16;
        cp16(smem_u32(Vs + r * FAV_LD + c * 8), Vg + (size_t)r * ldckv + c * 8);
    }
    CP_COMMIT();

    uint32_t qAddr = smem_u32(Qs + (warp * 16 + (lane & 15)) * FAQ_LD + (lane >> 4) * 8);
    uint32_t kAddr[2][8], vAddr[2][8];
#pragma unroll
    for (int s = 0; s < 2; s++) {
#pragma unroll
        for (int nb = 0; nb < 8; nb++) {
            kAddr[s][nb] = smem_u32(Ks + s * 128 * FAQ_LD
                + (nb * 16 + (lane & 7) + ((lane >> 4) & 1) * 8) * FAQ_LD
                + ((lane >> 3) & 1) * 8);
            vAddr[s][nb] = smem_u32(Vs + s * 128 * FAV_LD
                + (lane & 15) * FAV_LD
                + nb * 16 + ((lane >> 4) << 3));
        }
    }

    float oacc[16][4];
#pragma unroll
    for (int j = 0; j < 16; j++)
#pragma unroll
        for (int i = 0; i < 4; i++) oacc[j][i] = 0.0f;
    float m0 = -1e30f, m1 = -1e30f, l0 = 0.0f, l1 = 0.0f;

    for (int kt = 0; kt < 16; kt++) {
        CP_WAIT(0);
        __syncthreads();
        if (kt + 1 < 16) {
            int s = (kt + 1) & 1;
            const __half* Kt = Kg + (size_t)(kt + 1) * 128 * LDQP;
            const __half* Vt = Vg + (size_t)(kt + 1) * 128 * ldckv;
#pragma unroll
            for (int i = 0; i < 10; i++) {
                int idx = tid + i * 256;
                int r = idx / 20, c = idx % 20;
                cp16(smem_u32(Ks + s * 128 * FAQ_LD + r * FAQ_LD + c * 8),
                     Kt + (size_t)r * LDQP + c * 8);
            }
#pragma unroll
            for (int i = 0; i < 8; i++) {
                int idx = tid + i * 256;
                int r = idx / 16, c = idx % 16;
                cp16(smem_u32(Vs + s * 128 * FAV_LD + r * FAV_LD + c * 8),
                     Vt + (size_t)r * ldckv + c * 8);
            }
            CP_COMMIT();
        }

        int s = kt & 1;
        float sacc[16][4];
#pragma unroll
        for (int j = 0; j < 16; j++)
#pragma unroll
            for (int i = 0; i < 4; i++) sacc[j][i] = 0.0f;
#pragma unroll
        for (int ks = 0; ks < 10; ks++) {
            uint32_t a[4];
            ldm_x4(a, qAddr + ks * 32);
#pragma unroll
            for (int nb = 0; nb < 8; nb++) {
                uint32_t bb[4];
                ldm_x4(bb, kAddr[s][nb] + ks * 32);
                mma_f16(sacc[2 * nb],     a, bb[0], bb[1]);
                mma_f16(sacc[2 * nb + 1], a, bb[2], bb[3]);
            }
        }
        float mx0 = -1e30f, mx1 = -1e30f;
#pragma unroll
        for (int j = 0; j < 16; j++) {
            sacc[j][0] *= scale; sacc[j][1] *= scale;
            sacc[j][2] *= scale; sacc[j][3] *= scale;
            mx0 = fmaxf(mx0, fmaxf(sacc[j][0], sacc[j][1]));
            mx1 = fmaxf(mx1, fmaxf(sacc[j][2], sacc[j][3]));
        }
        mx0 = fmaxf(mx0, __shfl_xor_sync(0xFFFFFFFF, mx0, 1));
        mx0 = fmaxf(mx0, __shfl_xor_sync(0xFFFFFFFF, mx0, 2));
        mx1 = fmaxf(mx1, __shfl_xor_sync(0xFFFFFFFF, mx1, 1));
        mx1 = fmaxf(mx1, __shfl_xor_sync(0xFFFFFFFF, mx1, 2));
        float mn0 = fmaxf(m0, mx0), mn1 = fmaxf(m1, mx1);
        float f0 = __expf(m0 - mn0), f1 = __expf(m1 - mn1);
        m0 = mn0; m1 = mn1;
        float ts0 = 0.0f, ts1 = 0.0f;
#pragma unroll
        for (int j = 0; j < 16; j++) {
            sacc[j][0] = __expf(sacc[j][0] - m0);
            sacc[j][1] = __expf(sacc[j][1] - m0);
            sacc[j][2] = __expf(sacc[j][2] - m1);
            sacc[j][3] = __expf(sacc[j][3] - m1);
            ts0 += sacc[j][0] + sacc[j][1];
            ts1 += sacc[j][2] + sacc[j][3];
        }
        ts0 += __shfl_xor_sync(0xFFFFFFFF, ts0, 1);
        ts0 += __shfl_xor_sync(0xFFFFFFFF, ts0, 2);
        ts1 += __shfl_xor_sync(0xFFFFFFFF, ts1, 1);
        ts1 += __shfl_xor_sync(0xFFFFFFFF, ts1, 2);
        l0 = l0 * f0 + ts0;
        l1 = l1 * f1 + ts1;
#pragma unroll
        for (int j = 0; j < 16; j++) {
            oacc[j][0] *= f0; oacc[j][1] *= f0;
            oacc[j][2] *= f1; oacc[j][3] *= f1;
        }
#pragma unroll
        for (int kb = 0; kb < 8; kb++) {
            uint32_t a[4];
            a[0] = packh2(sacc[2 * kb][0],     sacc[2 * kb][1]);
            a[1] = packh2(sacc[2 * kb][2],     sacc[2 * kb][3]);
            a[2] = packh2(sacc[2 * kb + 1][0], sacc[2 * kb + 1][1]);
            a[3] = packh2(sacc[2 * kb + 1][2], sacc[2 * kb + 1][3]);
            uint32_t voff = (uint32_t)(kb * 16 * FAV_LD * 2);
#pragma unroll
            for (int nb = 0; nb < 8; nb++) {
                uint32_t bb[4];
                ldm_x4t(bb, vAddr[s][nb] + voff);
                mma_f16(oacc[2 * nb],     a, bb[0], bb[1]);
                mma_f16(oacc[2 * nb + 1], a, bb[2], bb[3]);
            }
        }
    }

    float il0 = 1.0f / l0, il1 = 1.0f / l1;
    int rowg = b * SEQ + qt * 128 + warp * 16;
#pragma unroll
    for (int j = 0; j < 16; j++) {
        int col = h * 128 + j * 8 + tig * 2;
        *reinterpret_cast<__half2*>(u + (size_t)(rowg + qid) * (NH * DKV) + col)
            = __floats2half2_rn(oacc[j][0] * il0, oacc[j][1] * il0);
        *reinterpret_cast<__half2*>(u + (size_t)(rowg + qid + 8) * (NH * DKV) + col)
            = __floats2half2_rn(oacc[j][2] * il1, oacc[j][3] * il1);
    }
}

// ============================================================================
// small kernels
// ============================================================================
__global__ __launch_bounds__(256)
void transpose_f2h(const float* __restrict__ in, __half* __restrict__ out, int ldi, int ldo)
{
    __shared__ float t[32][33];
    int bx = blockIdx.x * 32, by = blockIdx.y * 32;
    int tx = threadIdx.x & 31, ty = threadIdx.x >> 5;
#pragma unroll
    for (int i = 0; i < 4; i++)
        t[ty + 8 * i][tx] = in[(size_t)(by + ty + 8 * i) * ldi + bx + tx];
    __syncthreads();
#pragma unroll
    for (int i = 0; i < 4; i++)
        out[(size_t)(bx + ty + 8 * i) * ldo + by + tx] = __float2half_rn(t[tx][ty + 8 * i]);
}

__global__ void f2h_k(const float* __restrict__ in, __half* __restrict__ out, int n4)
{
    int i = blockIdx.x * blockDim.x + threadIdx.x;
    if (i >= n4) return;
    float4 v = *reinterpret_cast<const float4*>(in + (size_t)i * 4);
    __half2 a = __floats2half2_rn(v.x, v.y);
    __half2 b = __floats2half2_rn(v.z, v.w);
    *reinterpret_cast<uint2*>(out + (size_t)i * 4) = make_uint2(
        *reinterpret_cast<uint32_t*>(&a), *reinterpret_cast<uint32_t*>(&b));
}

__global__ void pad_w_k(const float* __restrict__ in, __half* __restrict__ out)
{
    int idx = blockIdx.x * blockDim.x + threadIdx.x;
    if (idx >= DKV * NH * DH) return;
    int i = idx / (NH * DH);
    int c = idx % (NH * DH);
    int h = c / DH, d = c % DH;
    float v = (d < SPLITD) ? in[(size_t)i * (NH * SPLITD) + h * SPLITD + d] : 0.0f;
    out[idx] = __float2half_rn(v);
}

// bias2 = outb + buv @ Wout : 2D-parallel, coalesced, atomic accumulate
__global__ void bias2init_k(const float* __restrict__ outb, float* __restrict__ o)
{
    int n = blockIdx.x * 256 + threadIdx.x;
    if (n < DM) o[n] = outb[n];
}
__global__ __launch_bounds__(256)
void bias2p_k(const float* __restrict__ outw, const float* __restrict__ buv,
              float* __restrict__ o)
{
    int n = blockIdx.x * 256 + threadIdx.x;
    int m0 = blockIdx.y * 256;
    float s = 0.0f;
#pragma unroll 4
    for (int i = 0; i < 256; i++)
        s += buv[m0 + i] * outw[(size_t)(m0 + i) * DM + n];
    atomicAdd(&o[n], s);
}

__global__ void bqrow_k(const float* __restrict__ buq, const float* __restrict__ wuk,
                        float* __restrict__ o)
{
    int idx = blockIdx.x * blockDim.x + threadIdx.x;
    if (idx >= NH * DKV) return;
    int h = idx / DKV, n = idx % DKV;
    float s = 0.0f;
    for (int d = 0; d < SPLITD; d++)
        s += buq[h * SPLITD + d] * wuk[(size_t)n * (NH * SPLITD) + h * SPLITD + d];
    o[idx] = s;
}

__global__ void wh_k(const float* __restrict__ wuq, const float* __restrict__ buk,
                     const float* __restrict__ buq, float* __restrict__ o, float* __restrict__ sc)
{
    int idx = blockIdx.x * blockDim.x + threadIdx.x;
    if (idx >= NH * DKV) return;
    int h = idx / DKV, k = idx % DKV;
    float s = 0.0f;
    for (int d = 0; d < SPLITD; d++)
        s += wuq[(size_t)k * (NH * SPLITD) + h * SPLITD + d] * buk[h * SPLITD + d];
    o[idx] = s;
    if (k == 0) {
        float c = 0.0f;
        for (int d = 0; d < SPLITD; d++) c += buq[h * SPLITD + d] * buk[h * SPLITD + d];
        sc[h] = c;
    }
}

__global__ void bias_cat2(const float* a, const float* b, float* o, int n1, int n2)
{
    int i = blockIdx.x * blockDim.x + threadIdx.x;
    if (i >= n1 + n2) return;
    o[i] = (i < n1) ? a[i] : b[i - n1];
}

// split-K reduce: ckvcq_half = p0+p1+bdd ; ckv float output for cols<128
__global__ void spk_reduce(const float* __restrict__ p0, const float* __restrict__ p1,
                           const float* __restrict__ bdd,
                           __half* __restrict__ ckvcq, float* __restrict__ ckvf)
{
    int i = blockIdx.x * blockDim.x + threadIdx.x;
    if (i >= MROWS * NDD) return;
    int m = i / NDD, c = i % NDD;
    float s = p0[i] + p1[i] + bdd[c];
    ckvcq[i] = __float2half_rn(s);
    if (c < DKV) ckvf[(size_t)m * DKV + c] = s;
}

__global__ void sq_k(const __half* __restrict__ cq, int ldcq, const float* __restrict__ wh,
                     const float* __restrict__ scst, __half* __restrict__ qp)
{
    int idx = blockIdx.x * blockDim.x + threadIdx.x;
    if (idx >= MROWS * NH) return;
    int m = idx / NH, h = idx % NH;
    float s = scst[h];
    for (int k = 0; k < DKV; k++)
        s += __half2float(cq[(size_t)m * ldcq + k]) * wh[h * DKV + k];
    qp[(size_t)m * LDQP + h * KP + 144] = __float2half_rn(s);
}

__global__ void qppad_k(__half* __restrict__ qp)
{
    int idx = blockIdx.x * blockDim.x + threadIdx.x;
    if (idx >= MROWS * NH) return;
    int m = idx / NH, h = idx % NH;
    __half* p = qp + (size_t)m * LDQP + h * KP;
    for (int c = 145; c < KP; c++) p[c] = __float2half_rn(0.0f);
}

__global__ void kpfill_k(const __half* __restrict__ ckv, int ldckv, __half* __restrict__ kp)
{
    int idx = blockIdx.x * blockDim.x + threadIdx.x;
    int total = MROWS * NH * 18;
    if (idx >= total) return;
    int c = idx % 18;
    int mh = idx / 18;
    int m = mh / NH, h = mh % NH;
    __half* p = kp + (size_t)m * LDQP + h * KP;
    if (c < 16) {
        uint4 v = *reinterpret_cast<const uint4*>(ckv + (size_t)m * ldckv + c * 8);
        *reinterpret_cast<uint4*>(p + c * 8) = v;
    } else if (c == 16) {
        __half z = __float2half_rn(0.0f);
        __half vals[8] = { __float2half_rn(1.0f), z, z, z, z, z, z, z };
        *reinterpret_cast<uint4*>(p + 144) = *reinterpret_cast<uint4*>(vals);
    } else {
        __half z = __float2half_rn(0.0f);
        __half vals[8] = { z, z, z, z, z, z, z, z };
        *reinterpret_cast<uint4*>(p + 152) = *reinterpret_cast<uint4*>(vals);
    }
}

__global__ void rope_k(const __half* __restrict__ pre, __half* __restrict__ dst,
                       float* __restrict__ rout)
{
    int idx = blockIdx.x * blockDim.x + threadIdx.x;
    if (idx >= MROWS * DKV) return;
    int m = idx >> 7;
    int c = idx & 127;
    int h = c >> 4;
    int d = c & 15;
    int j = d & 7;
    int s = m & (SEQ - 1);
    float t = (float)s * (1.0f / 40.0f);
    float invf = __expf(-(float)j * 0.86346941f);  // ln(1000)/8
    float ang = t * invf;
    float sn, cs;
    sincosf(ang, &sn, &cs);
    float x = __half2float(pre[idx]);
    float p = __half2float(pre[(m << 7) + (h << 4) + ((d < 8) ? d + 8 : d - 8)]);
    float val = x * cs + ((d < 8) ? -p : p) * sn;
    dst[(size_t)m * LDQP + h * KP + 128 + d] = __float2half_rn(val);
    if (rout) rout[idx] = val;
}

// ============================================================================
// host launcher — main chain on default stream, weight-prep forked to a side
// stream within graph capture (event fork/join).
// ============================================================================
extern "C" void kernel_launch(void* const* d_in, const int* in_sizes, int n_in,
                              void* d_out, int out_size)
{
    const float* h    = (const float*)d_in[0];
    const float* Wdkv = (const float*)d_in[1];
    const float* bdkv = (const float*)d_in[2];
    const float* Wdq  = (const float*)d_in[3];
    const float* bdq  = (const float*)d_in[4];
    const float* Wuk  = (const float*)d_in[5];
    const float* buk  = (const float*)d_in[6];
    const float* Wuv  = (const float*)d_in[7];
    const float* buv  = (const float*)d_in[8];
    const float* Wuq  = (const float*)d_in[9];
    const float* buq  = (const float*)d_in[10];
    const float* Wqr  = (const float*)d_in[11];
    const float* bqr  = (const float*)d_in[12];
    const float* Wkr  = (const float*)d_in[13];
    const float* bkr  = (const float*)d_in[14];
    const float* outw = (const float*)d_in[15];
    const float* outb = (const float*)d_in[16];
    float* out = (float*)d_out;

    __half *hh, *ckvcq, *krqrp, *qp, *kp, *u;
    __half *wdd, *wkq, *wt_out, *wuv_h, *wuq_p, *wuk_p, *mt, *w2t;
    float *ckvf, *part, *bias2, *bqrow, *wh, *scst, *bdd, *bkq;
    cudaGetSymbolAddress((void**)&hh,    g_hh);
    cudaGetSymbolAddress((void**)&ckvcq, g_ckvcq);
    cudaGetSymbolAddress((void**)&krqrp, g_krqrp);
    cudaGetSymbolAddress((void**)&qp,    g_qp);
    cudaGetSymbolAddress((void**)&kp,    g_kp);
    cudaGetSymbolAddress((void**)&u,     g_u);
    cudaGetSymbolAddress((void**)&ckvf,  g_ckvf);
    cudaGetSymbolAddress((void**)&part,  g_part);
    cudaGetSymbolAddress((void**)&wdd,   g_wdd);
    cudaGetSymbolAddress((void**)&wkq,   g_wkq);
    cudaGetSymbolAddress((void**)&wt_out, g_wt_out);
    cudaGetSymbolAddress((void**)&wuv_h,  g_wuv_h);
    cudaGetSymbolAddress((void**)&wuq_p,  g_wuq_p);
    cudaGetSymbolAddress((void**)&wuk_p,  g_wuk_p);
    cudaGetSymbolAddress((void**)&mt,     g_mt);
    cudaGetSymbolAddress((void**)&w2t,    g_w2t);
    cudaGetSymbolAddress((void**)&bias2,  g_bias2);
    cudaGetSymbolAddress((void**)&bqrow,  g_bqrow);
    cudaGetSymbolAddress((void**)&wh,     g_wh);
    cudaGetSymbolAddress((void**)&scst,   g_sconst);
    cudaGetSymbolAddress((void**)&bdd,    g_bdd);
    cudaGetSymbolAddress((void**)&bkq,    g_bkq);

    cudaFuncSetAttribute(flash_k, cudaFuncAttributeMaxDynamicSharedMemorySize, FA_SMEM);

    const size_t out_ckv_off  = (size_t)MROWS * DM;
    const size_t out_krot_off = out_ckv_off + (size_t)MROWS * DKV;
    bool full_out = (size_t)out_size >= out_krot_off + (size_t)MROWS * DKV;
    float* ckv_dst = full_out ? (out + out_ckv_off) : ckvf;

    dim3 b256(256);
    dim3 blk(256);
    auto grd = [](int M, int N, int Z) { return dim3((unsigned)(N / 128), (unsigned)(M / 128), (unsigned)Z); };

    // ---- fork side stream inside capture ----
    cudaStream_t side;
    cudaStreamCreateWithFlags(&side, cudaStreamNonBlocking);
    cudaEvent_t evFork, evA, evB;
    cudaEventCreateWithFlags(&evFork, cudaEventDisableTiming);
    cudaEventCreateWithFlags(&evA,    cudaEventDisableTiming);
    cudaEventCreateWithFlags(&evB,    cudaEventDisableTiming);
    cudaEventRecord(evFork, 0);
    cudaStreamWaitEvent(side, evFork, 0);

    // ---- side chain: weight prep independent of h ----
    pad_w_k<<<(DKV * NH * DH + 255) / 256, 256, 0, side>>>(Wuq, wuq_p);
    pad_w_k<<<(DKV * NH * DH + 255) / 256, 256, 0, side>>>(Wuk, wuk_p);
    hgemm<<<grd(DKV, DKV, NH), blk, 0, side>>>(wuk_p, wuq_p, nullptr, mt, nullptr,
        DKV, DKV, DH, NH*DH, NH*DH, DKV, DKV, 0, 1.0f,
        0, DH, 0, DH, 0, DKV*DKV, 0, NH);
    bqrow_k<<<(NH * DKV + 255) / 256, 256, 0, side>>>(buq, Wuk, bqrow);
    wh_k<<<(NH * DKV + 255) / 256, 256, 0, side>>>(Wuq, buk, buq, wh, scst);
    cudaEventRecord(evA, side);   // mt, bqrow, wh, sconst ready

    f2h_k<<<(DKV * DM / 4 + 255) / 256, 256, 0, side>>>(Wuv, wuv_h, DKV * DM / 4);
    transpose_f2h<<<dim3(DM/32, DM/32), b256, 0, side>>>(outw, wt_out, DM, DM);
    hgemm<<<grd(DM, DKV, NH), blk, 0, side>>>(wt_out, wuv_h, nullptr, w2t, nullptr,
        DM, DKV, DH, DM, DM, NH*DKV, NH*DKV, 0, 1.0f,
        0, DH, 0, DH, 0, DKV, 0, NH);
    bias2init_k<<<DM / 256, 256, 0, side>>>(outb, bias2);
    bias2p_k<<<dim3(DM / 256, DM / 256), 256, 0, side>>>(outw, buv, bias2);
    cudaEventRecord(evB, side);   // w2t, bias2 ready

    // ---- main chain (default stream) ----
    f2h_k<<<((size_t)MROWS * DM / 4 + 255) / 256, 256>>>(h, hh, MROWS * DM / 4);
    transpose_f2h<<<dim3(DKV/32, DM/32), b256>>>(Wdkv, wdd,                 DKV, DM);
    transpose_f2h<<<dim3(DKV/32, DM/32), b256>>>(Wdq,  wdd + (size_t)DKV*DM, DKV, DM);
    transpose_f2h<<<dim3(DKV/32, DKV/32), b256>>>(Wkr, wkq,                 DKV, DKV);
    transpose_f2h<<<dim3(DKV/32, DKV/32), b256>>>(Wqr, wkq + DKV*DKV,       DKV, DKV);
    bias_cat2<<<(NDD + 255) / 256, 256>>>(bdkv, bdq, bdd, DKV, DKV);
    bias_cat2<<<(2 * DKV + 255) / 256, 256>>>(bkr, bqr, bkq, DKV, DKV);

    // 1) merged down projection with split-K; reduce adds bias, emits outputs
    hgemm<<<grd(MROWS, NDD, 2), blk>>>(hh, wdd, part, nullptr, nullptr,
        MROWS, NDD, DM/2, DM, DM, NDD, NDD, NDD, 1.0f,
        0, DM/2, 0, DM/2, 0, (long long)MROWS * NDD, 0, 2);
    spk_reduce<<<(MROWS * NDD + 255) / 256, 256>>>(part, part + (size_t)MROWS * NDD,
        bdd, ckvcq, ckv_dst);

    // 2) merged rotary pre-projections
    hgemm<<<grd(MROWS, DKV, 2), blk>>>(ckvcq, wkq, nullptr, krqrp, bkq,
        MROWS, DKV, DKV, NDD, DKV, DKV, DKV, 0, 1.0f,
        0, DKV, 0, DKV*DKV, 0, (long long)MROWS*DKV, DKV, 2);

    // rope + kpfill (don't need side results)
    rope_k<<<(MROWS * DKV + 255) / 256, 256>>>(krqrp + (size_t)MROWS * DKV, qp, nullptr);
    rope_k<<<(MROWS * DKV + 255) / 256, 256>>>(krqrp, kp,
        full_out ? (out + out_krot_off) : nullptr);
    kpfill_k<<<(MROWS * NH * 18 + 255) / 256, 256>>>(ckvcq, NDD, kp);

    // join A: need mt, bqrow, wh, sconst
    cudaStreamWaitEvent(0, evA, 0);

    // 3) q-tilde
    hgemm<<<grd(MROWS, DKV, NH), blk>>>(ckvcq + DKV, mt, nullptr, qp, bqrow,
        MROWS, DKV, DKV, NDD, DKV, LDQP, LDQP, 0, 1.0f,
        0, 0, 0, DKV*DKV, 0, KP, DKV, NH);
    sq_k<<<(MROWS * NH + 255) / 256, 256>>>(ckvcq + DKV, NDD, wh, scst, qp);
    qppad_k<<<(MROWS * NH + 255) / 256, 256>>>(qp);

    // 5) fused flash attention -> u
    float inv_sqrt = 1.0f / sqrtf((float)DH);
    flash_k<<<dim3(SEQ/128, BATCH*NH), blk, FA_SMEM>>>(qp, kp, ckvcq, NDD, u, inv_sqrt);

    // join B: need w2t, bias2
    cudaStreamWaitEvent(0, evB, 0);

    // 6) out = u @ w2t^T + bias2
    hgemm<<<grd(MROWS, DM, 1), blk>>>(u, w2t, out, nullptr, bias2,
        MROWS, DM, NH*DKV, NH*DKV, NH*DKV, DM, DM, DM, 1.0f, 0,0,0,0,0,0,0, 1);

    cudaEventDestroy(evFork);
    cudaEventDestroy(evA);
    cudaEventDestroy(evB);
    cudaStreamDestroy(side);
}

// round 15
// speedup vs baseline: 2.1165x; 1.1953x over previous
#include <cuda_runtime.h>
#include <cuda_fp16.h>
#include <math.h>
#include <stdint.h>

// ---------------- problem constants ----------------
#define BATCH 2
#define SEQ   2048
#define DM    5120
#define NH    8
#define DH    640
#define DR    16
#define SPLITD 624
#define DKV   128
#define MROWS (BATCH*SEQ)        // 4096
#define KP    160                // per-head score K-dim: [128 ckv |16 rope |1 bias |15 pad]
#define LDQP  (NH*KP)            // 1280
#define NDD   256                // merged down-proj N: [ckv|cq]

// ---------------- scratch (device globals; no allocs allowed) ----------------
__device__ __align__(16) __half g_hh   [(size_t)MROWS*DM];
__device__ __align__(16) __half g_ckvcq[(size_t)MROWS*NDD];   // [ckv(0:128) | cq(128:256)]
__device__ __align__(16) __half g_krqrp[2*MROWS*DKV];          // [krp | qrp]
__device__ __align__(16) __half g_qp   [(size_t)MROWS*LDQP];
__device__ __align__(16) __half g_kp   [(size_t)MROWS*LDQP];
__device__ __align__(16) __half g_u    [(size_t)MROWS*NH*DKV]; // [4096,1024]
__device__ __align__(16) float  g_ckvf [MROWS*DKV];
__device__ __align__(16) float  g_part [2*(size_t)MROWS*NDD];  // split-K partials
// weights
__device__ __align__(16) __half g_wdd  [(size_t)NDD*DM];       // [wt_dkv; wt_dq] [256,5120]
__device__ __align__(16) __half g_wkq  [2*DKV*DKV];            // [wt_kr; wt_qr]
__device__ __align__(16) __half g_wt_out[(size_t)DM*DM];       // Wout^T [DM, NH*DH]
__device__ __align__(16) __half g_wuv_h [DKV*DM];
__device__ __align__(16) __half g_wuq_p [DKV*NH*DH];           // zero-padded 624->640
__device__ __align__(16) __half g_wuk_p [DKV*NH*DH];
__device__ __align__(16) __half g_mt    [NH*DKV*DKV];          // Mt_h = Wuk_h Wuq_h^T
__device__ __align__(16) __half g_w2t   [(size_t)DM*NH*DKV];   // [5120,1024]
__device__ __align__(16) float  g_bias2 [DM];
__device__ __align__(16) float  g_bqrow [NH*DKV];
__device__ __align__(16) float  g_wh    [NH*DKV];
__device__ __align__(16) float  g_sconst[NH];
__device__ __align__(16) float  g_bdd   [NDD];
__device__ __align__(16) float  g_bkq   [2*DKV];

// ---------------- PTX helpers ----------------
__device__ __forceinline__ uint32_t smem_u32(const void* p) {
    uint32_t a;
    asm("{ .reg .u64 t; cvta.to.shared.u64 t, %1; cvt.u32.u64 %0, t; }" : "=r"(a) : "l"(p));
    return a;
}
__device__ __forceinline__ void cp16(uint32_t dst, const void* src) {
    asm volatile("cp.async.cg.shared.global [%0], [%1], 16;" :: "r"(dst), "l"(src) : "memory");
}
#define CP_COMMIT() asm volatile("cp.async.commit_group;" ::: "memory")
#define CP_WAIT(n)  asm volatile("cp.async.wait_group %0;" :: "n"(n) : "memory")

__device__ __forceinline__ void ldm_x4(uint32_t* r, uint32_t addr) {
    asm volatile("ldmatrix.sync.aligned.m8n8.x4.shared.b16 {%0,%1,%2,%3}, [%4];"
                 : "=r"(r[0]), "=r"(r[1]), "=r"(r[2]), "=r"(r[3]) : "r"(addr));
}
__device__ __forceinline__ void ldm_x4t(uint32_t* r, uint32_t addr) {
    asm volatile("ldmatrix.sync.aligned.m8n8.x4.trans.shared.b16 {%0,%1,%2,%3}, [%4];"
                 : "=r"(r[0]), "=r"(r[1]), "=r"(r[2]), "=r"(r[3]) : "r"(addr));
}
__device__ __forceinline__ void mma_f16(float* c, const uint32_t* a, uint32_t b0, uint32_t b1) {
    asm volatile("mma.sync.aligned.m16n8k16.row.col.f32.f16.f16.f32 "
                 "{%0,%1,%2,%3}, {%4,%5,%6,%7}, {%8,%9}, {%0,%1,%2,%3};"
                 : "+f"(c[0]), "+f"(c[1]), "+f"(c[2]), "+f"(c[3])
                 : "r"(a[0]), "r"(a[1]), "r"(a[2]), "r"(a[3]), "r"(b0), "r"(b1));
}
__device__ __forceinline__ uint32_t packh2(float x, float y) {
    __half2 h = __floats2half2_rn(x, y);
    return *reinterpret_cast<uint32_t*>(&h);
}

// ============================================================================
// fp16 mma.sync GEMM: C = alpha*A*B^T + bias. 128x128 tile, BK=32, 2-stage.
// Cf written only for cols < cfN (ld ldcf); Ch full (ld ldc).
// ============================================================================
#define SPADH 40

__global__ __launch_bounds__(256)
void hgemm(const __half* __restrict__ A, const __half* __restrict__ B,
           float* __restrict__ Cf, __half* __restrict__ Ch,
           const float* __restrict__ bias,
           int M, int N, int K, int lda, int ldb, int ldc, int ldcf, int cfN,
           float alpha,
           long long sAhi, long long sAlo, long long sBhi, long long sBlo,
           long long sChi, long long sClo, long long sBiasLo, int zdiv)
{
    __shared__ __half As[2][128][SPADH];
    __shared__ __half Bs[2][128][SPADH];

    int tid  = threadIdx.x;
    int warp = tid >> 5;
    int lane = tid & 31;
    int wr = warp >> 1;
    int wc = warp & 1;
    int qid = lane >> 2;
    int tig = lane & 3;

    int z  = blockIdx.z;
    int zh = z / zdiv, zl = z % zdiv;
    A += zh * sAhi + zl * sAlo;
    B += zh * sBhi + zl * sBlo;
    long long cofs = zh * sChi + zl * sClo;
    if (Cf) Cf += cofs;
    if (Ch) Ch += cofs;
    if (bias) bias += zl * sBiasLo;

    int row0 = blockIdx.y * 128, col0 = blockIdx.x * 128;
    const __half* Ab = A + (size_t)row0 * lda;
    const __half* Bb = B + (size_t)col0 * ldb;

    int r0 = tid >> 2, cc = (tid & 3) * 8;
    int r1 = r0 + 64;
    uint32_t dA0[2], dA1[2], dB0[2], dB1[2];
#pragma unroll
    for (int s = 0; s < 2; s++) {
        dA0[s] = smem_u32(&As[s][r0][cc]);
        dA1[s] = smem_u32(&As[s][r1][cc]);
        dB0[s] = smem_u32(&Bs[s][r0][cc]);
        dB1[s] = smem_u32(&Bs[s][r1][cc]);
    }
    uint32_t aAddr[2][2], bAddr[2][4];
#pragma unroll
    for (int s = 0; s < 2; s++) {
#pragma unroll
        for (int mi = 0; mi < 2; mi++)
            aAddr[s][mi] = smem_u32(&As[s][wr * 32 + mi * 16 + (lane & 15)][(lane >> 4) * 8]);
#pragma unroll
        for (int np = 0; np < 4; np++)
            bAddr[s][np] = smem_u32(&Bs[s][wc * 64 + np * 16 + (lane & 7) + ((lane >> 4) & 1) * 8]
                                        [((lane >> 3) & 1) * 8]);
    }

    float acc[2][8][4];
#pragma unroll
    for (int mi = 0; mi < 2; mi++)
#pragma unroll
        for (int ni = 0; ni < 8; ni++)
#pragma unroll
            for (int i = 0; i < 4; i++) acc[mi][ni][i] = 0.0f;

    int T = K >> 5;

    cp16(dA0[0], Ab + (size_t)r0 * lda + cc);
    cp16(dA1[0], Ab + (size_t)r1 * lda + cc);
    cp16(dB0[0], Bb + (size_t)r0 * ldb + cc);
    cp16(dB1[0], Bb + (size_t)r1 * ldb + cc);
    CP_COMMIT();

    for (int t = 0; t < T; t++) {
        if (t + 1 < T) {
            int s = (t + 1) & 1;
            int k0 = (t + 1) * 32;
            cp16(dA0[s], Ab + (size_t)r0 * lda + k0 + cc);
            cp16(dA1[s], Ab + (size_t)r1 * lda + k0 + cc);
            cp16(dB0[s], Bb + (size_t)r0 * ldb + k0 + cc);
            cp16(dB1[s], Bb + (size_t)r1 * ldb + k0 + cc);
            CP_COMMIT();
            CP_WAIT(1);
        } else {
            CP_WAIT(0);
        }
        __syncthreads();

        int s = t & 1;
#pragma unroll
        for (int ks = 0; ks < 2; ks++) {
            uint32_t koff = ks * 32;
            uint32_t a[2][4], b[16];
#pragma unroll
            for (int mi = 0; mi < 2; mi++) ldm_x4(a[mi], aAddr[s][mi] + koff);
#pragma unroll
            for (int np = 0; np < 4; np++) ldm_x4(b + np * 4, bAddr[s][np] + koff);
#pragma unroll
            for (int ni = 0; ni < 8; ni++) {
                uint32_t b0 = b[(ni >> 1) * 4 + (ni & 1) * 2];
                uint32_t b1 = b[(ni >> 1) * 4 + (ni & 1) * 2 + 1];
                mma_f16(acc[0][ni], a[0], b0, b1);
                mma_f16(acc[1][ni], a[1], b0, b1);
            }
        }
        __syncthreads();
    }

#pragma unroll
    for (int mi = 0; mi < 2; mi++) {
        int rg = row0 + wr * 32 + mi * 16 + qid;
#pragma unroll
        for (int ni = 0; ni < 8; ni++) {
            int cg = col0 + wc * 64 + ni * 8 + tig * 2;
            float bx = 0.0f, by = 0.0f;
            if (bias) { bx = bias[cg]; by = bias[cg + 1]; }
            float o0 = alpha * acc[mi][ni][0] + bx;
            float o1 = alpha * acc[mi][ni][1] + by;
            float o2 = alpha * acc[mi][ni][2] + bx;
            float o3 = alpha * acc[mi][ni][3] + by;
            if (Cf && cg < cfN) {
                *reinterpret_cast<float2*>(Cf + (size_t)rg * ldcf + cg)       = make_float2(o0, o1);
                *reinterpret_cast<float2*>(Cf + (size_t)(rg + 8) * ldcf + cg) = make_float2(o2, o3);
            }
            if (Ch) {
                *reinterpret_cast<__half2*>(Ch + (size_t)rg * ldc + cg)       = __floats2half2_rn(o0, o1);
                *reinterpret_cast<__half2*>(Ch + (size_t)(rg + 8) * ldc + cg) = __floats2half2_rn(o2, o3);
            }
        }
    }
}

// ============================================================================
// flash attention: per CTA = (q-tile 128 rows, one (b,h)). online softmax.
// ============================================================================
#define FAQ_LD 168
#define FAV_LD 136
#define FA_SMEM ((3*128*FAQ_LD + 2*128*FAV_LD) * 2)   // 198656 B

__global__ __launch_bounds__(256, 1)
void flash_k(const __half* __restrict__ qp, const __half* __restrict__ kp,
             const __half* __restrict__ ckv, int ldckv,
             __half* __restrict__ u, float scale)
{
    extern __shared__ __half sm[];
    __half* Qs = sm;
    __half* Ks = sm + 128 * FAQ_LD;
    __half* Vs = sm + 3 * 128 * FAQ_LD;

    int tid = threadIdx.x;
    int warp = tid >> 5, lane = tid & 31;
    int qid = lane >> 2, tig = lane & 3;

    int qt = blockIdx.x;
    int z  = blockIdx.y;
    int b = z >> 3, h = z & 7;

    const __half* Qg = qp + ((size_t)(b * SEQ + qt * 128)) * LDQP + h * KP;
    const __half* Kg = kp + ((size_t)b * SEQ) * LDQP + h * KP;
    const __half* Vg = ckv + ((size_t)b * SEQ) * ldckv;

#pragma unroll
    for (int i = 0; i < 10; i++) {
        int idx = tid + i * 256;
        int r = idx / 20, c = idx % 20;
        cp16(smem_u32(Qs + r * FAQ_LD + c * 8), Qg + (size_t)r * LDQP + c * 8);
    }
#pragma unroll
    for (int i = 0; i < 10; i++) {
        int idx = tid + i * 256;
        int r = idx / 20, c = idx % 20;
        cp16(smem_u32(Ks + r * FAQ_LD + c * 8), Kg + (size_t)r * LDQP + c * 8);
    }
#pragma unroll
    for (int i = 0; i < 8; i++) {
        int idx = tid + i * 256;
        int r = idx / 16, c = idx % 16;
        cp16(smem_u32(Vs + r * FAV_LD + c * 8), Vg + (size_t)r * ldckv + c * 8);
    }
    CP_COMMIT();

    uint32_t qAddr = smem_u32(Qs + (warp * 16 + (lane & 15)) * FAQ_LD + (lane >> 4) * 8);
    uint32_t kAddr[2][8], vAddr[2][8];
#pragma unroll
    for (int s = 0; s < 2; s++) {
#pragma unroll
        for (int nb = 0; nb < 8; nb++) {
            kAddr[s][nb] = smem_u32(Ks + s * 128 * FAQ_LD
                + (nb * 16 + (lane & 7) + ((lane >> 4) & 1) * 8) * FAQ_LD
                + ((lane >> 3) & 1) * 8);
            vAddr[s][nb] = smem_u32(Vs + s * 128 * FAV_LD
                + (lane & 15) * FAV_LD
                + nb * 16 + ((lane >> 4) << 3));
        }
    }

    float oacc[16][4];
#pragma unroll
    for (int j = 0; j < 16; j++)
#pragma unroll
        for (int i = 0; i < 4; i++) oacc[j][i] = 0.0f;
    float m0 = -1e30f, m1 = -1e30f, l0 = 0.0f, l1 = 0.0f;

    for (int kt = 0; kt < 16; kt++) {
        CP_WAIT(0);
        __syncthreads();
        if (kt + 1 < 16) {
            int s = (kt + 1) & 1;
            const __half* Kt = Kg + (size_t)(kt + 1) * 128 * LDQP;
            const __half* Vt = Vg + (size_t)(kt + 1) * 128 * ldckv;
#pragma unroll
            for (int i = 0; i < 10; i++) {
                int idx = tid + i * 256;
                int r = idx / 20, c = idx % 20;
                cp16(smem_u32(Ks + s * 128 * FAQ_LD + r * FAQ_LD + c * 8),
                     Kt + (size_t)r * LDQP + c * 8);
            }
#pragma unroll
            for (int i = 0; i < 8; i++) {
                int idx = tid + i * 256;
                int r = idx / 16, c = idx % 16;
                cp16(smem_u32(Vs + s * 128 * FAV_LD + r * FAV_LD + c * 8),
                     Vt + (size_t)r * ldckv + c * 8);
            }
            CP_COMMIT();
        }

        int s = kt & 1;
        float sacc[16][4];
#pragma unroll
        for (int j = 0; j < 16; j++)
#pragma unroll
            for (int i = 0; i < 4; i++) sacc[j][i] = 0.0f;
#pragma unroll
        for (int ks = 0; ks < 10; ks++) {
            uint32_t a[4];
            ldm_x4(a, qAddr + ks * 32);
#pragma unroll
            for (int nb = 0; nb < 8; nb++) {
                uint32_t bb[4];
                ldm_x4(bb, kAddr[s][nb] + ks * 32);
                mma_f16(sacc[2 * nb],     a, bb[0], bb[1]);
                mma_f16(sacc[2 * nb + 1], a, bb[2], bb[3]);
            }
        }
        float mx0 = -1e30f, mx1 = -1e30f;
#pragma unroll
        for (int j = 0; j < 16; j++) {
            sacc[j][0] *= scale; sacc[j][1] *= scale;
            sacc[j][2] *= scale; sacc[j][3] *= scale;
            mx0 = fmaxf(mx0, fmaxf(sacc[j][0], sacc[j][1]));
            mx1 = fmaxf(mx1, fmaxf(sacc[j][2], sacc[j][3]));
        }
        mx0 = fmaxf(mx0, __shfl_xor_sync(0xFFFFFFFF, mx0, 1));
        mx0 = fmaxf(mx0, __shfl_xor_sync(0xFFFFFFFF, mx0, 2));
        mx1 = fmaxf(mx1, __shfl_xor_sync(0xFFFFFFFF, mx1, 1));
        mx1 = fmaxf(mx1, __shfl_xor_sync(0xFFFFFFFF, mx1, 2));
        float mn0 = fmaxf(m0, mx0), mn1 = fmaxf(m1, mx1);
        float f0 = __expf(m0 - mn0), f1 = __expf(m1 - mn1);
        m0 = mn0; m1 = mn1;
        float ts0 = 0.0f, ts1 = 0.0f;
#pragma unroll
        for (int j = 0; j < 16; j++) {
            sacc[j][0] = __expf(sacc[j][0] - m0);
            sacc[j][1] = __expf(sacc[j][1] - m0);
            sacc[j][2] = __expf(sacc[j][2] - m1);
            sacc[j][3] = __expf(sacc[j][3] - m1);
            ts0 += sacc[j][0] + sacc[j][1];
            ts1 += sacc[j][2] + sacc[j][3];
        }
        ts0 += __shfl_xor_sync(0xFFFFFFFF, ts0, 1);
        ts0 += __shfl_xor_sync(0xFFFFFFFF, ts0, 2);
        ts1 += __shfl_xor_sync(0xFFFFFFFF, ts1, 1);
        ts1 += __shfl_xor_sync(0xFFFFFFFF, ts1, 2);
        l0 = l0 * f0 + ts0;
        l1 = l1 * f1 + ts1;
#pragma unroll
        for (int j = 0; j < 16; j++) {
            oacc[j][0] *= f0; oacc[j][1] *= f0;
            oacc[j][2] *= f1; oacc[j][3] *= f1;
        }
#pragma unroll
        for (int kb = 0; kb < 8; kb++) {
            uint32_t a[4];
            a[0] = packh2(sacc[2 * kb][0],     sacc[2 * kb][1]);
            a[1] = packh2(sacc[2 * kb][2],     sacc[2 * kb][3]);
            a[2] = packh2(sacc[2 * kb + 1][0], sacc[2 * kb + 1][1]);
            a[3] = packh2(sacc[2 * kb + 1][2], sacc[2 * kb + 1][3]);
            uint32_t voff = (uint32_t)(kb * 16 * FAV_LD * 2);
#pragma unroll
            for (int nb = 0; nb < 8; nb++) {
                uint32_t bb[4];
                ldm_x4t(bb, vAddr[s][nb] + voff);
                mma_f16(oacc[2 * nb],     a, bb[0], bb[1]);
                mma_f16(oacc[2 * nb + 1], a, bb[2], bb[3]);
            }
        }
    }

    float il0 = 1.0f / l0, il1 = 1.0f / l1;
    int rowg = b * SEQ + qt * 128 + warp * 16;
#pragma unroll
    for (int j = 0; j < 16; j++) {
        int col = h * 128 + j * 8 + tig * 2;
        *reinterpret_cast<__half2*>(u + (size_t)(rowg + qid) * (NH * DKV) + col)
            = __floats2half2_rn(oacc[j][0] * il0, oacc[j][1] * il0);
        *reinterpret_cast<__half2*>(u + (size_t)(rowg + qid + 8) * (NH * DKV) + col)
            = __floats2half2_rn(oacc[j][2] * il1, oacc[j][3] * il1);
    }
}

// ============================================================================
// small kernels
// ============================================================================
__global__ __launch_bounds__(256)
void transpose_f2h(const float* __restrict__ in, __half* __restrict__ out, int ldi, int ldo)
{
    __shared__ float t[32][33];
    int bx = blockIdx.x * 32, by = blockIdx.y * 32;
    int tx = threadIdx.x & 31, ty = threadIdx.x >> 5;
#pragma unroll
    for (int i = 0; i < 4; i++)
        t[ty + 8 * i][tx] = in[(size_t)(by + ty + 8 * i) * ldi + bx + tx];
    __syncthreads();
#pragma unroll
    for (int i = 0; i < 4; i++)
        out[(size_t)(bx + ty + 8 * i) * ldo + by + tx] = __float2half_rn(t[tx][ty + 8 * i]);
}

__global__ void f2h_k(const float* __restrict__ in, __half* __restrict__ out, int n4)
{
    int i = blockIdx.x * blockDim.x + threadIdx.x;
    if (i >= n4) return;
    float4 v = *reinterpret_cast<const float4*>(in + (size_t)i * 4);
    __half2 a = __floats2half2_rn(v.x, v.y);
    __half2 b = __floats2half2_rn(v.z, v.w);
    *reinterpret_cast<uint2*>(out + (size_t)i * 4) = make_uint2(
        *reinterpret_cast<uint32_t*>(&a), *reinterpret_cast<uint32_t*>(&b));
}

__global__ void pad_w_k(const float* __restrict__ in, __half* __restrict__ out)
{
    int idx = blockIdx.x * blockDim.x + threadIdx.x;
    if (idx >= DKV * NH * DH) return;
    int i = idx / (NH * DH);
    int c = idx % (NH * DH);
    int h = c / DH, d = c % DH;
    float v = (d < SPLITD) ? in[(size_t)i * (NH * SPLITD) + h * SPLITD + d] : 0.0f;
    out[idx] = __float2half_rn(v);
}

// bias2 = outb + buv @ Wout : 2D-parallel, coalesced, atomic accumulate
__global__ void bias2init_k(const float* __restrict__ outb, float* __restrict__ o)
{
    int n = blockIdx.x * 256 + threadIdx.x;
    if (n < DM) o[n] = outb[n];
}
__global__ __launch_bounds__(256)
void bias2p_k(const float* __restrict__ outw, const float* __restrict__ buv,
              float* __restrict__ o)
{
    int n = blockIdx.x * 256 + threadIdx.x;
    int m0 = blockIdx.y * 256;
    float s = 0.0f;
#pragma unroll 4
    for (int i = 0; i < 256; i++)
        s += buv[m0 + i] * outw[(size_t)(m0 + i) * DM + n];
    atomicAdd(&o[n], s);
}

// warp-per-output: bqrow[h][n] = sum_d buq[h*624+d] * Wuk[n, h*624+d]
__global__ __launch_bounds__(256)
void bqrow_w_k(const float* __restrict__ buq, const float* __restrict__ wuk,
               float* __restrict__ o)
{
    int widx = blockIdx.x * 8 + (threadIdx.x >> 5);   // warp-global index
    int lane = threadIdx.x & 31;
    if (widx >= NH * DKV) return;
    int h = widx / DKV, n = widx % DKV;
    const float* wrow = wuk + (size_t)n * (NH * SPLITD) + h * SPLITD;
    const float* brow = buq + h * SPLITD;
    float s = 0.0f;
    for (int d = lane; d < SPLITD; d += 32) s += brow[d] * wrow[d];
#pragma unroll
    for (int off = 16; off > 0; off >>= 1) s += __shfl_xor_sync(0xFFFFFFFF, s, off);
    if (lane == 0) o[widx] = s;
}

// warp-per-output: wh[h][k] = sum_d Wuq[k, h*624+d]*buk[h*624+d];
// extra warps (widx >= 1024) compute sconst[h] = buq_h . buk_h
__global__ __launch_bounds__(256)
void wh_w_k(const float* __restrict__ wuq, const float* __restrict__ buk,
            const float* __restrict__ buq, float* __restrict__ o, float* __restrict__ sc)
{
    int widx = blockIdx.x * 8 + (threadIdx.x >> 5);
    int lane = threadIdx.x & 31;
    if (widx < NH * DKV) {
        int h = widx / DKV, k = widx % DKV;
        const float* wrow = wuq + (size_t)k * (NH * SPLITD) + h * SPLITD;
        const float* brow = buk + h * SPLITD;
        float s = 0.0f;
        for (int d = lane; d < SPLITD; d += 32) s += brow[d] * wrow[d];
#pragma unroll
        for (int off = 16; off > 0; off >>= 1) s += __shfl_xor_sync(0xFFFFFFFF, s, off);
        if (lane == 0) o[widx] = s;
    } else if (widx < NH * DKV + NH) {
        int h = widx - NH * DKV;
        float s = 0.0f;
        for (int d = lane; d < SPLITD; d += 32)
            s += buq[h * SPLITD + d] * buk[h * SPLITD + d];
#pragma unroll
        for (int off = 16; off > 0; off >>= 1) s += __shfl_xor_sync(0xFFFFFFFF, s, off);
        if (lane == 0) sc[h] = s;
    }
}

__global__ void bias_cat2(const float* a, const float* b, float* o, int n1, int n2)
{
    int i = blockIdx.x * blockDim.x + threadIdx.x;
    if (i >= n1 + n2) return;
    o[i] = (i < n1) ? a[i] : b[i - n1];
}

// split-K reduce: ckvcq_half = p0+p1+bdd ; ckv float output for cols<128
__global__ void spk_reduce(const float* __restrict__ p0, const float* __restrict__ p1,
                           const float* __restrict__ bdd,
                           __half* __restrict__ ckvcq, float* __restrict__ ckvf)
{
    int i = blockIdx.x * blockDim.x + threadIdx.x;
    if (i >= MROWS * NDD) return;
    int m = i / NDD, c = i % NDD;
    float s = p0[i] + p1[i] + bdd[c];
    ckvcq[i] = __float2half_rn(s);
    if (c < DKV) ckvf[(size_t)m * DKV + c] = s;
}

__global__ void sq_k(const __half* __restrict__ cq, int ldcq, const float* __restrict__ wh,
                     const float* __restrict__ scst, __half* __restrict__ qp)
{
    int idx = blockIdx.x * blockDim.x + threadIdx.x;
    if (idx >= MROWS * NH) return;
    int m = idx / NH, h = idx % NH;
    float s = scst[h];
    for (int k = 0; k < DKV; k++)
        s += __half2float(cq[(size_t)m * ldcq + k]) * wh[h * DKV + k];
    qp[(size_t)m * LDQP + h * KP + 144] = __float2half_rn(s);
}

__global__ void qppad_k(__half* __restrict__ qp)
{
    int idx = blockIdx.x * blockDim.x + threadIdx.x;
    if (idx >= MROWS * NH) return;
    int m = idx / NH, h = idx % NH;
    __half* p = qp + (size_t)m * LDQP + h * KP;
    for (int c = 145; c < KP; c++) p[c] = __float2half_rn(0.0f);
}

__global__ void kpfill_k(const __half* __restrict__ ckv, int ldckv, __half* __restrict__ kp)
{
    int idx = blockIdx.x * blockDim.x + threadIdx.x;
    int total = MROWS * NH * 18;
    if (idx >= total) return;
    int c = idx % 18;
    int mh = idx / 18;
    int m = mh / NH, h = mh % NH;
    __half* p = kp + (size_t)m * LDQP + h * KP;
    if (c < 16) {
        uint4 v = *reinterpret_cast<const uint4*>(ckv + (size_t)m * ldckv + c * 8);
        *reinterpret_cast<uint4*>(p + c * 8) = v;
    } else if (c == 16) {
        __half z = __float2half_rn(0.0f);
        __half vals[8] = { __float2half_rn(1.0f), z, z, z, z, z, z, z };
        *reinterpret_cast<uint4*>(p + 144) = *reinterpret_cast<uint4*>(vals);
    } else {
        __half z = __float2half_rn(0.0f);
        __half vals[8] = { z, z, z, z, z, z, z, z };
        *reinterpret_cast<uint4*>(p + 152) = *reinterpret_cast<uint4*>(vals);
    }
}

__global__ void rope_k(const __half* __restrict__ pre, __half* __restrict__ dst,
                       float* __restrict__ rout)
{
    int idx = blockIdx.x * blockDim.x + threadIdx.x;
    if (idx >= MROWS * DKV) return;
    int m = idx >> 7;
    int c = idx & 127;
    int h = c >> 4;
    int d = c & 15;
    int j = d & 7;
    int s = m & (SEQ - 1);
    float t = (float)s * (1.0f / 40.0f);
    float invf = __expf(-(float)j * 0.86346941f);  // ln(1000)/8
    float ang = t * invf;
    float sn, cs;
    sincosf(ang, &sn, &cs);
    float x = __half2float(pre[idx]);
    float p = __half2float(pre[(m << 7) + (h << 4) + ((d < 8) ? d + 8 : d - 8)]);
    float val = x * cs + ((d < 8) ? -p : p) * sn;
    dst[(size_t)m * LDQP + h * KP + 128 + d] = __float2half_rn(val);
    if (rout) rout[idx] = val;
}

// ============================================================================
// host launcher — main chain on default stream, weight-prep forked to a side
// stream within graph capture (event fork/join).
// ============================================================================
extern "C" void kernel_launch(void* const* d_in, const int* in_sizes, int n_in,
                              void* d_out, int out_size)
{
    const float* h    = (const float*)d_in[0];
    const float* Wdkv = (const float*)d_in[1];
    const float* bdkv = (const float*)d_in[2];
    const float* Wdq  = (const float*)d_in[3];
    const float* bdq  = (const float*)d_in[4];
    const float* Wuk  = (const float*)d_in[5];
    const float* buk  = (const float*)d_in[6];
    const float* Wuv  = (const float*)d_in[7];
    const float* buv  = (const float*)d_in[8];
    const float* Wuq  = (const float*)d_in[9];
    const float* buq  = (const float*)d_in[10];
    const float* Wqr  = (const float*)d_in[11];
    const float* bqr  = (const float*)d_in[12];
    const float* Wkr  = (const float*)d_in[13];
    const float* bkr  = (const float*)d_in[14];
    const float* outw = (const float*)d_in[15];
    const float* outb = (const float*)d_in[16];
    float* out = (float*)d_out;

    __half *hh, *ckvcq, *krqrp, *qp, *kp, *u;
    __half *wdd, *wkq, *wt_out, *wuv_h, *wuq_p, *wuk_p, *mt, *w2t;
    float *ckvf, *part, *bias2, *bqrow, *wh, *scst, *bdd, *bkq;
    cudaGetSymbolAddress((void**)&hh,    g_hh);
    cudaGetSymbolAddress((void**)&ckvcq, g_ckvcq);
    cudaGetSymbolAddress((void**)&krqrp, g_krqrp);
    cudaGetSymbolAddress((void**)&qp,    g_qp);
    cudaGetSymbolAddress((void**)&kp,    g_kp);
    cudaGetSymbolAddress((void**)&u,     g_u);
    cudaGetSymbolAddress((void**)&ckvf,  g_ckvf);
    cudaGetSymbolAddress((void**)&part,  g_part);
    cudaGetSymbolAddress((void**)&wdd,   g_wdd);
    cudaGetSymbolAddress((void**)&wkq,   g_wkq);
    cudaGetSymbolAddress((void**)&wt_out, g_wt_out);
    cudaGetSymbolAddress((void**)&wuv_h,  g_wuv_h);
    cudaGetSymbolAddress((void**)&wuq_p,  g_wuq_p);
    cudaGetSymbolAddress((void**)&wuk_p,  g_wuk_p);
    cudaGetSymbolAddress((void**)&mt,     g_mt);
    cudaGetSymbolAddress((void**)&w2t,    g_w2t);
    cudaGetSymbolAddress((void**)&bias2,  g_bias2);
    cudaGetSymbolAddress((void**)&bqrow,  g_bqrow);
    cudaGetSymbolAddress((void**)&wh,     g_wh);
    cudaGetSymbolAddress((void**)&scst,   g_sconst);
    cudaGetSymbolAddress((void**)&bdd,    g_bdd);
    cudaGetSymbolAddress((void**)&bkq,    g_bkq);

    cudaFuncSetAttribute(flash_k, cudaFuncAttributeMaxDynamicSharedMemorySize, FA_SMEM);

    const size_t out_ckv_off  = (size_t)MROWS * DM;
    const size_t out_krot_off = out_ckv_off + (size_t)MROWS * DKV;
    bool full_out = (size_t)out_size >= out_krot_off + (size_t)MROWS * DKV;
    float* ckv_dst = full_out ? (out + out_ckv_off) : ckvf;

    dim3 b256(256);
    dim3 blk(256);
    auto grd = [](int M, int N, int Z) { return dim3((unsigned)(N / 128), (unsigned)(M / 128), (unsigned)Z); };

    // ---- fork side stream inside capture ----
    cudaStream_t side;
    cudaStreamCreateWithFlags(&side, cudaStreamNonBlocking);
    cudaEvent_t evFork, evA, evB;
    cudaEventCreateWithFlags(&evFork, cudaEventDisableTiming);
    cudaEventCreateWithFlags(&evA,    cudaEventDisableTiming);
    cudaEventCreateWithFlags(&evB,    cudaEventDisableTiming);
    cudaEventRecord(evFork, 0);
    cudaStreamWaitEvent(side, evFork, 0);

    // ---- side chain: weight prep independent of h ----
    pad_w_k<<<(DKV * NH * DH + 255) / 256, 256, 0, side>>>(Wuq, wuq_p);
    pad_w_k<<<(DKV * NH * DH + 255) / 256, 256, 0, side>>>(Wuk, wuk_p);
    hgemm<<<grd(DKV, DKV, NH), blk, 0, side>>>(wuk_p, wuq_p, nullptr, mt, nullptr,
        DKV, DKV, DH, NH*DH, NH*DH, DKV, DKV, 0, 1.0f,
        0, DH, 0, DH, 0, DKV*DKV, 0, NH);
    bqrow_w_k<<<(NH * DKV + 7) / 8, 256, 0, side>>>(buq, Wuk, bqrow);
    wh_w_k<<<(NH * DKV + NH + 7) / 8, 256, 0, side>>>(Wuq, buk, buq, wh, scst);
    cudaEventRecord(evA, side);   // mt, bqrow, wh, sconst ready

    f2h_k<<<(DKV * DM / 4 + 255) / 256, 256, 0, side>>>(Wuv, wuv_h, DKV * DM / 4);
    transpose_f2h<<<dim3(DM/32, DM/32), b256, 0, side>>>(outw, wt_out, DM, DM);
    hgemm<<<grd(DM, DKV, NH), blk, 0, side>>>(wt_out, wuv_h, nullptr, w2t, nullptr,
        DM, DKV, DH, DM, DM, NH*DKV, NH*DKV, 0, 1.0f,
        0, DH, 0, DH, 0, DKV, 0, NH);
    bias2init_k<<<DM / 256, 256, 0, side>>>(outb, bias2);
    bias2p_k<<<dim3(DM / 256, DM / 256), 256, 0, side>>>(outw, buv, bias2);
    cudaEventRecord(evB, side);   // w2t, bias2 ready

    // ---- main chain (default stream) ----
    f2h_k<<<((size_t)MROWS * DM / 4 + 255) / 256, 256>>>(h, hh, MROWS * DM / 4);
    transpose_f2h<<<dim3(DKV/32, DM/32), b256>>>(Wdkv, wdd,                 DKV, DM);
    transpose_f2h<<<dim3(DKV/32, DM/32), b256>>>(Wdq,  wdd + (size_t)DKV*DM, DKV, DM);
    transpose_f2h<<<dim3(DKV/32, DKV/32), b256>>>(Wkr, wkq,                 DKV, DKV);
    transpose_f2h<<<dim3(DKV/32, DKV/32), b256>>>(Wqr, wkq + DKV*DKV,       DKV, DKV);
    bias_cat2<<<(NDD + 255) / 256, 256>>>(bdkv, bdq, bdd, DKV, DKV);
    bias_cat2<<<(2 * DKV + 255) / 256, 256>>>(bkr, bqr, bkq, DKV, DKV);

    // 1) merged down projection with split-K; reduce adds bias, emits outputs
    hgemm<<<grd(MROWS, NDD, 2), blk>>>(hh, wdd, part, nullptr, nullptr,
        MROWS, NDD, DM/2, DM, DM, NDD, NDD, NDD, 1.0f,
        0, DM/2, 0, DM/2, 0, (long long)MROWS * NDD, 0, 2);
    spk_reduce<<<(MROWS * NDD + 255) / 256, 256>>>(part, part + (size_t)MROWS * NDD,
        bdd, ckvcq, ckv_dst);

    // 2) merged rotary pre-projections
    hgemm<<<grd(MROWS, DKV, 2), blk>>>(ckvcq, wkq, nullptr, krqrp, bkq,
        MROWS, DKV, DKV, NDD, DKV, DKV, DKV, 0, 1.0f,
        0, DKV, 0, DKV*DKV, 0, (long long)MROWS*DKV, DKV, 2);

    // rope + kpfill (don't need side results)
    rope_k<<<(MROWS * DKV + 255) / 256, 256>>>(krqrp + (size_t)MROWS * DKV, qp, nullptr);
    rope_k<<<(MROWS * DKV + 255) / 256, 256>>>(krqrp, kp,
        full_out ? (out + out_krot_off) : nullptr);
    kpfill_k<<<(MROWS * NH * 18 + 255) / 256, 256>>>(ckvcq, NDD, kp);

    // join A: need mt, bqrow, wh, sconst
    cudaStreamWaitEvent(0, evA, 0);

    // 3) q-tilde
    hgemm<<<grd(MROWS, DKV, NH), blk>>>(ckvcq + DKV, mt, nullptr, qp, bqrow,
        MROWS, DKV, DKV, NDD, DKV, LDQP, LDQP, 0, 1.0f,
        0, 0, 0, DKV*DKV, 0, KP, DKV, NH);
    sq_k<<<(MROWS * NH + 255) / 256, 256>>>(ckvcq + DKV, NDD, wh, scst, qp);
    qppad_k<<<(MROWS * NH + 255) / 256, 256>>>(qp);

    // 5) fused flash attention -> u
    float inv_sqrt = 1.0f / sqrtf((float)DH);
    flash_k<<<dim3(SEQ/128, BATCH*NH), blk, FA_SMEM>>>(qp, kp, ckvcq, NDD, u, inv_sqrt);

    // join B: need w2t, bias2
    cudaStreamWaitEvent(0, evB, 0);

    // 6) out = u @ w2t^T + bias2
    hgemm<<<grd(MROWS, DM, 1), blk>>>(u, w2t, out, nullptr, bias2,
        MROWS, DM, NH*DKV, NH*DKV, NH*DKV, DM, DM, DM, 1.0f, 0,0,0,0,0,0,0, 1);

    cudaEventDestroy(evFork);
    cudaEventDestroy(evA);
    cudaEventDestroy(evB);
    cudaStreamDestroy(side);
}

// round 16
// speedup vs baseline: 2.2419x; 1.0592x over previous
#include <cuda_runtime.h>
#include <cuda_fp16.h>
#include <math.h>
#include <stdint.h>

// ---------------- problem constants ----------------
#define BATCH 2
#define SEQ   2048
#define DM    5120
#define NH    8
#define DH    640
#define DR    16
#define SPLITD 624
#define DKV   128
#define MROWS (BATCH*SEQ)        // 4096
#define KP    144                // per-head score K-dim: [128 ckv |16 rope]  (no pad!)
#define LDQP  (NH*KP)            // 1152
#define NDD   256                // merged down-proj N: [ckv|cq]

// ---------------- scratch (device globals; no allocs allowed) ----------------
__device__ __align__(16) __half g_hh   [(size_t)MROWS*DM];
__device__ __align__(16) __half g_ckvcq[(size_t)MROWS*NDD];   // [ckv(0:128) | cq(128:256)]
__device__ __align__(16) __half g_krqrp[2*MROWS*DKV];          // [krp | qrp]
__device__ __align__(16) __half g_qp   [(size_t)MROWS*LDQP];
__device__ __align__(16) __half g_kp   [(size_t)MROWS*LDQP];
__device__ __align__(16) __half g_u    [(size_t)MROWS*NH*DKV]; // [4096,1024]
__device__ __align__(16) float  g_ckvf [MROWS*DKV];
__device__ __align__(16) float  g_part [2*(size_t)MROWS*NDD];  // split-K partials
// weights
__device__ __align__(16) __half g_wdd  [(size_t)NDD*DM];       // [wt_dkv; wt_dq] [256,5120]
__device__ __align__(16) __half g_wkq  [2*DKV*DKV];            // [wt_kr; wt_qr]
__device__ __align__(16) __half g_wt_out[(size_t)DM*DM];       // Wout^T [DM, NH*DH]
__device__ __align__(16) __half g_wuv_h [DKV*DM];
__device__ __align__(16) __half g_wuq_p [DKV*NH*DH];           // zero-padded 624->640
__device__ __align__(16) __half g_wuk_p [DKV*NH*DH];
__device__ __align__(16) __half g_mt    [NH*DKV*DKV];          // Mt_h = Wuk_h Wuq_h^T
__device__ __align__(16) __half g_w2t   [(size_t)DM*NH*DKV];   // [5120,1024]
__device__ __align__(16) float  g_bias2 [DM];
__device__ __align__(16) float  g_bqrow [NH*DKV];
__device__ __align__(16) float  g_bdd   [NDD];
__device__ __align__(16) float  g_bkq   [2*DKV];

// ---------------- PTX helpers ----------------
__device__ __forceinline__ uint32_t smem_u32(const void* p) {
    uint32_t a;
    asm("{ .reg .u64 t; cvta.to.shared.u64 t, %1; cvt.u32.u64 %0, t; }" : "=r"(a) : "l"(p));
    return a;
}
__device__ __forceinline__ void cp16(uint32_t dst, const void* src) {
    asm volatile("cp.async.cg.shared.global [%0], [%1], 16;" :: "r"(dst), "l"(src) : "memory");
}
#define CP_COMMIT() asm volatile("cp.async.commit_group;" ::: "memory")
#define CP_WAIT(n)  asm volatile("cp.async.wait_group %0;" :: "n"(n) : "memory")

__device__ __forceinline__ void ldm_x4(uint32_t* r, uint32_t addr) {
    asm volatile("ldmatrix.sync.aligned.m8n8.x4.shared.b16 {%0,%1,%2,%3}, [%4];"
                 : "=r"(r[0]), "=r"(r[1]), "=r"(r[2]), "=r"(r[3]) : "r"(addr));
}
__device__ __forceinline__ void ldm_x4t(uint32_t* r, uint32_t addr) {
    asm volatile("ldmatrix.sync.aligned.m8n8.x4.trans.shared.b16 {%0,%1,%2,%3}, [%4];"
                 : "=r"(r[0]), "=r"(r[1]), "=r"(r[2]), "=r"(r[3]) : "r"(addr));
}
__device__ __forceinline__ void mma_f16(float* c, const uint32_t* a, uint32_t b0, uint32_t b1) {
    asm volatile("mma.sync.aligned.m16n8k16.row.col.f32.f16.f16.f32 "
                 "{%0,%1,%2,%3}, {%4,%5,%6,%7}, {%8,%9}, {%0,%1,%2,%3};"
                 : "+f"(c[0]), "+f"(c[1]), "+f"(c[2]), "+f"(c[3])
                 : "r"(a[0]), "r"(a[1]), "r"(a[2]), "r"(a[3]), "r"(b0), "r"(b1));
}
__device__ __forceinline__ uint32_t packh2(float x, float y) {
    __half2 h = __floats2half2_rn(x, y);
    return *reinterpret_cast<uint32_t*>(&h);
}

// ============================================================================
// fp16 mma.sync GEMM: C = alpha*A*B^T + bias. 128x128 tile, BK=32, 2-stage.
// Cf written only for cols < cfN (ld ldcf); Ch full (ld ldc).
// ============================================================================
#define SPADH 40

__global__ __launch_bounds__(256)
void hgemm(const __half* __restrict__ A, const __half* __restrict__ B,
           float* __restrict__ Cf, __half* __restrict__ Ch,
           const float* __restrict__ bias,
           int M, int N, int K, int lda, int ldb, int ldc, int ldcf, int cfN,
           float alpha,
           long long sAhi, long long sAlo, long long sBhi, long long sBlo,
           long long sChi, long long sClo, long long sBiasLo, int zdiv)
{
    __shared__ __half As[2][128][SPADH];
    __shared__ __half Bs[2][128][SPADH];

    int tid  = threadIdx.x;
    int warp = tid >> 5;
    int lane = tid & 31;
    int wr = warp >> 1;
    int wc = warp & 1;
    int qid = lane >> 2;
    int tig = lane & 3;

    int z  = blockIdx.z;
    int zh = z / zdiv, zl = z % zdiv;
    A += zh * sAhi + zl * sAlo;
    B += zh * sBhi + zl * sBlo;
    long long cofs = zh * sChi + zl * sClo;
    if (Cf) Cf += cofs;
    if (Ch) Ch += cofs;
    if (bias) bias += zl * sBiasLo;

    int row0 = blockIdx.y * 128, col0 = blockIdx.x * 128;
    const __half* Ab = A + (size_t)row0 * lda;
    const __half* Bb = B + (size_t)col0 * ldb;

    int r0 = tid >> 2, cc = (tid & 3) * 8;
    int r1 = r0 + 64;
    uint32_t dA0[2], dA1[2], dB0[2], dB1[2];
#pragma unroll
    for (int s = 0; s < 2; s++) {
        dA0[s] = smem_u32(&As[s][r0][cc]);
        dA1[s] = smem_u32(&As[s][r1][cc]);
        dB0[s] = smem_u32(&Bs[s][r0][cc]);
        dB1[s] = smem_u32(&Bs[s][r1][cc]);
    }
    uint32_t aAddr[2][2], bAddr[2][4];
#pragma unroll
    for (int s = 0; s < 2; s++) {
#pragma unroll
        for (int mi = 0; mi < 2; mi++)
            aAddr[s][mi] = smem_u32(&As[s][wr * 32 + mi * 16 + (lane & 15)][(lane >> 4) * 8]);
#pragma unroll
        for (int np = 0; np < 4; np++)
            bAddr[s][np] = smem_u32(&Bs[s][wc * 64 + np * 16 + (lane & 7) + ((lane >> 4) & 1) * 8]
                                        [((lane >> 3) & 1) * 8]);
    }

    float acc[2][8][4];
#pragma unroll
    for (int mi = 0; mi < 2; mi++)
#pragma unroll
        for (int ni = 0; ni < 8; ni++)
#pragma unroll
            for (int i = 0; i < 4; i++) acc[mi][ni][i] = 0.0f;

    int T = K >> 5;

    cp16(dA0[0], Ab + (size_t)r0 * lda + cc);
    cp16(dA1[0], Ab + (size_t)r1 * lda + cc);
    cp16(dB0[0], Bb + (size_t)r0 * ldb + cc);
    cp16(dB1[0], Bb + (size_t)r1 * ldb + cc);
    CP_COMMIT();

    for (int t = 0; t < T; t++) {
        if (t + 1 < T) {
            int s = (t + 1) & 1;
            int k0 = (t + 1) * 32;
            cp16(dA0[s], Ab + (size_t)r0 * lda + k0 + cc);
            cp16(dA1[s], Ab + (size_t)r1 * lda + k0 + cc);
            cp16(dB0[s], Bb + (size_t)r0 * ldb + k0 + cc);
            cp16(dB1[s], Bb + (size_t)r1 * ldb + k0 + cc);
            CP_COMMIT();
            CP_WAIT(1);
        } else {
            CP_WAIT(0);
        }
        __syncthreads();

        int s = t & 1;
#pragma unroll
        for (int ks = 0; ks < 2; ks++) {
            uint32_t koff = ks * 32;
            uint32_t a[2][4], b[16];
#pragma unroll
            for (int mi = 0; mi < 2; mi++) ldm_x4(a[mi], aAddr[s][mi] + koff);
#pragma unroll
            for (int np = 0; np < 4; np++) ldm_x4(b + np * 4, bAddr[s][np] + koff);
#pragma unroll
            for (int ni = 0; ni < 8; ni++) {
                uint32_t b0 = b[(ni >> 1) * 4 + (ni & 1) * 2];
                uint32_t b1 = b[(ni >> 1) * 4 + (ni & 1) * 2 + 1];
                mma_f16(acc[0][ni], a[0], b0, b1);
                mma_f16(acc[1][ni], a[1], b0, b1);
            }
        }
        __syncthreads();
    }

#pragma unroll
    for (int mi = 0; mi < 2; mi++) {
        int rg = row0 + wr * 32 + mi * 16 + qid;
#pragma unroll
        for (int ni = 0; ni < 8; ni++) {
            int cg = col0 + wc * 64 + ni * 8 + tig * 2;
            float bx = 0.0f, by = 0.0f;
            if (bias) { bx = bias[cg]; by = bias[cg + 1]; }
            float o0 = alpha * acc[mi][ni][0] + bx;
            float o1 = alpha * acc[mi][ni][1] + by;
            float o2 = alpha * acc[mi][ni][2] + bx;
            float o3 = alpha * acc[mi][ni][3] + by;
            if (Cf && cg < cfN) {
                *reinterpret_cast<float2*>(Cf + (size_t)rg * ldcf + cg)       = make_float2(o0, o1);
                *reinterpret_cast<float2*>(Cf + (size_t)(rg + 8) * ldcf + cg) = make_float2(o2, o3);
            }
            if (Ch) {
                *reinterpret_cast<__half2*>(Ch + (size_t)rg * ldc + cg)       = __floats2half2_rn(o0, o1);
                *reinterpret_cast<__half2*>(Ch + (size_t)(rg + 8) * ldc + cg) = __floats2half2_rn(o2, o3);
            }
        }
    }
}

// ============================================================================
// flash attention: per CTA = (q-tile 128 rows, one (b,h)). online softmax.
// KP = 144: Q/K rows are 144 halfs, 9 k-steps of 16.
// ============================================================================
#define FAQ_LD 152                // 144 + 8 pad halfs (304B rows, conflict-free)
#define FAV_LD 136
#define FA_SMEM ((3*128*FAQ_LD + 2*128*FAV_LD) * 2)   // 186368 B

__global__ __launch_bounds__(256, 1)
void flash_k(const __half* __restrict__ qp, const __half* __restrict__ kp,
             const __half* __restrict__ ckv, int ldckv,
             __half* __restrict__ u, float scale)
{
    extern __shared__ __half sm[];
    __half* Qs = sm;
    __half* Ks = sm + 128 * FAQ_LD;
    __half* Vs = sm + 3 * 128 * FAQ_LD;

    int tid = threadIdx.x;
    int warp = tid >> 5, lane = tid & 31;
    int qid = lane >> 2, tig = lane & 3;

    int qt = blockIdx.x;
    int z  = blockIdx.y;
    int b = z >> 3, h = z & 7;

    const __half* Qg = qp + ((size_t)(b * SEQ + qt * 128)) * LDQP + h * KP;
    const __half* Kg = kp + ((size_t)b * SEQ) * LDQP + h * KP;
    const __half* Vg = ckv + ((size_t)b * SEQ) * ldckv;

    // Q/K tile: 128 rows x 18 chunks (144 halfs) = 2304 chunks, 9 per thread
#pragma unroll
    for (int i = 0; i < 9; i++) {
        int idx = tid + i * 256;
        int r = idx / 18, c = idx % 18;
        cp16(smem_u32(Qs + r * FAQ_LD + c * 8), Qg + (size_t)r * LDQP + c * 8);
    }
#pragma unroll
    for (int i = 0; i < 9; i++) {
        int idx = tid + i * 256;
        int r = idx / 18, c = idx % 18;
        cp16(smem_u32(Ks + r * FAQ_LD + c * 8), Kg + (size_t)r * LDQP + c * 8);
    }
#pragma unroll
    for (int i = 0; i < 8; i++) {
        int idx = tid + i * 256;
        int r = idx / 16, c = idx % 16;
        cp16(smem_u32(Vs + r * FAV_LD + c * 8), Vg + (size_t)r * ldckv + c * 8);
    }
    CP_COMMIT();

    uint32_t qAddr = smem_u32(Qs + (warp * 16 + (lane & 15)) * FAQ_LD + (lane >> 4) * 8);
    uint32_t kAddr[2][8], vAddr[2][8];
#pragma unroll
    for (int s = 0; s < 2; s++) {
#pragma unroll
        for (int nb = 0; nb < 8; nb++) {
            kAddr[s][nb] = smem_u32(Ks + s * 128 * FAQ_LD
                + (nb * 16 + (lane & 7) + ((lane >> 4) & 1) * 8) * FAQ_LD
                + ((lane >> 3) & 1) * 8);
            vAddr[s][nb] = smem_u32(Vs + s * 128 * FAV_LD
                + (lane & 15) * FAV_LD
                + nb * 16 + ((lane >> 4) << 3));
        }
    }

    float oacc[16][4];
#pragma unroll
    for (int j = 0; j < 16; j++)
#pragma unroll
        for (int i = 0; i < 4; i++) oacc[j][i] = 0.0f;
    float m0 = -1e30f, m1 = -1e30f, l0 = 0.0f, l1 = 0.0f;

    for (int kt = 0; kt < 16; kt++) {
        CP_WAIT(0);
        __syncthreads();
        if (kt + 1 < 16) {
            int s = (kt + 1) & 1;
            const __half* Kt = Kg + (size_t)(kt + 1) * 128 * LDQP;
            const __half* Vt = Vg + (size_t)(kt + 1) * 128 * ldckv;
#pragma unroll
            for (int i = 0; i < 9; i++) {
                int idx = tid + i * 256;
                int r = idx / 18, c = idx % 18;
                cp16(smem_u32(Ks + s * 128 * FAQ_LD + r * FAQ_LD + c * 8),
                     Kt + (size_t)r * LDQP + c * 8);
            }
#pragma unroll
            for (int i = 0; i < 8; i++) {
                int idx = tid + i * 256;
                int r = idx / 16, c = idx % 16;
                cp16(smem_u32(Vs + s * 128 * FAV_LD + r * FAV_LD + c * 8),
                     Vt + (size_t)r * ldckv + c * 8);
            }
            CP_COMMIT();
        }

        int s = kt & 1;
        float sacc[16][4];
#pragma unroll
        for (int j = 0; j < 16; j++)
#pragma unroll
            for (int i = 0; i < 4; i++) sacc[j][i] = 0.0f;
#pragma unroll
        for (int ks = 0; ks < 9; ks++) {
            uint32_t a[4];
            ldm_x4(a, qAddr + ks * 32);
#pragma unroll
            for (int nb = 0; nb < 8; nb++) {
                uint32_t bb[4];
                ldm_x4(bb, kAddr[s][nb] + ks * 32);
                mma_f16(sacc[2 * nb],     a, bb[0], bb[1]);
                mma_f16(sacc[2 * nb + 1], a, bb[2], bb[3]);
            }
        }
        float mx0 = -1e30f, mx1 = -1e30f;
#pragma unroll
        for (int j = 0; j < 16; j++) {
            sacc[j][0] *= scale; sacc[j][1] *= scale;
            sacc[j][2] *= scale; sacc[j][3] *= scale;
            mx0 = fmaxf(mx0, fmaxf(sacc[j][0], sacc[j][1]));
            mx1 = fmaxf(mx1, fmaxf(sacc[j][2], sacc[j][3]));
        }
        mx0 = fmaxf(mx0, __shfl_xor_sync(0xFFFFFFFF, mx0, 1));
        mx0 = fmaxf(mx0, __shfl_xor_sync(0xFFFFFFFF, mx0, 2));
        mx1 = fmaxf(mx1, __shfl_xor_sync(0xFFFFFFFF, mx1, 1));
        mx1 = fmaxf(mx1, __shfl_xor_sync(0xFFFFFFFF, mx1, 2));
        float mn0 = fmaxf(m0, mx0), mn1 = fmaxf(m1, mx1);
        float f0 = __expf(m0 - mn0), f1 = __expf(m1 - mn1);
        m0 = mn0; m1 = mn1;
        float ts0 = 0.0f, ts1 = 0.0f;
#pragma unroll
        for (int j = 0; j < 16; j++) {
            sacc[j][0] = __expf(sacc[j][0] - m0);
            sacc[j][1] = __expf(sacc[j][1] - m0);
            sacc[j][2] = __expf(sacc[j][2] - m1);
            sacc[j][3] = __expf(sacc[j][3] - m1);
            ts0 += sacc[j][0] + sacc[j][1];
            ts1 += sacc[j][2] + sacc[j][3];
        }
        ts0 += __shfl_xor_sync(0xFFFFFFFF, ts0, 1);
        ts0 += __shfl_xor_sync(0xFFFFFFFF, ts0, 2);
        ts1 += __shfl_xor_sync(0xFFFFFFFF, ts1, 1);
        ts1 += __shfl_xor_sync(0xFFFFFFFF, ts1, 2);
        l0 = l0 * f0 + ts0;
        l1 = l1 * f1 + ts1;
#pragma unroll
        for (int j = 0; j < 16; j++) {
            oacc[j][0] *= f0; oacc[j][1] *= f0;
            oacc[j][2] *= f1; oacc[j][3] *= f1;
        }
#pragma unroll
        for (int kb = 0; kb < 8; kb++) {
            uint32_t a[4];
            a[0] = packh2(sacc[2 * kb][0],     sacc[2 * kb][1]);
            a[1] = packh2(sacc[2 * kb][2],     sacc[2 * kb][3]);
            a[2] = packh2(sacc[2 * kb + 1][0], sacc[2 * kb + 1][1]);
            a[3] = packh2(sacc[2 * kb + 1][2], sacc[2 * kb + 1][3]);
            uint32_t voff = (uint32_t)(kb * 16 * FAV_LD * 2);
#pragma unroll
            for (int nb = 0; nb < 8; nb++) {
                uint32_t bb[4];
                ldm_x4t(bb, vAddr[s][nb] + voff);
                mma_f16(oacc[2 * nb],     a, bb[0], bb[1]);
                mma_f16(oacc[2 * nb + 1], a, bb[2], bb[3]);
            }
        }
    }

    float il0 = 1.0f / l0, il1 = 1.0f / l1;
    int rowg = b * SEQ + qt * 128 + warp * 16;
#pragma unroll
    for (int j = 0; j < 16; j++) {
        int col = h * 128 + j * 8 + tig * 2;
        *reinterpret_cast<__half2*>(u + (size_t)(rowg + qid) * (NH * DKV) + col)
            = __floats2half2_rn(oacc[j][0] * il0, oacc[j][1] * il0);
        *reinterpret_cast<__half2*>(u + (size_t)(rowg + qid + 8) * (NH * DKV) + col)
            = __floats2half2_rn(oacc[j][2] * il1, oacc[j][3] * il1);
    }
}

// ============================================================================
// small kernels
// ============================================================================
__global__ __launch_bounds__(256)
void transpose_f2h(const float* __restrict__ in, __half* __restrict__ out, int ldi, int ldo)
{
    __shared__ float t[32][33];
    int bx = blockIdx.x * 32, by = blockIdx.y * 32;
    int tx = threadIdx.x & 31, ty = threadIdx.x >> 5;
#pragma unroll
    for (int i = 0; i < 4; i++)
        t[ty + 8 * i][tx] = in[(size_t)(by + ty + 8 * i) * ldi + bx + tx];
    __syncthreads();
#pragma unroll
    for (int i = 0; i < 4; i++)
        out[(size_t)(bx + ty + 8 * i) * ldo + by + tx] = __float2half_rn(t[tx][ty + 8 * i]);
}

__global__ void f2h_k(const float* __restrict__ in, __half* __restrict__ out, int n4)
{
    int i = blockIdx.x * blockDim.x + threadIdx.x;
    if (i >= n4) return;
    float4 v = *reinterpret_cast<const float4*>(in + (size_t)i * 4);
    __half2 a = __floats2half2_rn(v.x, v.y);
    __half2 b = __floats2half2_rn(v.z, v.w);
    *reinterpret_cast<uint2*>(out + (size_t)i * 4) = make_uint2(
        *reinterpret_cast<uint32_t*>(&a), *reinterpret_cast<uint32_t*>(&b));
}

__global__ void pad_w_k(const float* __restrict__ in, __half* __restrict__ out)
{
    int idx = blockIdx.x * blockDim.x + threadIdx.x;
    if (idx >= DKV * NH * DH) return;
    int i = idx / (NH * DH);
    int c = idx % (NH * DH);
    int h = c / DH, d = c % DH;
    float v = (d < SPLITD) ? in[(size_t)i * (NH * SPLITD) + h * SPLITD + d] : 0.0f;
    out[idx] = __float2half_rn(v);
}

// bias2 = outb + buv @ Wout : 2D-parallel, coalesced, atomic accumulate
__global__ void bias2init_k(const float* __restrict__ outb, float* __restrict__ o)
{
    int n = blockIdx.x * 256 + threadIdx.x;
    if (n < DM) o[n] = outb[n];
}
__global__ __launch_bounds__(256)
void bias2p_k(const float* __restrict__ outw, const float* __restrict__ buv,
              float* __restrict__ o)
{
    int n = blockIdx.x * 256 + threadIdx.x;
    int m0 = blockIdx.y * 256;
    float s = 0.0f;
#pragma unroll 4
    for (int i = 0; i < 256; i++)
        s += buv[m0 + i] * outw[(size_t)(m0 + i) * DM + n];
    atomicAdd(&o[n], s);
}

// warp-per-output: bqrow[h][n] = sum_d buq[h*624+d] * Wuk[n, h*624+d]
__global__ __launch_bounds__(256)
void bqrow_w_k(const float* __restrict__ buq, const float* __restrict__ wuk,
               float* __restrict__ o)
{
    int widx = blockIdx.x * 8 + (threadIdx.x >> 5);
    int lane = threadIdx.x & 31;
    if (widx >= NH * DKV) return;
    int h = widx / DKV, n = widx % DKV;
    const float* wrow = wuk + (size_t)n * (NH * SPLITD) + h * SPLITD;
    const float* brow = buq + h * SPLITD;
    float s = 0.0f;
    for (int d = lane; d < SPLITD; d += 32) s += brow[d] * wrow[d];
#pragma unroll
    for (int off = 16; off > 0; off >>= 1) s += __shfl_xor_sync(0xFFFFFFFF, s, off);
    if (lane == 0) o[widx] = s;
}

__global__ void bias_cat2(const float* a, const float* b, float* o, int n1, int n2)
{
    int i = blockIdx.x * blockDim.x + threadIdx.x;
    if (i >= n1 + n2) return;
    o[i] = (i < n1) ? a[i] : b[i - n1];
}

// split-K reduce: ckvcq_half = p0+p1+bdd ; ckv float output for cols<128
__global__ void spk_reduce(const float* __restrict__ p0, const float* __restrict__ p1,
                           const float* __restrict__ bdd,
                           __half* __restrict__ ckvcq, float* __restrict__ ckvf)
{
    int i = blockIdx.x * blockDim.x + threadIdx.x;
    if (i >= MROWS * NDD) return;
    int m = i / NDD, c = i % NDD;
    float s = p0[i] + p1[i] + bdd[c];
    ckvcq[i] = __float2half_rn(s);
    if (c < DKV) ckvf[(size_t)m * DKV + c] = s;
}

// kp fill: cols 0..127 = ckv[m] (strided) per head
__global__ void kpfill_k(const __half* __restrict__ ckv, int ldckv, __half* __restrict__ kp)
{
    int idx = blockIdx.x * blockDim.x + threadIdx.x;
    int total = MROWS * NH * 16;
    if (idx >= total) return;
    int c = idx % 16;
    int mh = idx / 16;
    int m = mh / NH, h = mh % NH;
    uint4 v = *reinterpret_cast<const uint4*>(ckv + (size_t)m * ldckv + c * 8);
    *reinterpret_cast<uint4*>(kp + (size_t)m * LDQP + h * KP + c * 8) = v;
}

__global__ void rope_k(const __half* __restrict__ pre, __half* __restrict__ dst,
                       float* __restrict__ rout)
{
    int idx = blockIdx.x * blockDim.x + threadIdx.x;
    if (idx >= MROWS * DKV) return;
    int m = idx >> 7;
    int c = idx & 127;
    int h = c >> 4;
    int d = c & 15;
    int j = d & 7;
    int s = m & (SEQ - 1);
    float t = (float)s * (1.0f / 40.0f);
    float invf = __expf(-(float)j * 0.86346941f);  // ln(1000)/8
    float ang = t * invf;
    float sn, cs;
    sincosf(ang, &sn, &cs);
    float x = __half2float(pre[idx]);
    float p = __half2float(pre[(m << 7) + (h << 4) + ((d < 8) ? d + 8 : d - 8)]);
    float val = x * cs + ((d < 8) ? -p : p) * sn;
    dst[(size_t)m * LDQP + h * KP + 128 + d] = __float2half_rn(val);
    if (rout) rout[idx] = val;
}

// ============================================================================
// host launcher — main chain on default stream, weight-prep forked to a side
// stream within graph capture (event fork/join).
// ============================================================================
extern "C" void kernel_launch(void* const* d_in, const int* in_sizes, int n_in,
                              void* d_out, int out_size)
{
    const float* h    = (const float*)d_in[0];
    const float* Wdkv = (const float*)d_in[1];
    const float* bdkv = (const float*)d_in[2];
    const float* Wdq  = (const float*)d_in[3];
    const float* bdq  = (const float*)d_in[4];
    const float* Wuk  = (const float*)d_in[5];
    const float* buk  = (const float*)d_in[6];
    const float* Wuv  = (const float*)d_in[7];
    const float* buv  = (const float*)d_in[8];
    const float* Wuq  = (const float*)d_in[9];
    const float* buq  = (const float*)d_in[10];
    const float* Wqr  = (const float*)d_in[11];
    const float* bqr  = (const float*)d_in[12];
    const float* Wkr  = (const float*)d_in[13];
    const float* bkr  = (const float*)d_in[14];
    const float* outw = (const float*)d_in[15];
    const float* outb = (const float*)d_in[16];
    float* out = (float*)d_out;

    __half *hh, *ckvcq, *krqrp, *qp, *kp, *u;
    __half *wdd, *wkq, *wt_out, *wuv_h, *wuq_p, *wuk_p, *mt, *w2t;
    float *ckvf, *part, *bias2, *bqrow, *bdd, *bkq;
    cudaGetSymbolAddress((void**)&hh,    g_hh);
    cudaGetSymbolAddress((void**)&ckvcq, g_ckvcq);
    cudaGetSymbolAddress((void**)&krqrp, g_krqrp);
    cudaGetSymbolAddress((void**)&qp,    g_qp);
    cudaGetSymbolAddress((void**)&kp,    g_kp);
    cudaGetSymbolAddress((void**)&u,     g_u);
    cudaGetSymbolAddress((void**)&ckvf,  g_ckvf);
    cudaGetSymbolAddress((void**)&part,  g_part);
    cudaGetSymbolAddress((void**)&wdd,   g_wdd);
    cudaGetSymbolAddress((void**)&wkq,   g_wkq);
    cudaGetSymbolAddress((void**)&wt_out, g_wt_out);
    cudaGetSymbolAddress((void**)&wuv_h,  g_wuv_h);
    cudaGetSymbolAddress((void**)&wuq_p,  g_wuq_p);
    cudaGetSymbolAddress((void**)&wuk_p,  g_wuk_p);
    cudaGetSymbolAddress((void**)&mt,     g_mt);
    cudaGetSymbolAddress((void**)&w2t,    g_w2t);
    cudaGetSymbolAddress((void**)&bias2,  g_bias2);
    cudaGetSymbolAddress((void**)&bqrow,  g_bqrow);
    cudaGetSymbolAddress((void**)&bdd,    g_bdd);
    cudaGetSymbolAddress((void**)&bkq,    g_bkq);

    cudaFuncSetAttribute(flash_k, cudaFuncAttributeMaxDynamicSharedMemorySize, FA_SMEM);

    const size_t out_ckv_off  = (size_t)MROWS * DM;
    const size_t out_krot_off = out_ckv_off + (size_t)MROWS * DKV;
    bool full_out = (size_t)out_size >= out_krot_off + (size_t)MROWS * DKV;
    float* ckv_dst = full_out ? (out + out_ckv_off) : ckvf;

    dim3 b256(256);
    dim3 blk(256);
    auto grd = [](int M, int N, int Z) { return dim3((unsigned)(N / 128), (unsigned)(M / 128), (unsigned)Z); };

    // ---- fork side stream inside capture ----
    cudaStream_t side;
    cudaStreamCreateWithFlags(&side, cudaStreamNonBlocking);
    cudaEvent_t evFork, evA, evB;
    cudaEventCreateWithFlags(&evFork, cudaEventDisableTiming);
    cudaEventCreateWithFlags(&evA,    cudaEventDisableTiming);
    cudaEventCreateWithFlags(&evB,    cudaEventDisableTiming);
    cudaEventRecord(evFork, 0);
    cudaStreamWaitEvent(side, evFork, 0);

    // ---- side chain: weight prep independent of h ----
    pad_w_k<<<(DKV * NH * DH + 255) / 256, 256, 0, side>>>(Wuq, wuq_p);
    pad_w_k<<<(DKV * NH * DH + 255) / 256, 256, 0, side>>>(Wuk, wuk_p);
    hgemm<<<grd(DKV, DKV, NH), blk, 0, side>>>(wuk_p, wuq_p, nullptr, mt, nullptr,
        DKV, DKV, DH, NH*DH, NH*DH, DKV, DKV, 0, 1.0f,
        0, DH, 0, DH, 0, DKV*DKV, 0, NH);
    bqrow_w_k<<<(NH * DKV + 7) / 8, 256, 0, side>>>(buq, Wuk, bqrow);
    cudaEventRecord(evA, side);   // mt, bqrow ready

    f2h_k<<<(DKV * DM / 4 + 255) / 256, 256, 0, side>>>(Wuv, wuv_h, DKV * DM / 4);
    transpose_f2h<<<dim3(DM/32, DM/32), b256, 0, side>>>(outw, wt_out, DM, DM);
    hgemm<<<grd(DM, DKV, NH), blk, 0, side>>>(wt_out, wuv_h, nullptr, w2t, nullptr,
        DM, DKV, DH, DM, DM, NH*DKV, NH*DKV, 0, 1.0f,
        0, DH, 0, DH, 0, DKV, 0, NH);
    bias2init_k<<<DM / 256, 256, 0, side>>>(outb, bias2);
    bias2p_k<<<dim3(DM / 256, DM / 256), 256, 0, side>>>(outw, buv, bias2);
    cudaEventRecord(evB, side);   // w2t, bias2 ready

    // ---- main chain (default stream) ----
    f2h_k<<<((size_t)MROWS * DM / 4 + 255) / 256, 256>>>(h, hh, MROWS * DM / 4);
    transpose_f2h<<<dim3(DKV/32, DM/32), b256>>>(Wdkv, wdd,                 DKV, DM);
    transpose_f2h<<<dim3(DKV/32, DM/32), b256>>>(Wdq,  wdd + (size_t)DKV*DM, DKV, DM);
    transpose_f2h<<<dim3(DKV/32, DKV/32), b256>>>(Wkr, wkq,                 DKV, DKV);
    transpose_f2h<<<dim3(DKV/32, DKV/32), b256>>>(Wqr, wkq + DKV*DKV,       DKV, DKV);
    bias_cat2<<<(NDD + 255) / 256, 256>>>(bdkv, bdq, bdd, DKV, DKV);
    bias_cat2<<<(2 * DKV + 255) / 256, 256>>>(bkr, bqr, bkq, DKV, DKV);

    // 1) merged down projection with split-K; reduce adds bias, emits outputs
    hgemm<<<grd(MROWS, NDD, 2), blk>>>(hh, wdd, part, nullptr, nullptr,
        MROWS, NDD, DM/2, DM, DM, NDD, NDD, NDD, 1.0f,
        0, DM/2, 0, DM/2, 0, (long long)MROWS * NDD, 0, 2);
    spk_reduce<<<(MROWS * NDD + 255) / 256, 256>>>(part, part + (size_t)MROWS * NDD,
        bdd, ckvcq, ckv_dst);

    // 2) merged rotary pre-projections
    hgemm<<<grd(MROWS, DKV, 2), blk>>>(ckvcq, wkq, nullptr, krqrp, bkq,
        MROWS, DKV, DKV, NDD, DKV, DKV, DKV, 0, 1.0f,
        0, DKV, 0, DKV*DKV, 0, (long long)MROWS*DKV, DKV, 2);

    // rope + kpfill (don't need side results)
    rope_k<<<(MROWS * DKV + 255) / 256, 256>>>(krqrp + (size_t)MROWS * DKV, qp, nullptr);
    rope_k<<<(MROWS * DKV + 255) / 256, 256>>>(krqrp, kp,
        full_out ? (out + out_krot_off) : nullptr);
    kpfill_k<<<(MROWS * NH * 16 + 255) / 256, 256>>>(ckvcq, NDD, kp);

    // join A: need mt, bqrow
    cudaStreamWaitEvent(0, evA, 0);

    // 3) q-tilde = cq @ Mt_h^T + bqrow_h  -> qp cols [h*KP .. h*KP+127]
    hgemm<<<grd(MROWS, DKV, NH), blk>>>(ckvcq + DKV, mt, nullptr, qp, bqrow,
        MROWS, DKV, DKV, NDD, DKV, LDQP, LDQP, 0, 1.0f,
        0, 0, 0, DKV*DKV, 0, KP, DKV, NH);

    // 5) fused flash attention -> u  (softmax-invariant terms dropped; KP=144)
    float inv_sqrt = 1.0f / sqrtf((float)DH);
    flash_k<<<dim3(SEQ/128, BATCH*NH), blk, FA_SMEM>>>(qp, kp, ckvcq, NDD, u, inv_sqrt);

    // join B: need w2t, bias2
    cudaStreamWaitEvent(0, evB, 0);

    // 6) out = u @ w2t^T + bias2
    hgemm<<<grd(MROWS, DM, 1), blk>>>(u, w2t, out, nullptr, bias2,
        MROWS, DM, NH*DKV, NH*DKV, NH*DKV, DM, DM, DM, 1.0f, 0,0,0,0,0,0,0, 1);

    cudaEventDestroy(evFork);
    cudaEventDestroy(evA);
    cudaEventDestroy(evB);
    cudaStreamDestroy(side);
}